// round 5
// baseline (speedup 1.0000x reference)
#include <cuda_runtime.h>
#include <cstdint>

#define Y_SZ  (16*256*256*3)
#define F_SZ  (16*64*64*128)

__device__ __align__(16) float g_A[16*128*128*64];   // enc1 out / dt1 out
__device__ __align__(16) float g_col[16*128*128*64]; // enc1 im2col
__device__ __align__(16) float g_B1[16*64*64*128];
__device__ __align__(16) float g_B2[16*64*64*128];
__device__ __align__(16) float g_T[16*64*64*32];
__device__ __align__(16) float g_norme[512];
__device__ __align__(16) float g_embT[512*128];
__device__ __align__(16) float g_wdt2[16*3*64];
__device__ __align__(16) float g_w1p[64*64];
__device__ __align__(16) float g_wtens[1536*1024];   // prepped tf32 hi/lo weights (mma pair layout)

// prepped weight chunk offsets (floats); chunk = 2*BF floats, BF = 32*(OC+4)
#define WP_ENC2 0
#define WP_ENC3 270336
#define WP_ERB1 574464
#define WP_ERB2 657408
#define WP_DEC  740352
#define WP_DRB1 1044480
#define WP_DRB2 1127424
#define WP_DT1  1210368

__device__ __forceinline__ float4 relu4(float4 a) {
    a.x = fmaxf(a.x, 0.f); a.y = fmaxf(a.y, 0.f);
    a.z = fmaxf(a.z, 0.f); a.w = fmaxf(a.w, 0.f);
    return a;
}
__device__ __forceinline__ float dot4(float4 a, float4 b) {
    return fmaf(a.x, b.x, fmaf(a.y, b.y, fmaf(a.z, b.z, a.w * b.w)));
}

// ---- packed fp32x2 helpers ----
__device__ __forceinline__ unsigned long long pk2(float x, float y) {
    unsigned long long r;
    asm("mov.b64 %0, {%1, %2};" : "=l"(r)
        : "r"(__float_as_uint(x)), "r"(__float_as_uint(y)));
    return r;
}
__device__ __forceinline__ float2 up2(unsigned long long v) {
    unsigned int lo, hi;
    asm("mov.b64 {%0, %1}, %2;" : "=r"(lo), "=r"(hi) : "l"(v));
    return make_float2(__uint_as_float(lo), __uint_as_float(hi));
}
__device__ __forceinline__ void fma2(unsigned long long& d,
                                     unsigned long long a, unsigned long long b) {
    asm("fma.rn.f32x2 %0, %1, %2, %0;" : "+l"(d) : "l"(a), "l"(b));
}

// ---- tf32 helpers ----
__device__ __forceinline__ float rna_tf32(float x) {
    uint32_t o;
    asm("cvt.rna.tf32.f32 %0, %1;" : "=r"(o) : "f"(x));
    return __uint_as_float(o);
}
__device__ __forceinline__ void mma8(float* c, const uint32_t* a, float2 b) {
    asm volatile(
        "mma.sync.aligned.m16n8k8.row.col.f32.tf32.tf32.f32 "
        "{%0,%1,%2,%3},{%4,%5,%6,%7},{%8,%9},{%0,%1,%2,%3};"
        : "+f"(c[0]), "+f"(c[1]), "+f"(c[2]), "+f"(c[3])
        : "r"(a[0]), "r"(a[1]), "r"(a[2]), "r"(a[3]),
          "r"(__float_as_uint(b.x)), "r"(__float_as_uint(b.y)));
}

// ---- weight prep: [tap][ic][oc] -> per-(tap,kc) hi/lo tiles in mma pair layout ----
// B pair layout: row = (k8*4 + t4) of (OC+4) float2 cols; pair = (k, k+4) halves.
template<int TAPS, int IC, int OC>
__global__ void prep_w_tf32(const float* __restrict__ w, float* __restrict__ out) {
    constexpr int KC = IC / 32;
    constexpr int BF = 32 * (OC + 4);     // floats per precision buffer
    int t = blockIdx.x * 256 + threadIdx.x;
    if (t >= TAPS * IC * OC) return;
    int oc = t % OC;
    int r = t / OC;
    int ic = r % IC;
    int tap = r / IC;
    int kc = ic >> 5, lk = ic & 31;
    int k8 = lk >> 3, t4 = lk & 3, half = (lk >> 2) & 1;
    float v = w[t];
    float hi = rna_tf32(v);
    float lo = rna_tf32(v - hi);
    long base = (long)(tap * KC + kc) * 2 * BF;
    int idx = ((k8 * 4 + t4) * (OC + 4) + oc) * 2 + half;
    out[base + idx] = hi;
    out[base + BF + idx] = lo;
}

// ================= mma.sync tf32 implicit-GEMM conv =================
// MODE 0: conv KHxKW stride/pad on square IH input, 64x64 output grid, 128 px/CTA.
// MODE 1: dt1 deconv parity class (blockIdx.y), output scatter to 128x128.
template<int MODE, int KH, int KW, int STRIDE, int PAD, int IH, int IC, int OC,
         bool RELU_IN, bool HAS_BIAS, bool RELU_OUT>
__global__ void __launch_bounds__(256, 2) conv_mma(
    const float* __restrict__ in, const float* __restrict__ wp,
    const float* __restrict__ bias, float* __restrict__ out)
{
    constexpr int KC = IC / 32;
    constexpr int NTAPS = (MODE == 0) ? KH * KW : 4;
    constexpr int SE = (MODE == 0) ? STRIDE : 1;
    constexpr int BMp = 132;              // A row stride in float2 (132 % 16 == 4)
    constexpr int BNp = OC + 4;           // B row stride in float2
    constexpr int AF = 16 * BMp * 2;      // floats per A precision buffer
    constexpr int BF = 16 * BNp * 2;      // floats per B precision buffer
    constexpr int NT = OC / 16;           // n-tiles (8 cols) per warp

    extern __shared__ __align__(16) float sm[];
    float* Ah = sm;
    float* Al = sm + AF;
    float* Bh = sm + 2 * AF;
    float* Bl = sm + 2 * AF + BF;

    int tid = threadIdx.x;
    int lane = tid & 31;
    int g = lane >> 2, t4 = lane & 3;
    int wid = tid >> 5;
    int wm = wid >> 1, wn = wid & 1;
    int m0 = blockIdx.x * 128;
    int po = 0, pw_ = 0;
    if (MODE == 1) { po = blockIdx.y >> 1; pw_ = blockIdx.y & 1; }

    int c4 = tid & 7, mp = tid >> 3;

    float acc[2][NT][4];
#pragma unroll
    for (int i = 0; i < 2; i++)
#pragma unroll
        for (int j = 0; j < NT; j++)
#pragma unroll
            for (int u = 0; u < 4; u++) acc[i][j][u] = 0.f;

    for (int tap = 0; tap < NTAPS; tap++) {
        int hoff, woff, wtap;
        if (MODE == 0) {
            int kh = tap / KW, kw = tap % KW;
            hoff = kh - PAD; woff = kw - PAD; wtap = tap;
        } else {
            int dh = tap >> 1, dw = tap & 1;
            hoff = po + dh - 1; woff = pw_ + dw - 1;
            wtap = (po + 2 * dh) * 4 + (pw_ + 2 * dw);
        }
        for (int kc = 0; kc < KC; kc++) {
            __syncthreads();   // previous frag reads done before refill
            // ---- A fill (128 px x 32 ch), hi/lo, mma pair layout
            int k8 = c4 >> 1, h = c4 & 1;
#pragma unroll
            for (int pass = 0; pass < 4; pass++) {
                int m = mp + 32 * pass;
                int p = m0 + m;
                int n_img = p >> 12, oh = (p >> 6) & 63, ow = p & 63;
                int ih = oh * SE + hoff, iw = ow * SE + woff;
                float4 v = make_float4(0.f, 0.f, 0.f, 0.f);
                if ((unsigned)ih < (unsigned)IH && (unsigned)iw < (unsigned)IH)
                    v = *(const float4*)(in + (((long)n_img * IH + ih) * IH + iw) * IC
                                            + kc * 32 + 4 * c4);
                if (RELU_IN) v = relu4(v);
                float4 hi = make_float4(rna_tf32(v.x), rna_tf32(v.y),
                                        rna_tf32(v.z), rna_tf32(v.w));
                float4 lo = make_float4(rna_tf32(v.x - hi.x), rna_tf32(v.y - hi.y),
                                        rna_tf32(v.z - hi.z), rna_tf32(v.w - hi.w));
                int i0 = ((k8 * 4 + 0) * BMp + m) * 2 + h;
                int i1 = ((k8 * 4 + 1) * BMp + m) * 2 + h;
                int i2 = ((k8 * 4 + 2) * BMp + m) * 2 + h;
                int i3 = ((k8 * 4 + 3) * BMp + m) * 2 + h;
                Ah[i0] = hi.x; Ah[i1] = hi.y; Ah[i2] = hi.z; Ah[i3] = hi.w;
                Al[i0] = lo.x; Al[i1] = lo.y; Al[i2] = lo.z; Al[i3] = lo.w;
            }
            // ---- B copy (pre-packed hi+lo contiguous)
            {
                const float4* src = (const float4*)(wp + (long)(wtap * KC + kc) * 2 * BF);
                float4* dst = (float4*)Bh;     // Bh..Bl contiguous
                constexpr int NF4 = 2 * BF / 4;
#pragma unroll
                for (int i = 0; i < (NF4 + 255) / 256; i++) {
                    int idx = tid + i * 256;
                    if (idx < NF4) dst[idx] = src[idx];
                }
            }
            __syncthreads();
            // ---- mma: 3 passes (Ah*Bh + Al*Bh + Ah*Bl)
#pragma unroll
            for (int kk = 0; kk < 4; kk++) {
                uint32_t ah[2][4], al[2][4];
                const float2* arh = (const float2*)Ah + (kk * 4 + t4) * BMp + wm * 32 + g;
                const float2* arl = (const float2*)Al + (kk * 4 + t4) * BMp + wm * 32 + g;
#pragma unroll
                for (int mt = 0; mt < 2; mt++) {
                    float2 q0 = arh[mt * 16];
                    float2 q1 = arh[mt * 16 + 8];
                    ah[mt][0] = __float_as_uint(q0.x);
                    ah[mt][1] = __float_as_uint(q1.x);
                    ah[mt][2] = __float_as_uint(q0.y);
                    ah[mt][3] = __float_as_uint(q1.y);
                    float2 r0 = arl[mt * 16];
                    float2 r1 = arl[mt * 16 + 8];
                    al[mt][0] = __float_as_uint(r0.x);
                    al[mt][1] = __float_as_uint(r1.x);
                    al[mt][2] = __float_as_uint(r0.y);
                    al[mt][3] = __float_as_uint(r1.y);
                }
                const float2* brh = (const float2*)Bh + (kk * 4 + t4) * BNp
                                    + wn * (OC / 2) + g;
                const float2* brl = (const float2*)Bl + (kk * 4 + t4) * BNp
                                    + wn * (OC / 2) + g;
#pragma unroll
                for (int nt = 0; nt < NT; nt++) {
                    float2 bh = brh[nt * 8];
                    float2 bl = brl[nt * 8];
#pragma unroll
                    for (int mt = 0; mt < 2; mt++) {
                        mma8(acc[mt][nt], ah[mt], bh);
                        mma8(acc[mt][nt], al[mt], bh);
                        mma8(acc[mt][nt], ah[mt], bl);
                    }
                }
            }
        }
    }
    // ---- epilogue
#pragma unroll
    for (int mt = 0; mt < 2; mt++) {
        int r0 = m0 + wm * 32 + mt * 16 + g;
        int r1 = r0 + 8;
        long o0, o1;
        if (MODE == 0) {
            o0 = (long)r0 * OC;
            o1 = (long)r1 * OC;
        } else {
            int n0 = r0 >> 12, a0 = (r0 >> 6) & 63, b0 = r0 & 63;
            int n1 = r1 >> 12, a1 = (r1 >> 6) & 63, b1 = r1 & 63;
            o0 = (((long)n0 * 128 + 2 * a0 + po) * 128 + 2 * b0 + pw_) * OC;
            o1 = (((long)n1 * 128 + 2 * a1 + po) * 128 + 2 * b1 + pw_) * OC;
        }
#pragma unroll
        for (int nt = 0; nt < NT; nt++) {
            int nb = wn * (OC / 2) + nt * 8 + 2 * t4;
            float b0v = HAS_BIAS ? bias[nb] : 0.f;
            float b1v = HAS_BIAS ? bias[nb + 1] : 0.f;
            float2 v0 = make_float2(acc[mt][nt][0] + b0v, acc[mt][nt][1] + b1v);
            float2 v1 = make_float2(acc[mt][nt][2] + b0v, acc[mt][nt][3] + b1v);
            if (RELU_OUT) {
                v0.x = fmaxf(v0.x, 0.f); v0.y = fmaxf(v0.y, 0.f);
                v1.x = fmaxf(v1.x, 0.f); v1.y = fmaxf(v1.y, 0.f);
            }
            *(float2*)(out + o0 + nb) = v0;
            *(float2*)(out + o1 + nb) = v1;
        }
    }
}

// [k][ic][oc] -> [k][oc][ic]  (dt2 tiny weights)
__global__ void transpose_w(const float* __restrict__ in, float* __restrict__ out,
                            int K, int IC, int OC) {
    int i = blockIdx.x * blockDim.x + threadIdx.x;
    int total = K * IC * OC;
    if (i >= total) return;
    int oc = i % OC;
    int ic = (i / OC) % IC;
    int k  = i / (OC * IC);
    out[(k * OC + oc) * IC + ic] = in[i];
}

__global__ void norme_kernel(const float* __restrict__ emb, float* __restrict__ norme) {
    int k = blockIdx.x * blockDim.x + threadIdx.x;
    if (k >= 512) return;
    const float4* e = (const float4*)(emb + k * 128);
    float s = 0.f;
#pragma unroll 8
    for (int i = 0; i < 32; i++) {
        float4 v = e[i];
        s = fmaf(v.x, v.x, s); s = fmaf(v.y, v.y, s);
        s = fmaf(v.z, v.z, s); s = fmaf(v.w, v.w, s);
    }
    norme[k] = s;
}

__global__ void embT_kernel(const float* __restrict__ emb, float* __restrict__ embT) {
    int i = blockIdx.x * 256 + threadIdx.x;
    if (i >= 512 * 32) return;
    int c = i & 511, d4 = i >> 9;
    float4 v = *(const float4*)(emb + c * 128 + 4 * d4);
    *(float4*)(embT + (d4 * 512 + c) * 4) = v;
}

__global__ void pad_w1(const float* __restrict__ w, float* __restrict__ out) {
    int t = blockIdx.x * 256 + threadIdx.x;
    if (t >= 64 * 64) return;
    int r = t >> 6;
    out[t] = (r < 48) ? w[t] : 0.f;
}

__global__ void im2col_enc1(const float* __restrict__ x, float* __restrict__ col) {
    int t = blockIdx.x * 256 + threadIdx.x;
    int kidx = t & 63;
    int p = t >> 6;
    int ow = p & 127, oh = (p >> 7) & 127, n = p >> 14;
    float v = 0.f;
    if (kidx < 48) {
        int ic = kidx % 3;
        int kw = (kidx / 3) & 3;
        int kh = kidx / 12;
        int ih = 2 * oh - 1 + kh, iw = 2 * ow - 1 + kw;
        if ((unsigned)ih < 256u && (unsigned)iw < 256u)
            v = x[((n * 256 + ih) * 256 + iw) * 3 + ic];
    }
    col[t] = v;
}

// ======== scalar f32x2 GEMM (enc1): flat GEMM in[p][IC] -> out[p][OC] ========
template<int IC, int OC, int BM, int TM, int TN, bool HAS_BIAS, bool RELU_OUT>
__global__ void __launch_bounds__(256, 2) flat_gemm(
    const float* __restrict__ in, const float* __restrict__ w,
    const float* __restrict__ bias, float* __restrict__ out)
{
    constexpr int BK = 32;
    constexpr int BN = OC;
    constexpr int TX = BN / TN;
    constexpr int ASTR = BM + 2;
    __shared__ __align__(16) float As[BK * ASTR];
    __shared__ __align__(16) float Bs[BK * BN];
    int tid = threadIdx.x;
    int m0 = blockIdx.x * BM;
    int tx = tid % TX, ty = tid / TX;
    int c4 = tid & 7;
    int mp = tid >> 3;
    unsigned long long acc2[TM / 2][TN];
#pragma unroll
    for (int i = 0; i < TM / 2; i++)
#pragma unroll
        for (int j = 0; j < TN; j++) acc2[i][j] = 0ull;

    for (int kc = 0; kc < IC / BK; kc++) {
        __syncthreads();
#pragma unroll
        for (int pass = 0; pass < BM / 32; pass++) {
            int m = mp + pass * 32;
            int p = m0 + m;
            float4 v = *(const float4*)(in + (long)p * IC + kc * BK + 4 * c4);
            int kk = 4 * c4;
            As[(kk + 0) * ASTR + m] = v.x;
            As[(kk + 1) * ASTR + m] = v.y;
            As[(kk + 2) * ASTR + m] = v.z;
            As[(kk + 3) * ASTR + m] = v.w;
        }
        {
            const float* wb = w + kc * BK * OC;
#pragma unroll
            for (int i = 0; i < (BK * BN / 4) / 256; i++) {
                int idx = tid + i * 256;
                int kr = idx / (BN / 4);
                int n4 = idx % (BN / 4);
                *(float4*)(Bs + kr * BN + 4 * n4) = *(const float4*)(wb + kr * OC + 4 * n4);
            }
        }
        __syncthreads();
#pragma unroll 8
        for (int k = 0; k < BK; k++) {
            unsigned long long a2[TM / 2], b2[TN];
            const double* ap = (const double*)(As + k * ASTR + ty * TM);
#pragma unroll
            for (int i = 0; i < TM / 2; i++) a2[i] = __double_as_longlong(ap[i]);
            float b[TN];
#pragma unroll
            for (int j = 0; j < TN / 4; j++)
                *(float4*)(b + 4 * j) = *(const float4*)(Bs + k * BN + tx * TN + 4 * j);
#pragma unroll
            for (int j = 0; j < TN; j++) b2[j] = pk2(b[j], b[j]);
#pragma unroll
            for (int i = 0; i < TM / 2; i++)
#pragma unroll
                for (int j = 0; j < TN; j++) fma2(acc2[i][j], a2[i], b2[j]);
        }
    }
    float bv[TN];
#pragma unroll
    for (int j = 0; j < TN; j++) bv[j] = HAS_BIAS ? bias[tx * TN + j] : 0.f;
    int base_m = m0 + ty * TM;
#pragma unroll
    for (int i2 = 0; i2 < TM / 2; i2++) {
        float2 tv[TN];
#pragma unroll
        for (int j = 0; j < TN; j++) tv[j] = up2(acc2[i2][j]);
#pragma unroll
        for (int h = 0; h < 2; h++) {
            int p = base_m + 2 * i2 + h;
            float v[TN];
#pragma unroll
            for (int j = 0; j < TN; j++) {
                float t = (h ? tv[j].y : tv[j].x) + bv[j];
                v[j] = RELU_OUT ? fmaxf(t, 0.f) : t;
            }
            long oaddr = (long)p * OC + tx * TN;
#pragma unroll
            for (int j = 0; j < TN / 4; j++)
                *(float4*)(out + oaddr + 4 * j) = *(float4*)(v + 4 * j);
        }
    }
}

// ---------------- 1x1 conv (relu on input) + residual add, 32->128 ----------------
template<bool RELU_OUT>
__global__ void conv1x1_res(const float* __restrict__ tin, const float* __restrict__ res,
                            const float* __restrict__ w, float* __restrict__ out) {
    int t = blockIdx.x * 256 + threadIdx.x;
    int oc = t & 127;
    long p0 = (long)(t >> 7) * 4;
    float wv[32];
#pragma unroll
    for (int ic = 0; ic < 32; ic++) wv[ic] = w[ic * 128 + oc];
    float accp[4] = {0.f, 0.f, 0.f, 0.f};
#pragma unroll
    for (int ic4 = 0; ic4 < 8; ic4++) {
#pragma unroll
        for (int p = 0; p < 4; p++) {
            float4 tv = *(const float4*)(tin + (p0 + p) * 32 + 4 * ic4);
            tv = relu4(tv);
            accp[p] = fmaf(tv.x, wv[4 * ic4],     accp[p]);
            accp[p] = fmaf(tv.y, wv[4 * ic4 + 1], accp[p]);
            accp[p] = fmaf(tv.z, wv[4 * ic4 + 2], accp[p]);
            accp[p] = fmaf(tv.w, wv[4 * ic4 + 3], accp[p]);
        }
    }
    long o = p0 * 128 + oc;
#pragma unroll
    for (int p = 0; p < 4; p++) {
        float v = res[o + p * 128] + accp[p];
        if (RELU_OUT) v = fmaxf(v, 0.f);
        out[o + p * 128] = v;
    }
}

// ---------------- VQ: 16 pixels/block ----------------
__global__ void __launch_bounds__(128) vq16(const float* __restrict__ f,
                                            const float* __restrict__ embT,
                                            const float* __restrict__ emb,
                                            const float* __restrict__ norme,
                                            float* __restrict__ q) {
    __shared__ float4 xs4[16 * 32];
    __shared__ float rdist[16 * 128];
    __shared__ int   ridx[16 * 128];
    __shared__ int   best[16];
    int tid = threadIdx.x;
    long pixel0 = (long)blockIdx.x * 16;
    const float4* fin = (const float4*)(f + pixel0 * 128);
#pragma unroll
    for (int i = 0; i < 4; i++) xs4[tid + 128 * i] = fin[tid + 128 * i];
    __syncthreads();

    unsigned long long acc2[4][8];
#pragma unroll
    for (int j = 0; j < 4; j++)
#pragma unroll
        for (int p2 = 0; p2 < 8; p2++) acc2[j][p2] = 0ull;

    const float4* eT = (const float4*)embT;
    for (int d4 = 0; d4 < 32; d4++) {
        float4 ev[4];
#pragma unroll
        for (int j = 0; j < 4; j++) ev[j] = eT[d4 * 512 + 128 * j + tid];
        unsigned long long e2[4][4];
#pragma unroll
        for (int j = 0; j < 4; j++) {
            e2[j][0] = pk2(ev[j].x, ev[j].x);
            e2[j][1] = pk2(ev[j].y, ev[j].y);
            e2[j][2] = pk2(ev[j].z, ev[j].z);
            e2[j][3] = pk2(ev[j].w, ev[j].w);
        }
#pragma unroll
        for (int p2 = 0; p2 < 8; p2++) {
            float4 xa = xs4[(2 * p2) * 32 + d4];
            float4 xb = xs4[(2 * p2 + 1) * 32 + d4];
            unsigned long long xp0 = pk2(xa.x, xb.x);
            unsigned long long xp1 = pk2(xa.y, xb.y);
            unsigned long long xp2 = pk2(xa.z, xb.z);
            unsigned long long xp3 = pk2(xa.w, xb.w);
#pragma unroll
            for (int j = 0; j < 4; j++) {
                fma2(acc2[j][p2], xp0, e2[j][0]);
                fma2(acc2[j][p2], xp1, e2[j][1]);
                fma2(acc2[j][p2], xp2, e2[j][2]);
                fma2(acc2[j][p2], xp3, e2[j][3]);
            }
        }
    }
    float accs[4][16];
#pragma unroll
    for (int j = 0; j < 4; j++)
#pragma unroll
        for (int p2 = 0; p2 < 8; p2++) {
            float2 u = up2(acc2[j][p2]);
            accs[j][2 * p2] = u.x;
            accs[j][2 * p2 + 1] = u.y;
        }
    float nd[4];
#pragma unroll
    for (int j = 0; j < 4; j++) nd[j] = norme[tid + 128 * j];
#pragma unroll
    for (int p = 0; p < 16; p++) {
        float bd = 1e30f; int bi = 0;
#pragma unroll
        for (int j = 0; j < 4; j++) {
            float d = nd[j] - 2.f * accs[j][p];
            if (d < bd) { bd = d; bi = tid + 128 * j; }
        }
        rdist[p * 128 + tid] = bd;
        ridx[p * 128 + tid]  = bi;
    }
    __syncthreads();
    if (tid < 16) {
        float bd = 1e30f; int bi = 1 << 30;
        for (int u = 0; u < 128; u++) {
            float d = rdist[tid * 128 + u];
            int   i = ridx[tid * 128 + u];
            if (d < bd || (d == bd && i < bi)) { bd = d; bi = i; }
        }
        best[tid] = bi;
    }
    __syncthreads();
#pragma unroll
    for (int p = 0; p < 16; p++)
        q[(pixel0 + p) * 128 + tid] = emb[best[p] * 128 + tid];
}

// ---------------- dt2: conv_transpose 4x4 s2, 64->3; wt [k][oc][ic] ----------------
__global__ void dt2_kernel(const float* __restrict__ in, const float* __restrict__ wt,
                           const float* __restrict__ b, float* __restrict__ out) {
    int t = blockIdx.x * 256 + threadIdx.x;
    int ow = t & 255;
    int oh = (t >> 8) & 255;
    int n  = t >> 16;
    float a0 = b[0], a1 = b[1], a2 = b[2];
#pragma unroll
    for (int dh = 0; dh < 2; dh++) {
        int kh = (oh & 1) + 2 * dh;
        int ih2 = oh + kh - 2;
        if (ih2 < 0 || ih2 >= 256) continue;
        int ih = ih2 >> 1;
#pragma unroll
        for (int dw = 0; dw < 2; dw++) {
            int kw = (ow & 1) + 2 * dw;
            int iw2 = ow + kw - 2;
            if (iw2 < 0 || iw2 >= 256) continue;
            int iw = iw2 >> 1;
            const float4* xp = (const float4*)(in + ((n * 128 + ih) * 128 + iw) * 64);
            const float* wb = wt + (kh * 4 + kw) * 3 * 64;
            const float4* w0 = (const float4*)(wb);
            const float4* w1 = (const float4*)(wb + 64);
            const float4* w2 = (const float4*)(wb + 128);
#pragma unroll 4
            for (int ic4 = 0; ic4 < 16; ic4++) {
                float4 x4 = xp[ic4];
                a0 += dot4(x4, w0[ic4]);
                a1 += dot4(x4, w1[ic4]);
                a2 += dot4(x4, w2[ic4]);
            }
        }
    }
    float* op = out + (long)((n * 256 + oh) * 256 + ow) * 3;
    op[0] = a0; op[1] = a1; op[2] = a2;
}

extern "C" void kernel_launch(void* const* d_in, const int* in_sizes, int n_in,
                              void* d_out, int out_size) {
    const float* x       = (const float*)d_in[0];
    const float* emb     = (const float*)d_in[1];
    const float* enc_w1  = (const float*)d_in[2];
    const float* enc_b1  = (const float*)d_in[3];
    const float* enc_w2  = (const float*)d_in[4];
    const float* enc_b2  = (const float*)d_in[5];
    const float* enc_w3  = (const float*)d_in[6];
    const float* enc_b3  = (const float*)d_in[7];
    const float* erb1_w1 = (const float*)d_in[8];
    const float* erb1_w2 = (const float*)d_in[9];
    const float* erb2_w1 = (const float*)d_in[10];
    const float* erb2_w2 = (const float*)d_in[11];
    const float* dec_w   = (const float*)d_in[12];
    const float* dec_b   = (const float*)d_in[13];
    const float* drb1_w1 = (const float*)d_in[14];
    const float* drb1_w2 = (const float*)d_in[15];
    const float* drb2_w1 = (const float*)d_in[16];
    const float* drb2_w2 = (const float*)d_in[17];
    const float* dt1_w   = (const float*)d_in[18];
    const float* dt1_b   = (const float*)d_in[19];
    const float* dt2_w   = (const float*)d_in[20];
    const float* dt2_b   = (const float*)d_in[21];

    float *pA, *pCol, *pB1, *pB2, *pT, *pN, *pE, *pWdt2, *pW1p, *pWT;
    cudaGetSymbolAddress((void**)&pA,    g_A);
    cudaGetSymbolAddress((void**)&pCol,  g_col);
    cudaGetSymbolAddress((void**)&pB1,   g_B1);
    cudaGetSymbolAddress((void**)&pB2,   g_B2);
    cudaGetSymbolAddress((void**)&pT,    g_T);
    cudaGetSymbolAddress((void**)&pN,    g_norme);
    cudaGetSymbolAddress((void**)&pE,    g_embT);
    cudaGetSymbolAddress((void**)&pWdt2, g_wdt2);
    cudaGetSymbolAddress((void**)&pW1p,  g_w1p);
    cudaGetSymbolAddress((void**)&pWT,   g_wtens);

    float* yout = (float*)d_out;
    float* fout = yout + Y_SZ;
    float* qout = fout + F_SZ;

    // dynamic smem: 2*AF + 2*BF floats; AF = 16*132*2 = 4224
    const int SM128 = (2 * 4224 + 2 * (16 * 132 * 2)) * 4;  // 67584
    const int SM64  = (2 * 4224 + 2 * (16 * 68  * 2)) * 4;  // 51200
    const int SM32  = (2 * 4224 + 2 * (16 * 36  * 2)) * 4;  // 43008
    cudaFuncSetAttribute(
        conv_mma<0, 4, 4, 2, 1, 128, 64, 128, false, true, true>,
        cudaFuncAttributeMaxDynamicSharedMemorySize, SM128);
    cudaFuncSetAttribute(
        conv_mma<0, 3, 3, 1, 1, 64, 128, 128, false, true, false>,
        cudaFuncAttributeMaxDynamicSharedMemorySize, SM128);
    cudaFuncSetAttribute(
        conv_mma<0, 3, 3, 1, 1, 64, 128, 32, true, false, false>,
        cudaFuncAttributeMaxDynamicSharedMemorySize, SM32);
    cudaFuncSetAttribute(
        conv_mma<1, 4, 4, 1, 0, 64, 128, 64, false, true, true>,
        cudaFuncAttributeMaxDynamicSharedMemorySize, SM64);

    // prep + enc1
    im2col_enc1<<<65536, 256>>>(x, pCol);
    pad_w1<<<16, 256>>>(enc_w1, pW1p);
    prep_w_tf32<16, 64, 128><<<512, 256>>>(enc_w2, pWT + WP_ENC2);
    flat_gemm<64, 64, 128, 8, 4, true, true><<<2048, 256>>>(pCol, pW1p, enc_b1, pA);
    prep_w_tf32<9, 128, 128><<<576, 256>>>(enc_w3, pWT + WP_ENC3);
    prep_w_tf32<9, 128, 32><<<144, 256>>>(erb1_w1, pWT + WP_ERB1);
    prep_w_tf32<9, 128, 32><<<144, 256>>>(erb2_w1, pWT + WP_ERB2);
    prep_w_tf32<9, 128, 128><<<576, 256>>>(dec_w, pWT + WP_DEC);
    prep_w_tf32<9, 128, 32><<<144, 256>>>(drb1_w1, pWT + WP_DRB1);
    prep_w_tf32<9, 128, 32><<<144, 256>>>(drb2_w1, pWT + WP_DRB2);
    prep_w_tf32<16, 128, 64><<<512, 256>>>(dt1_w, pWT + WP_DT1);
    transpose_w<<<12, 256>>>(dt2_w, pWdt2, 16, 64, 3);
    norme_kernel<<<2, 256>>>(emb, pN);
    embT_kernel<<<64, 256>>>(emb, pE);

    // Encoder
    conv_mma<0, 4, 4, 2, 1, 128, 64, 128, false, true, true>
        <<<512, 256, SM128>>>(pA, pWT + WP_ENC2, enc_b2, pB1);
    conv_mma<0, 3, 3, 1, 1, 64, 128, 128, false, true, false>
        <<<512, 256, SM128>>>(pB1, pWT + WP_ENC3, enc_b3, pB2);
    conv_mma<0, 3, 3, 1, 1, 64, 128, 32, true, false, false>
        <<<512, 256, SM32>>>(pB2, pWT + WP_ERB1, nullptr, pT);
    conv1x1_res<false><<<8192, 256>>>(pT, pB2, erb1_w2, pB1);
    conv_mma<0, 3, 3, 1, 1, 64, 128, 32, true, false, false>
        <<<512, 256, SM32>>>(pB1, pWT + WP_ERB2, nullptr, pT);
    conv1x1_res<true><<<8192, 256>>>(pT, pB1, erb2_w2, fout);   // f -> d_out

    // VQ
    vq16<<<4096, 128>>>(fout, pE, emb, pN, qout);               // q -> d_out

    // Decoder
    conv_mma<0, 3, 3, 1, 1, 64, 128, 128, false, true, false>
        <<<512, 256, SM128>>>(qout, pWT + WP_DEC, dec_b, pB1);
    conv_mma<0, 3, 3, 1, 1, 64, 128, 32, true, false, false>
        <<<512, 256, SM32>>>(pB1, pWT + WP_DRB1, nullptr, pT);
    conv1x1_res<false><<<8192, 256>>>(pT, pB1, drb1_w2, pB2);
    conv_mma<0, 3, 3, 1, 1, 64, 128, 32, true, false, false>
        <<<512, 256, SM32>>>(pB2, pWT + WP_DRB2, nullptr, pT);
    conv1x1_res<true><<<8192, 256>>>(pT, pB2, drb2_w2, pB1);
    conv_mma<1, 4, 4, 1, 0, 64, 128, 64, false, true, true>
        <<<dim3(512, 4), 256, SM64>>>(pB1, pWT + WP_DT1, dt1_b, pA);
    dt2_kernel<<<4096, 256>>>(pA, pWdt2, dt2_b, yout);
}

// round 6
// speedup vs baseline: 1.0051x; 1.0051x over previous
#include <cuda_runtime.h>
#include <cstdint>

#define Y_SZ  (16*256*256*3)
#define F_SZ  (16*64*64*128)

__device__ __align__(16) float g_A[16*128*128*64];   // enc1 out / dt1 out
__device__ __align__(16) float g_col[16*128*128*64]; // enc1 im2col
__device__ __align__(16) float g_cvt[16*128*128*64*2]; // packed hi/lo activations
__device__ __align__(16) float g_B1[16*64*64*128];
__device__ __align__(16) float g_B2[16*64*64*128];
__device__ __align__(16) float g_T[16*64*64*32];
__device__ __align__(16) float g_norme[512];
__device__ __align__(16) float g_embT[512*128];
__device__ __align__(16) float g_wdt2[16*3*64];
__device__ __align__(16) float g_w1p[64*64];
__device__ __align__(16) float g_wtens[1536*1024];   // prepped tf32 hi/lo weights

#define WP_ENC2 0
#define WP_ENC3 270336
#define WP_ERB1 574464
#define WP_ERB2 657408
#define WP_DEC  740352
#define WP_DRB1 1044480
#define WP_DRB2 1127424
#define WP_DT1  1210368

__device__ __forceinline__ float4 relu4(float4 a) {
    a.x = fmaxf(a.x, 0.f); a.y = fmaxf(a.y, 0.f);
    a.z = fmaxf(a.z, 0.f); a.w = fmaxf(a.w, 0.f);
    return a;
}
__device__ __forceinline__ float dot4(float4 a, float4 b) {
    return fmaf(a.x, b.x, fmaf(a.y, b.y, fmaf(a.z, b.z, a.w * b.w)));
}
__device__ __forceinline__ unsigned long long pk2(float x, float y) {
    unsigned long long r;
    asm("mov.b64 %0, {%1, %2};" : "=l"(r)
        : "r"(__float_as_uint(x)), "r"(__float_as_uint(y)));
    return r;
}
__device__ __forceinline__ float2 up2(unsigned long long v) {
    unsigned int lo, hi;
    asm("mov.b64 {%0, %1}, %2;" : "=r"(lo), "=r"(hi) : "l"(v));
    return make_float2(__uint_as_float(lo), __uint_as_float(hi));
}
__device__ __forceinline__ void fma2(unsigned long long& d,
                                     unsigned long long a, unsigned long long b) {
    asm("fma.rn.f32x2 %0, %1, %2, %0;" : "+l"(d) : "l"(a), "l"(b));
}
__device__ __forceinline__ float rna_tf32(float x) {
    uint32_t o;
    asm("cvt.rna.tf32.f32 %0, %1;" : "=r"(o) : "f"(x));
    return __uint_as_float(o);
}
__device__ __forceinline__ void mma8(float* c, const uint32_t* a, float2 b) {
    asm volatile(
        "mma.sync.aligned.m16n8k8.row.col.f32.tf32.tf32.f32 "
        "{%0,%1,%2,%3},{%4,%5,%6,%7},{%8,%9},{%0,%1,%2,%3};"
        : "+f"(c[0]), "+f"(c[1]), "+f"(c[2]), "+f"(c[3])
        : "r"(a[0]), "r"(a[1]), "r"(a[2]), "r"(a[3]),
          "r"(__float_as_uint(b.x)), "r"(__float_as_uint(b.y)));
}
__device__ __forceinline__ uint32_t smem_u32(const void* p) {
    uint32_t a;
    asm("{ .reg .u64 t; cvta.to.shared.u64 t, %1; cvt.u32.u64 %0, t; }"
        : "=r"(a) : "l"(p));
    return a;
}
__device__ __forceinline__ void cpasync16(uint32_t dst, const void* src) {
    asm volatile("cp.async.cg.shared.global [%0], [%1], 16;" :: "r"(dst), "l"(src));
}
__device__ __forceinline__ void cpasync_commit() {
    asm volatile("cp.async.commit_group;" ::: "memory");
}
__device__ __forceinline__ void cpasync_wait0() {
    asm volatile("cp.async.wait_group 0;" ::: "memory");
}

// ---- activation pre-convert: [p][IC] fp32 -> [p][kc][hi32|lo32] ----
template<int IC, bool RELU>
__global__ void cvt_act(const float* __restrict__ in, float* __restrict__ out, int npx) {
    int t = blockIdx.x * 256 + threadIdx.x;
    if (t >= npx * (IC / 4)) return;
    int j = t % (IC / 4);
    long p = t / (IC / 4);
    float4 v = *(const float4*)(in + p * IC + 4 * j);
    if (RELU) v = relu4(v);
    float4 hi = make_float4(rna_tf32(v.x), rna_tf32(v.y), rna_tf32(v.z), rna_tf32(v.w));
    float4 lo = make_float4(rna_tf32(v.x - hi.x), rna_tf32(v.y - hi.y),
                            rna_tf32(v.z - hi.z), rna_tf32(v.w - hi.w));
    int kc = j >> 3, e = j & 7;
    long base = p * 2 * IC + kc * 64 + 4 * e;
    *(float4*)(out + base)      = hi;
    *(float4*)(out + base + 32) = lo;
}

// ---- weight prep: [tap][ic][oc] -> per-(tap,kc) hi/lo tiles in mma pair layout ----
template<int TAPS, int IC, int OC>
__global__ void prep_w_tf32(const float* __restrict__ w, float* __restrict__ out) {
    constexpr int KC = IC / 32;
    constexpr int BF = 32 * (OC + 4);
    int t = blockIdx.x * 256 + threadIdx.x;
    if (t >= TAPS * IC * OC) return;
    int oc = t % OC;
    int r = t / OC;
    int ic = r % IC;
    int tap = r / IC;
    int kc = ic >> 5, lk = ic & 31;
    int k8 = lk >> 3, t4 = lk & 3, half = (lk >> 2) & 1;
    float v = w[t];
    float hi = rna_tf32(v);
    float lo = rna_tf32(v - hi);
    long base = (long)(tap * KC + kc) * 2 * BF;
    int idx = ((k8 * 4 + t4) * (OC + 4) + oc) * 2 + half;
    out[base + idx] = hi;
    out[base + BF + idx] = lo;
}

// ================= pipelined mma.sync tf32 implicit-GEMM conv =================
// Input: pre-converted hi/lo activations (cv layout). Weights: prepped pair layout.
template<int MODE, int KH, int KW, int STRIDE, int PAD, int IH, int IC, int OC,
         int NPASS, bool HAS_BIAS, bool RELU_OUT>
__global__ void __launch_bounds__(256, (OC >= 128) ? 1 : 2) conv_mma(
    const float* __restrict__ cv, const float* __restrict__ wp,
    const float* __restrict__ bias, float* __restrict__ out)
{
    constexpr int KC = IC / 32;
    constexpr int NTAPS = (MODE == 0) ? KH * KW : 4;
    constexpr int SE = (MODE == 0) ? STRIDE : 1;
    constexpr int BMp = 132;              // A row stride (float2)
    constexpr int BNp = OC + 4;
    constexpr int AF = 16 * BMp * 2;      // floats per A precision buf
    constexpr int BF = 16 * BNp * 2;
    constexpr int SS = 2 * AF + 2 * BF;   // floats per stage
    constexpr int NT = OC / 16;
    constexpr int TOTAL = NTAPS * KC;

    extern __shared__ __align__(16) float sm[];

    int tid = threadIdx.x;
    int lane = tid & 31;
    int g = lane >> 2, t4 = lane & 3;
    int wid = tid >> 5;
    int wm = wid >> 1, wn = wid & 1;
    int m0 = blockIdx.x * 128;
    int po = 0, pw_ = 0;
    if (MODE == 1) { po = blockIdx.y >> 1; pw_ = blockIdx.y & 1; }
    int c4 = tid & 7, mp = tid >> 3;
    int k8 = c4 >> 1, h = c4 & 1;

    float acc[2][NT][4];
#pragma unroll
    for (int i = 0; i < 2; i++)
#pragma unroll
        for (int j = 0; j < NT; j++)
#pragma unroll
            for (int u = 0; u < 4; u++) acc[i][j][u] = 0.f;

    // ---- helpers (lambdas) ----
    auto tapgeom = [&](int it, int& hoff, int& woff, int& wtap, int& kc) {
        int tap = it / KC; kc = it % KC;
        if (MODE == 0) {
            int kh = tap / KW, kw = tap % KW;
            hoff = kh - PAD; woff = kw - PAD; wtap = tap;
        } else {
            int dh = tap >> 1, dw = tap & 1;
            hoff = po + dh - 1; woff = pw_ + dw - 1;
            wtap = (po + 2 * dh) * 4 + (pw_ + 2 * dw);
        }
    };
    auto fillregs = [&](int it, float4* rh, float4* rl) {
        int hoff, woff, wtap, kc;
        tapgeom(it, hoff, woff, wtap, kc);
#pragma unroll
        for (int pass = 0; pass < 4; pass++) {
            int m = mp + 32 * pass;
            int p = m0 + m;
            int n_img = p >> 12, oh = (p >> 6) & 63, ow = p & 63;
            int ih = oh * SE + hoff, iw = ow * SE + woff;
            rh[pass] = make_float4(0.f, 0.f, 0.f, 0.f);
            rl[pass] = make_float4(0.f, 0.f, 0.f, 0.f);
            if ((unsigned)ih < (unsigned)IH && (unsigned)iw < (unsigned)IH) {
                long P = ((long)n_img * IH + ih) * IH + iw;
                const float* b = cv + P * 2 * IC + kc * 64 + 4 * c4;
                rh[pass] = *(const float4*)(b);
                rl[pass] = *(const float4*)(b + 32);
            }
        }
    };
    auto stsregs = [&](int s, const float4* rh, const float4* rl) {
        float* Ah = sm + s * SS;
        float* Al = Ah + AF;
#pragma unroll
        for (int pass = 0; pass < 4; pass++) {
            int m = mp + 32 * pass;
            int rot = ((m + 4 * k8) & 127) * 2 + h;
            int r0 = (k8 * 4 + 0) * (2 * BMp) + rot;
            int r1 = (k8 * 4 + 1) * (2 * BMp) + rot;
            int r2 = (k8 * 4 + 2) * (2 * BMp) + rot;
            int r3 = (k8 * 4 + 3) * (2 * BMp) + rot;
            Ah[r0] = rh[pass].x; Ah[r1] = rh[pass].y;
            Ah[r2] = rh[pass].z; Ah[r3] = rh[pass].w;
            Al[r0] = rl[pass].x; Al[r1] = rl[pass].y;
            Al[r2] = rl[pass].z; Al[r3] = rl[pass].w;
        }
    };
    auto copyB = [&](int it, int s) {
        int hoff, woff, wtap, kc;
        tapgeom(it, hoff, woff, wtap, kc);
        const float* src = wp + (long)(wtap * KC + kc) * 2 * BF;
        uint32_t dst = smem_u32(sm + s * SS + 2 * AF);
        constexpr int NF4 = 2 * BF / 4;
#pragma unroll
        for (int i = 0; i < (NF4 + 255) / 256; i++) {
            int idx = tid + i * 256;
            if (idx < NF4) cpasync16(dst + idx * 16, src + idx * 4);
        }
        cpasync_commit();
    };
    auto do_mma = [&](int s) {
        const float* Ah = sm + s * SS;
        const float* Al = Ah + AF;
        const float* Bh = Ah + 2 * AF;
        const float* Bl = Bh + BF;
#pragma unroll
        for (int kk = 0; kk < 4; kk++) {
            uint32_t ah[2][4], al[2][4];
            const float2* arh = (const float2*)Ah + (kk * 4 + t4) * BMp;
            const float2* arl = (const float2*)Al + (kk * 4 + t4) * BMp;
#pragma unroll
            for (int mt = 0; mt < 2; mt++) {
                int c0 = (wm * 32 + mt * 16 + g + 4 * kk) & 127;
                int c1 = (wm * 32 + mt * 16 + g + 8 + 4 * kk) & 127;
                float2 q0 = arh[c0], q1 = arh[c1];
                ah[mt][0] = __float_as_uint(q0.x);
                ah[mt][1] = __float_as_uint(q1.x);
                ah[mt][2] = __float_as_uint(q0.y);
                ah[mt][3] = __float_as_uint(q1.y);
                float2 s0 = arl[c0], s1 = arl[c1];
                al[mt][0] = __float_as_uint(s0.x);
                al[mt][1] = __float_as_uint(s1.x);
                al[mt][2] = __float_as_uint(s0.y);
                al[mt][3] = __float_as_uint(s1.y);
            }
            const float2* brh = (const float2*)Bh + (kk * 4 + t4) * BNp + wn * (OC / 2) + g;
            const float2* brl = (const float2*)Bl + (kk * 4 + t4) * BNp + wn * (OC / 2) + g;
#pragma unroll
            for (int nt = 0; nt < NT; nt++) {
                float2 bh = brh[nt * 8];
                float2 bl = brl[nt * 8];
#pragma unroll
                for (int mt = 0; mt < 2; mt++) {
                    mma8(acc[mt][nt], ah[mt], bh);
                    mma8(acc[mt][nt], al[mt], bh);
                    mma8(acc[mt][nt], ah[mt], bl);
                    if (NPASS == 4) mma8(acc[mt][nt], al[mt], bl);
                }
            }
        }
    };

    // ---- prologue: fill stage 0
    {
        float4 rh[4], rl[4];
        fillregs(0, rh, rl);
        stsregs(0, rh, rl);
        copyB(0, 0);
        cpasync_wait0();
        __syncthreads();
    }
    // ---- pipelined main loop
    for (int it = 0; it < TOTAL; it++) {
        int cur = it & 1, nxt = cur ^ 1;
        float4 rh[4], rl[4];
        bool have = (it + 1 < TOTAL);
        if (have) {
            fillregs(it + 1, rh, rl);
            copyB(it + 1, nxt);
        }
        do_mma(cur);
        if (have) stsregs(nxt, rh, rl);
        cpasync_wait0();
        __syncthreads();
    }

    // ---- epilogue
#pragma unroll
    for (int mt = 0; mt < 2; mt++) {
        int r0 = m0 + wm * 32 + mt * 16 + g;
        int r1 = r0 + 8;
        long o0, o1;
        if (MODE == 0) {
            o0 = (long)r0 * OC;
            o1 = (long)r1 * OC;
        } else {
            int n0 = r0 >> 12, a0 = (r0 >> 6) & 63, b0 = r0 & 63;
            int n1 = r1 >> 12, a1 = (r1 >> 6) & 63, b1 = r1 & 63;
            o0 = (((long)n0 * 128 + 2 * a0 + po) * 128 + 2 * b0 + pw_) * OC;
            o1 = (((long)n1 * 128 + 2 * a1 + po) * 128 + 2 * b1 + pw_) * OC;
        }
#pragma unroll
        for (int nt = 0; nt < NT; nt++) {
            int nb = wn * (OC / 2) + nt * 8 + 2 * t4;
            float b0v = HAS_BIAS ? bias[nb] : 0.f;
            float b1v = HAS_BIAS ? bias[nb + 1] : 0.f;
            float2 v0 = make_float2(acc[mt][nt][0] + b0v, acc[mt][nt][1] + b1v);
            float2 v1 = make_float2(acc[mt][nt][2] + b0v, acc[mt][nt][3] + b1v);
            if (RELU_OUT) {
                v0.x = fmaxf(v0.x, 0.f); v0.y = fmaxf(v0.y, 0.f);
                v1.x = fmaxf(v1.x, 0.f); v1.y = fmaxf(v1.y, 0.f);
            }
            *(float2*)(out + o0 + nb) = v0;
            *(float2*)(out + o1 + nb) = v1;
        }
    }
}

// ---------------- misc small kernels (unchanged from R5) ----------------
__global__ void transpose_w(const float* __restrict__ in, float* __restrict__ out,
                            int K, int IC, int OC) {
    int i = blockIdx.x * blockDim.x + threadIdx.x;
    int total = K * IC * OC;
    if (i >= total) return;
    int oc = i % OC;
    int ic = (i / OC) % IC;
    int k  = i / (OC * IC);
    out[(k * OC + oc) * IC + ic] = in[i];
}

__global__ void norme_kernel(const float* __restrict__ emb, float* __restrict__ norme) {
    int k = blockIdx.x * blockDim.x + threadIdx.x;
    if (k >= 512) return;
    const float4* e = (const float4*)(emb + k * 128);
    float s = 0.f;
#pragma unroll 8
    for (int i = 0; i < 32; i++) {
        float4 v = e[i];
        s = fmaf(v.x, v.x, s); s = fmaf(v.y, v.y, s);
        s = fmaf(v.z, v.z, s); s = fmaf(v.w, v.w, s);
    }
    norme[k] = s;
}

__global__ void embT_kernel(const float* __restrict__ emb, float* __restrict__ embT) {
    int i = blockIdx.x * 256 + threadIdx.x;
    if (i >= 512 * 32) return;
    int c = i & 511, d4 = i >> 9;
    float4 v = *(const float4*)(emb + c * 128 + 4 * d4);
    *(float4*)(embT + (d4 * 512 + c) * 4) = v;
}

__global__ void pad_w1(const float* __restrict__ w, float* __restrict__ out) {
    int t = blockIdx.x * 256 + threadIdx.x;
    if (t >= 64 * 64) return;
    int r = t >> 6;
    out[t] = (r < 48) ? w[t] : 0.f;
}

__global__ void im2col_enc1(const float* __restrict__ x, float* __restrict__ col) {
    int t = blockIdx.x * 256 + threadIdx.x;
    int kidx = t & 63;
    int p = t >> 6;
    int ow = p & 127, oh = (p >> 7) & 127, n = p >> 14;
    float v = 0.f;
    if (kidx < 48) {
        int ic = kidx % 3;
        int kw = (kidx / 3) & 3;
        int kh = kidx / 12;
        int ih = 2 * oh - 1 + kh, iw = 2 * ow - 1 + kw;
        if ((unsigned)ih < 256u && (unsigned)iw < 256u)
            v = x[((n * 256 + ih) * 256 + iw) * 3 + ic];
    }
    col[t] = v;
}

template<int IC, int OC, int BM, int TM, int TN, bool HAS_BIAS, bool RELU_OUT>
__global__ void __launch_bounds__(256, 2) flat_gemm(
    const float* __restrict__ in, const float* __restrict__ w,
    const float* __restrict__ bias, float* __restrict__ out)
{
    constexpr int BK = 32;
    constexpr int BN = OC;
    constexpr int TX = BN / TN;
    constexpr int ASTR = BM + 2;
    __shared__ __align__(16) float As[BK * ASTR];
    __shared__ __align__(16) float Bs[BK * BN];
    int tid = threadIdx.x;
    int m0 = blockIdx.x * BM;
    int tx = tid % TX, ty = tid / TX;
    int c4 = tid & 7;
    int mp = tid >> 3;
    unsigned long long acc2[TM / 2][TN];
#pragma unroll
    for (int i = 0; i < TM / 2; i++)
#pragma unroll
        for (int j = 0; j < TN; j++) acc2[i][j] = 0ull;

    for (int kc = 0; kc < IC / BK; kc++) {
        __syncthreads();
#pragma unroll
        for (int pass = 0; pass < BM / 32; pass++) {
            int m = mp + pass * 32;
            int p = m0 + m;
            float4 v = *(const float4*)(in + (long)p * IC + kc * BK + 4 * c4);
            int kk = 4 * c4;
            As[(kk + 0) * ASTR + m] = v.x;
            As[(kk + 1) * ASTR + m] = v.y;
            As[(kk + 2) * ASTR + m] = v.z;
            As[(kk + 3) * ASTR + m] = v.w;
        }
        {
            const float* wb = w + kc * BK * OC;
#pragma unroll
            for (int i = 0; i < (BK * BN / 4) / 256; i++) {
                int idx = tid + i * 256;
                int kr = idx / (BN / 4);
                int n4 = idx % (BN / 4);
                *(float4*)(Bs + kr * BN + 4 * n4) = *(const float4*)(wb + kr * OC + 4 * n4);
            }
        }
        __syncthreads();
#pragma unroll 8
        for (int k = 0; k < BK; k++) {
            unsigned long long a2[TM / 2], b2[TN];
            const double* ap = (const double*)(As + k * ASTR + ty * TM);
#pragma unroll
            for (int i = 0; i < TM / 2; i++) a2[i] = __double_as_longlong(ap[i]);
            float b[TN];
#pragma unroll
            for (int j = 0; j < TN / 4; j++)
                *(float4*)(b + 4 * j) = *(const float4*)(Bs + k * BN + tx * TN + 4 * j);
#pragma unroll
            for (int j = 0; j < TN; j++) b2[j] = pk2(b[j], b[j]);
#pragma unroll
            for (int i = 0; i < TM / 2; i++)
#pragma unroll
                for (int j = 0; j < TN; j++) fma2(acc2[i][j], a2[i], b2[j]);
        }
    }
    float bv[TN];
#pragma unroll
    for (int j = 0; j < TN; j++) bv[j] = HAS_BIAS ? bias[tx * TN + j] : 0.f;
    int base_m = m0 + ty * TM;
#pragma unroll
    for (int i2 = 0; i2 < TM / 2; i2++) {
        float2 tv[TN];
#pragma unroll
        for (int j = 0; j < TN; j++) tv[j] = up2(acc2[i2][j]);
#pragma unroll
        for (int hh = 0; hh < 2; hh++) {
            int p = base_m + 2 * i2 + hh;
            float v[TN];
#pragma unroll
            for (int j = 0; j < TN; j++) {
                float t = (hh ? tv[j].y : tv[j].x) + bv[j];
                v[j] = RELU_OUT ? fmaxf(t, 0.f) : t;
            }
            long oaddr = (long)p * OC + tx * TN;
#pragma unroll
            for (int j = 0; j < TN / 4; j++)
                *(float4*)(out + oaddr + 4 * j) = *(float4*)(v + 4 * j);
        }
    }
}

template<bool RELU_OUT>
__global__ void conv1x1_res(const float* __restrict__ tin, const float* __restrict__ res,
                            const float* __restrict__ w, float* __restrict__ out) {
    int t = blockIdx.x * 256 + threadIdx.x;
    int oc = t & 127;
    long p0 = (long)(t >> 7) * 4;
    float wv[32];
#pragma unroll
    for (int ic = 0; ic < 32; ic++) wv[ic] = w[ic * 128 + oc];
    float accp[4] = {0.f, 0.f, 0.f, 0.f};
#pragma unroll
    for (int ic4 = 0; ic4 < 8; ic4++) {
#pragma unroll
        for (int p = 0; p < 4; p++) {
            float4 tv = *(const float4*)(tin + (p0 + p) * 32 + 4 * ic4);
            tv = relu4(tv);
            accp[p] = fmaf(tv.x, wv[4 * ic4],     accp[p]);
            accp[p] = fmaf(tv.y, wv[4 * ic4 + 1], accp[p]);
            accp[p] = fmaf(tv.z, wv[4 * ic4 + 2], accp[p]);
            accp[p] = fmaf(tv.w, wv[4 * ic4 + 3], accp[p]);
        }
    }
    long o = p0 * 128 + oc;
#pragma unroll
    for (int p = 0; p < 4; p++) {
        float v = res[o + p * 128] + accp[p];
        if (RELU_OUT) v = fmaxf(v, 0.f);
        out[o + p * 128] = v;
    }
}

__global__ void __launch_bounds__(128) vq16(const float* __restrict__ f,
                                            const float* __restrict__ embT,
                                            const float* __restrict__ emb,
                                            const float* __restrict__ norme,
                                            float* __restrict__ q) {
    __shared__ float4 xs4[16 * 32];
    __shared__ float rdist[16 * 128];
    __shared__ int   ridx[16 * 128];
    __shared__ int   best[16];
    int tid = threadIdx.x;
    long pixel0 = (long)blockIdx.x * 16;
    const float4* fin = (const float4*)(f + pixel0 * 128);
#pragma unroll
    for (int i = 0; i < 4; i++) xs4[tid + 128 * i] = fin[tid + 128 * i];
    __syncthreads();

    unsigned long long acc2[4][8];
#pragma unroll
    for (int j = 0; j < 4; j++)
#pragma unroll
        for (int p2 = 0; p2 < 8; p2++) acc2[j][p2] = 0ull;

    const float4* eT = (const float4*)embT;
    for (int d4 = 0; d4 < 32; d4++) {
        float4 ev[4];
#pragma unroll
        for (int j = 0; j < 4; j++) ev[j] = eT[d4 * 512 + 128 * j + tid];
        unsigned long long e2[4][4];
#pragma unroll
        for (int j = 0; j < 4; j++) {
            e2[j][0] = pk2(ev[j].x, ev[j].x);
            e2[j][1] = pk2(ev[j].y, ev[j].y);
            e2[j][2] = pk2(ev[j].z, ev[j].z);
            e2[j][3] = pk2(ev[j].w, ev[j].w);
        }
#pragma unroll
        for (int p2 = 0; p2 < 8; p2++) {
            float4 xa = xs4[(2 * p2) * 32 + d4];
            float4 xb = xs4[(2 * p2 + 1) * 32 + d4];
            unsigned long long xp0 = pk2(xa.x, xb.x);
            unsigned long long xp1 = pk2(xa.y, xb.y);
            unsigned long long xp2 = pk2(xa.z, xb.z);
            unsigned long long xp3 = pk2(xa.w, xb.w);
#pragma unroll
            for (int j = 0; j < 4; j++) {
                fma2(acc2[j][p2], xp0, e2[j][0]);
                fma2(acc2[j][p2], xp1, e2[j][1]);
                fma2(acc2[j][p2], xp2, e2[j][2]);
                fma2(acc2[j][p2], xp3, e2[j][3]);
            }
        }
    }
    float accs[4][16];
#pragma unroll
    for (int j = 0; j < 4; j++)
#pragma unroll
        for (int p2 = 0; p2 < 8; p2++) {
            float2 u = up2(acc2[j][p2]);
            accs[j][2 * p2] = u.x;
            accs[j][2 * p2 + 1] = u.y;
        }
    float nd[4];
#pragma unroll
    for (int j = 0; j < 4; j++) nd[j] = norme[tid + 128 * j];
#pragma unroll
    for (int p = 0; p < 16; p++) {
        float bd = 1e30f; int bi = 0;
#pragma unroll
        for (int j = 0; j < 4; j++) {
            float d = nd[j] - 2.f * accs[j][p];
            if (d < bd) { bd = d; bi = tid + 128 * j; }
        }
        rdist[p * 128 + tid] = bd;
        ridx[p * 128 + tid]  = bi;
    }
    __syncthreads();
    if (tid < 16) {
        float bd = 1e30f; int bi = 1 << 30;
        for (int u = 0; u < 128; u++) {
            float d = rdist[tid * 128 + u];
            int   i = ridx[tid * 128 + u];
            if (d < bd || (d == bd && i < bi)) { bd = d; bi = i; }
        }
        best[tid] = bi;
    }
    __syncthreads();
#pragma unroll
    for (int p = 0; p < 16; p++)
        q[(pixel0 + p) * 128 + tid] = emb[best[p] * 128 + tid];
}

__global__ void dt2_kernel(const float* __restrict__ in, const float* __restrict__ wt,
                           const float* __restrict__ b, float* __restrict__ out) {
    int t = blockIdx.x * 256 + threadIdx.x;
    int ow = t & 255;
    int oh = (t >> 8) & 255;
    int n  = t >> 16;
    float a0 = b[0], a1 = b[1], a2 = b[2];
#pragma unroll
    for (int dh = 0; dh < 2; dh++) {
        int kh = (oh & 1) + 2 * dh;
        int ih2 = oh + kh - 2;
        if (ih2 < 0 || ih2 >= 256) continue;
        int ih = ih2 >> 1;
#pragma unroll
        for (int dw = 0; dw < 2; dw++) {
            int kw = (ow & 1) + 2 * dw;
            int iw2 = ow + kw - 2;
            if (iw2 < 0 || iw2 >= 256) continue;
            int iw = iw2 >> 1;
            const float4* xp = (const float4*)(in + ((n * 128 + ih) * 128 + iw) * 64);
            const float* wb = wt + (kh * 4 + kw) * 3 * 64;
            const float4* w0 = (const float4*)(wb);
            const float4* w1 = (const float4*)(wb + 64);
            const float4* w2 = (const float4*)(wb + 128);
#pragma unroll 4
            for (int ic4 = 0; ic4 < 16; ic4++) {
                float4 x4 = xp[ic4];
                a0 += dot4(x4, w0[ic4]);
                a1 += dot4(x4, w1[ic4]);
                a2 += dot4(x4, w2[ic4]);
            }
        }
    }
    float* op = out + (long)((n * 256 + oh) * 256 + ow) * 3;
    op[0] = a0; op[1] = a1; op[2] = a2;
}

extern "C" void kernel_launch(void* const* d_in, const int* in_sizes, int n_in,
                              void* d_out, int out_size) {
    const float* x       = (const float*)d_in[0];
    const float* emb     = (const float*)d_in[1];
    const float* enc_w1  = (const float*)d_in[2];
    const float* enc_b1  = (const float*)d_in[3];
    const float* enc_w2  = (const float*)d_in[4];
    const float* enc_b2  = (const float*)d_in[5];
    const float* enc_w3  = (const float*)d_in[6];
    const float* enc_b3  = (const float*)d_in[7];
    const float* erb1_w1 = (const float*)d_in[8];
    const float* erb1_w2 = (const float*)d_in[9];
    const float* erb2_w1 = (const float*)d_in[10];
    const float* erb2_w2 = (const float*)d_in[11];
    const float* dec_w   = (const float*)d_in[12];
    const float* dec_b   = (const float*)d_in[13];
    const float* drb1_w1 = (const float*)d_in[14];
    const float* drb1_w2 = (const float*)d_in[15];
    const float* drb2_w1 = (const float*)d_in[16];
    const float* drb2_w2 = (const float*)d_in[17];
    const float* dt1_w   = (const float*)d_in[18];
    const float* dt1_b   = (const float*)d_in[19];
    const float* dt2_w   = (const float*)d_in[20];
    const float* dt2_b   = (const float*)d_in[21];

    float *pA, *pCol, *pCv, *pB1, *pB2, *pT, *pN, *pE, *pWdt2, *pW1p, *pWT;
    cudaGetSymbolAddress((void**)&pA,    g_A);
    cudaGetSymbolAddress((void**)&pCol,  g_col);
    cudaGetSymbolAddress((void**)&pCv,   g_cvt);
    cudaGetSymbolAddress((void**)&pB1,   g_B1);
    cudaGetSymbolAddress((void**)&pB2,   g_B2);
    cudaGetSymbolAddress((void**)&pT,    g_T);
    cudaGetSymbolAddress((void**)&pN,    g_norme);
    cudaGetSymbolAddress((void**)&pE,    g_embT);
    cudaGetSymbolAddress((void**)&pWdt2, g_wdt2);
    cudaGetSymbolAddress((void**)&pW1p,  g_w1p);
    cudaGetSymbolAddress((void**)&pWT,   g_wtens);

    float* yout = (float*)d_out;
    float* fout = yout + Y_SZ;
    float* qout = fout + F_SZ;

    // dynamic smem per stage-pair
    const int SM128 = (2 * (16 * 132 * 2) + 2 * (16 * 132 * 2)) * 2 * 4;  // 135168
    const int SM64  = (2 * (16 * 132 * 2) + 2 * (16 * 68  * 2)) * 2 * 4;  // 102400
    const int SM32  = (2 * (16 * 132 * 2) + 2 * (16 * 36  * 2)) * 2 * 4;  // 86016
    cudaFuncSetAttribute(conv_mma<0, 4, 4, 2, 1, 128, 64, 128, 4, true, true>,
                         cudaFuncAttributeMaxDynamicSharedMemorySize, SM128);
    cudaFuncSetAttribute(conv_mma<0, 3, 3, 1, 1, 64, 128, 128, 4, true, false>,
                         cudaFuncAttributeMaxDynamicSharedMemorySize, SM128);
    cudaFuncSetAttribute(conv_mma<0, 3, 3, 1, 1, 64, 128, 32, 4, false, false>,
                         cudaFuncAttributeMaxDynamicSharedMemorySize, SM32);
    cudaFuncSetAttribute(conv_mma<0, 3, 3, 1, 1, 64, 128, 128, 3, true, false>,
                         cudaFuncAttributeMaxDynamicSharedMemorySize, SM128);
    cudaFuncSetAttribute(conv_mma<0, 3, 3, 1, 1, 64, 128, 32, 3, false, false>,
                         cudaFuncAttributeMaxDynamicSharedMemorySize, SM32);
    cudaFuncSetAttribute(conv_mma<1, 4, 4, 1, 0, 64, 128, 64, 3, true, true>,
                         cudaFuncAttributeMaxDynamicSharedMemorySize, SM64);

    // prep + enc1
    im2col_enc1<<<65536, 256>>>(x, pCol);
    pad_w1<<<16, 256>>>(enc_w1, pW1p);
    prep_w_tf32<16, 64, 128><<<512, 256>>>(enc_w2, pWT + WP_ENC2);
    flat_gemm<64, 64, 128, 8, 4, true, true><<<2048, 256>>>(pCol, pW1p, enc_b1, pA);
    prep_w_tf32<9, 128, 128><<<576, 256>>>(enc_w3, pWT + WP_ENC3);
    prep_w_tf32<9, 128, 32><<<144, 256>>>(erb1_w1, pWT + WP_ERB1);
    prep_w_tf32<9, 128, 32><<<144, 256>>>(erb2_w1, pWT + WP_ERB2);
    prep_w_tf32<9, 128, 128><<<576, 256>>>(dec_w, pWT + WP_DEC);
    prep_w_tf32<9, 128, 32><<<144, 256>>>(drb1_w1, pWT + WP_DRB1);
    prep_w_tf32<9, 128, 32><<<144, 256>>>(drb2_w1, pWT + WP_DRB2);
    prep_w_tf32<16, 128, 64><<<512, 256>>>(dt1_w, pWT + WP_DT1);
    transpose_w<<<12, 256>>>(dt2_w, pWdt2, 16, 64, 3);
    norme_kernel<<<2, 256>>>(emb, pN);
    embT_kernel<<<64, 256>>>(emb, pE);

    // Encoder (4-pass tf32)
    cvt_act<64, false><<<16384, 256>>>(pA, pCv, 262144);
    conv_mma<0, 4, 4, 2, 1, 128, 64, 128, 4, true, true>
        <<<512, 256, SM128>>>(pCv, pWT + WP_ENC2, enc_b2, pB1);
    cvt_act<128, false><<<8192, 256>>>(pB1, pCv, 65536);
    conv_mma<0, 3, 3, 1, 1, 64, 128, 128, 4, true, false>
        <<<512, 256, SM128>>>(pCv, pWT + WP_ENC3, enc_b3, pB2);
    cvt_act<128, true><<<8192, 256>>>(pB2, pCv, 65536);
    conv_mma<0, 3, 3, 1, 1, 64, 128, 32, 4, false, false>
        <<<512, 256, SM32>>>(pCv, pWT + WP_ERB1, nullptr, pT);
    conv1x1_res<false><<<8192, 256>>>(pT, pB2, erb1_w2, pB1);
    cvt_act<128, true><<<8192, 256>>>(pB1, pCv, 65536);
    conv_mma<0, 3, 3, 1, 1, 64, 128, 32, 4, false, false>
        <<<512, 256, SM32>>>(pCv, pWT + WP_ERB2, nullptr, pT);
    conv1x1_res<true><<<8192, 256>>>(pT, pB1, erb2_w2, fout);   // f -> d_out

    // VQ
    vq16<<<4096, 128>>>(fout, pE, emb, pN, qout);               // q -> d_out

    // Decoder (3-pass tf32)
    cvt_act<128, false><<<8192, 256>>>(qout, pCv, 65536);
    conv_mma<0, 3, 3, 1, 1, 64, 128, 128, 3, true, false>
        <<<512, 256, SM128>>>(pCv, pWT + WP_DEC, dec_b, pB1);
    cvt_act<128, true><<<8192, 256>>>(pB1, pCv, 65536);
    conv_mma<0, 3, 3, 1, 1, 64, 128, 32, 3, false, false>
        <<<512, 256, SM32>>>(pCv, pWT + WP_DRB1, nullptr, pT);
    conv1x1_res<false><<<8192, 256>>>(pT, pB1, drb1_w2, pB2);
    cvt_act<128, true><<<8192, 256>>>(pB2, pCv, 65536);
    conv_mma<0, 3, 3, 1, 1, 64, 128, 32, 3, false, false>
        <<<512, 256, SM32>>>(pCv, pWT + WP_DRB2, nullptr, pT);
    conv1x1_res<true><<<8192, 256>>>(pT, pB2, drb2_w2, pB1);
    cvt_act<128, false><<<8192, 256>>>(pB1, pCv, 65536);
    conv_mma<1, 4, 4, 1, 0, 64, 128, 64, 3, true, true>
        <<<dim3(512, 4), 256, SM64>>>(pCv, pWT + WP_DT1, dt1_b, pA);
    dt2_kernel<<<4096, 256>>>(pA, pWdt2, dt2_b, yout);
}

// round 9
// speedup vs baseline: 1.0784x; 1.0730x over previous
#include <cuda_runtime.h>
#include <cstdint>

#define Y_SZ  (16*256*256*3)
#define F_SZ  (16*64*64*128)

__device__ __align__(16) float g_A[16*128*128*64];    // enc1 out / dt1 out
__device__ __align__(16) float g_col[16*128*128*64];  // enc1 im2col
__device__ __align__(16) float g_cvtA[16*128*128*64*2];
__device__ __align__(16) float g_cvtB[16*64*64*256];
__device__ __align__(16) float g_B1[16*64*64*128];
__device__ __align__(16) float g_B2[16*64*64*128];
__device__ __align__(16) float g_T[16*64*64*32];
__device__ __align__(16) float g_norme[512];
__device__ __align__(16) float g_embT[512*128];
__device__ __align__(16) float g_wdt2[16*3*64];
__device__ __align__(16) float g_w1p[64*64];
__device__ __align__(16) float g_wtens[1536*1024];

#define WP_ENC2 0
#define WP_ENC3 270336
#define WP_ERB1 574464
#define WP_ERB2 657408
#define WP_DEC  740352
#define WP_DRB1 1044480
#define WP_DRB2 1127424
#define WP_DT1  1210368

__device__ __forceinline__ float4 relu4(float4 a) {
    a.x = fmaxf(a.x, 0.f); a.y = fmaxf(a.y, 0.f);
    a.z = fmaxf(a.z, 0.f); a.w = fmaxf(a.w, 0.f);
    return a;
}
__device__ __forceinline__ float dot4(float4 a, float4 b) {
    return fmaf(a.x, b.x, fmaf(a.y, b.y, fmaf(a.z, b.z, a.w * b.w)));
}
__device__ __forceinline__ unsigned long long pk2(float x, float y) {
    unsigned long long r;
    asm("mov.b64 %0, {%1, %2};" : "=l"(r)
        : "r"(__float_as_uint(x)), "r"(__float_as_uint(y)));
    return r;
}
__device__ __forceinline__ float2 up2(unsigned long long v) {
    unsigned int lo, hi;
    asm("mov.b64 {%0, %1}, %2;" : "=r"(lo), "=r"(hi) : "l"(v));
    return make_float2(__uint_as_float(lo), __uint_as_float(hi));
}
__device__ __forceinline__ void fma2(unsigned long long& d,
                                     unsigned long long a, unsigned long long b) {
    asm("fma.rn.f32x2 %0, %1, %2, %0;" : "+l"(d) : "l"(a), "l"(b));
}
__device__ __forceinline__ float rna_tf32(float x) {
    uint32_t o;
    asm("cvt.rna.tf32.f32 %0, %1;" : "=r"(o) : "f"(x));
    return __uint_as_float(o);
}
__device__ __forceinline__ void mma8(float* c, const uint32_t* a, float2 b) {
    asm volatile(
        "mma.sync.aligned.m16n8k8.row.col.f32.tf32.tf32.f32 "
        "{%0,%1,%2,%3},{%4,%5,%6,%7},{%8,%9},{%0,%1,%2,%3};"
        : "+f"(c[0]), "+f"(c[1]), "+f"(c[2]), "+f"(c[3])
        : "r"(a[0]), "r"(a[1]), "r"(a[2]), "r"(a[3]),
          "r"(__float_as_uint(b.x)), "r"(__float_as_uint(b.y)));
}
__device__ __forceinline__ uint32_t smem_u32(const void* p) {
    uint32_t a;
    asm("{ .reg .u64 t; cvta.to.shared.u64 t, %1; cvt.u32.u64 %0, t; }"
        : "=r"(a) : "l"(p));
    return a;
}
__device__ __forceinline__ void cpasync16(uint32_t dst, const void* src) {
    asm volatile("cp.async.cg.shared.global [%0], [%1], 16;" :: "r"(dst), "l"(src));
}
__device__ __forceinline__ void cpasync_commit() {
    asm volatile("cp.async.commit_group;" ::: "memory");
}
__device__ __forceinline__ void cpasync_wait0() {
    asm volatile("cp.async.wait_group 0;" ::: "memory");
}

// ---- weight prep: [tap][ic][oc] -> per-(tap,kc) hi/lo tiles in mma pair layout ----
template<int TAPS, int IC, int OC>
__global__ void prep_w_tf32(const float* __restrict__ w, float* __restrict__ out) {
    constexpr int KC = IC / 32;
    constexpr int BF = 32 * (OC + 4);
    int t = blockIdx.x * 256 + threadIdx.x;
    if (t >= TAPS * IC * OC) return;
    int oc = t % OC;
    int r = t / OC;
    int ic = r % IC;
    int tap = r / IC;
    int kc = ic >> 5, lk = ic & 31;
    int k8 = lk >> 3, t4 = lk & 3, half = (lk >> 2) & 1;
    float v = w[t];
    float hi = rna_tf32(v);
    float lo = rna_tf32(v - hi);
    long base = (long)(tap * KC + kc) * 2 * BF;
    int idx = ((k8 * 4 + t4) * (OC + 4) + oc) * 2 + half;
    out[base + idx] = hi;
    out[base + BF + idx] = lo;
}

// ================= pipelined mma.sync tf32 implicit-GEMM conv =================
template<int MODE, int KH, int KW, int STRIDE, int PAD, int IH, int IC, int OC,
         int NPASS, bool HAS_BIAS, bool RELU_OUT, bool WRITE_OUT, bool WRITE_CVT,
         bool CVT_RELU>
__global__ void __launch_bounds__(256, (OC >= 128) ? 1 : 2) conv_mma(
    const float* __restrict__ cv, const float* __restrict__ wp,
    const float* __restrict__ bias, float* __restrict__ out,
    float* __restrict__ cvt_out)
{
    constexpr int KC = IC / 32;
    constexpr int NTAPS = (MODE == 0) ? KH * KW : 4;
    constexpr int SE = (MODE == 0) ? STRIDE : 1;
    constexpr int BMp = 132;
    constexpr int BNp = OC + 4;
    constexpr int AF = 16 * BMp * 2;
    constexpr int BF = 16 * BNp * 2;
    constexpr int SS = 2 * AF + 2 * BF;
    constexpr int NT = OC / 16;
    constexpr int TOTAL = NTAPS * KC;

    extern __shared__ __align__(16) float sm[];

    int tid = threadIdx.x;
    int lane = tid & 31;
    int g = lane >> 2, t4 = lane & 3;
    int wid = tid >> 5;
    int wm = wid >> 1, wn = wid & 1;
    int m0 = blockIdx.x * 128;
    int po = 0, pw_ = 0;
    if (MODE == 1) { po = blockIdx.y >> 1; pw_ = blockIdx.y & 1; }
    int c4 = tid & 7, mp = tid >> 3;
    int k8 = c4 >> 1, h = c4 & 1;

    float acc[2][NT][4];
#pragma unroll
    for (int i = 0; i < 2; i++)
#pragma unroll
        for (int j = 0; j < NT; j++)
#pragma unroll
            for (int u = 0; u < 4; u++) acc[i][j][u] = 0.f;

    auto tapgeom = [&](int it, int& hoff, int& woff, int& wtap, int& kc) {
        int tap = it / KC; kc = it % KC;
        if (MODE == 0) {
            int kh = tap / KW, kw = tap % KW;
            hoff = kh - PAD; woff = kw - PAD; wtap = tap;
        } else {
            int dh = tap >> 1, dw = tap & 1;
            hoff = po + dh - 1; woff = pw_ + dw - 1;
            wtap = (po + 2 * dh) * 4 + (pw_ + 2 * dw);
        }
    };
    auto fillregs = [&](int it, float4* rh, float4* rl) {
        int hoff, woff, wtap, kc;
        tapgeom(it, hoff, woff, wtap, kc);
#pragma unroll
        for (int pass = 0; pass < 4; pass++) {
            int m = mp + 32 * pass;
            int p = m0 + m;
            int n_img = p >> 12, oh = (p >> 6) & 63, ow = p & 63;
            int ih = oh * SE + hoff, iw = ow * SE + woff;
            rh[pass] = make_float4(0.f, 0.f, 0.f, 0.f);
            rl[pass] = make_float4(0.f, 0.f, 0.f, 0.f);
            if ((unsigned)ih < (unsigned)IH && (unsigned)iw < (unsigned)IH) {
                long P = ((long)n_img * IH + ih) * IH + iw;
                const float* b = cv + P * 2 * IC + kc * 64 + 4 * c4;
                rh[pass] = *(const float4*)(b);
                rl[pass] = *(const float4*)(b + 32);
            }
        }
    };
    auto stsregs = [&](int s, const float4* rh, const float4* rl) {
        float* Ah = sm + s * SS;
        float* Al = Ah + AF;
#pragma unroll
        for (int pass = 0; pass < 4; pass++) {
            int m = mp + 32 * pass;
            int rot = ((m + 4 * k8) & 127) * 2 + h;
            int r0 = (k8 * 4 + 0) * (2 * BMp) + rot;
            int r1 = (k8 * 4 + 1) * (2 * BMp) + rot;
            int r2 = (k8 * 4 + 2) * (2 * BMp) + rot;
            int r3 = (k8 * 4 + 3) * (2 * BMp) + rot;
            Ah[r0] = rh[pass].x; Ah[r1] = rh[pass].y;
            Ah[r2] = rh[pass].z; Ah[r3] = rh[pass].w;
            Al[r0] = rl[pass].x; Al[r1] = rl[pass].y;
            Al[r2] = rl[pass].z; Al[r3] = rl[pass].w;
        }
    };
    auto copyB = [&](int it, int s) {
        int hoff, woff, wtap, kc;
        tapgeom(it, hoff, woff, wtap, kc);
        const float* src = wp + (long)(wtap * KC + kc) * 2 * BF;
        uint32_t dst = smem_u32(sm + s * SS + 2 * AF);
        constexpr int NF4 = 2 * BF / 4;
#pragma unroll
        for (int i = 0; i < (NF4 + 255) / 256; i++) {
            int idx = tid + i * 256;
            if (idx < NF4) cpasync16(dst + idx * 16, src + idx * 4);
        }
        cpasync_commit();
    };
    auto do_mma = [&](int s) {
        const float* Ah = sm + s * SS;
        const float* Al = Ah + AF;
        const float* Bh = Ah + 2 * AF;
        const float* Bl = Bh + BF;
#pragma unroll
        for (int kk = 0; kk < 4; kk++) {
            uint32_t ah[2][4], al[2][4];
            const float2* arh = (const float2*)Ah + (kk * 4 + t4) * BMp;
            const float2* arl = (const float2*)Al + (kk * 4 + t4) * BMp;
#pragma unroll
            for (int mt = 0; mt < 2; mt++) {
                int c0 = (wm * 32 + mt * 16 + g + 4 * kk) & 127;
                int c1 = (wm * 32 + mt * 16 + g + 8 + 4 * kk) & 127;
                float2 q0 = arh[c0], q1 = arh[c1];
                ah[mt][0] = __float_as_uint(q0.x);
                ah[mt][1] = __float_as_uint(q1.x);
                ah[mt][2] = __float_as_uint(q0.y);
                ah[mt][3] = __float_as_uint(q1.y);
                float2 s0 = arl[c0], s1 = arl[c1];
                al[mt][0] = __float_as_uint(s0.x);
                al[mt][1] = __float_as_uint(s1.x);
                al[mt][2] = __float_as_uint(s0.y);
                al[mt][3] = __float_as_uint(s1.y);
            }
            // hoist ALL B fragments for this kk
            float2 bh[NT], bl[NT];
            const float2* brh = (const float2*)Bh + (kk * 4 + t4) * BNp + wn * (OC / 2) + g;
            const float2* brl = (const float2*)Bl + (kk * 4 + t4) * BNp + wn * (OC / 2) + g;
#pragma unroll
            for (int nt = 0; nt < NT; nt++) { bh[nt] = brh[nt * 8]; bl[nt] = brl[nt * 8]; }
            // pass-major: dependency distance = 2*NT
#pragma unroll
            for (int nt = 0; nt < NT; nt++)
#pragma unroll
                for (int mt = 0; mt < 2; mt++) mma8(acc[mt][nt], ah[mt], bh[nt]);
#pragma unroll
            for (int nt = 0; nt < NT; nt++)
#pragma unroll
                for (int mt = 0; mt < 2; mt++) mma8(acc[mt][nt], al[mt], bh[nt]);
#pragma unroll
            for (int nt = 0; nt < NT; nt++)
#pragma unroll
                for (int mt = 0; mt < 2; mt++) mma8(acc[mt][nt], ah[mt], bl[nt]);
            if (NPASS == 4) {
#pragma unroll
                for (int nt = 0; nt < NT; nt++)
#pragma unroll
                    for (int mt = 0; mt < 2; mt++) mma8(acc[mt][nt], al[mt], bl[nt]);
            }
        }
    };

    {
        float4 rh[4], rl[4];
        fillregs(0, rh, rl);
        stsregs(0, rh, rl);
        copyB(0, 0);
        cpasync_wait0();
        __syncthreads();
    }
    for (int it = 0; it < TOTAL; it++) {
        int cur = it & 1, nxt = cur ^ 1;
        float4 rh[4], rl[4];
        bool have = (it + 1 < TOTAL);
        if (have) {
            fillregs(it + 1, rh, rl);
            copyB(it + 1, nxt);
        }
        do_mma(cur);
        if (have) stsregs(nxt, rh, rl);
        cpasync_wait0();
        __syncthreads();
    }

    // ---- epilogue
#pragma unroll
    for (int mt = 0; mt < 2; mt++) {
        int r0 = m0 + wm * 32 + mt * 16 + g;
        int r1 = r0 + 8;
        long o0, o1;
        if (MODE == 0) {
            o0 = (long)r0 * OC;
            o1 = (long)r1 * OC;
        } else {
            int n0 = r0 >> 12, a0 = (r0 >> 6) & 63, b0 = r0 & 63;
            int n1 = r1 >> 12, a1 = (r1 >> 6) & 63, b1 = r1 & 63;
            o0 = (((long)n0 * 128 + 2 * a0 + po) * 128 + 2 * b0 + pw_) * OC;
            o1 = (((long)n1 * 128 + 2 * a1 + po) * 128 + 2 * b1 + pw_) * OC;
        }
#pragma unroll
        for (int nt = 0; nt < NT; nt++) {
            int nb = wn * (OC / 2) + nt * 8 + 2 * t4;
            float b0v = HAS_BIAS ? bias[nb] : 0.f;
            float b1v = HAS_BIAS ? bias[nb + 1] : 0.f;
            float2 v0 = make_float2(acc[mt][nt][0] + b0v, acc[mt][nt][1] + b1v);
            float2 v1 = make_float2(acc[mt][nt][2] + b0v, acc[mt][nt][3] + b1v);
            if (RELU_OUT) {
                v0.x = fmaxf(v0.x, 0.f); v0.y = fmaxf(v0.y, 0.f);
                v1.x = fmaxf(v1.x, 0.f); v1.y = fmaxf(v1.y, 0.f);
            }
            if (WRITE_OUT) {
                *(float2*)(out + o0 + nb) = v0;
                *(float2*)(out + o1 + nb) = v1;
            }
            if (WRITE_CVT) {
                float c0x = CVT_RELU ? fmaxf(v0.x, 0.f) : v0.x;
                float c0y = CVT_RELU ? fmaxf(v0.y, 0.f) : v0.y;
                float c1x = CVT_RELU ? fmaxf(v1.x, 0.f) : v1.x;
                float c1y = CVT_RELU ? fmaxf(v1.y, 0.f) : v1.y;
                float h0x = rna_tf32(c0x), h0y = rna_tf32(c0y);
                float h1x = rna_tf32(c1x), h1y = rna_tf32(c1y);
                long cb0 = (long)r0 * 2 * OC + ((nb >> 5) << 6) + (nb & 31);
                long cb1 = (long)r1 * 2 * OC + ((nb >> 5) << 6) + (nb & 31);
                *(float2*)(cvt_out + cb0) = make_float2(h0x, h0y);
                *(float2*)(cvt_out + cb0 + 32) =
                    make_float2(rna_tf32(c0x - h0x), rna_tf32(c0y - h0y));
                *(float2*)(cvt_out + cb1) = make_float2(h1x, h1y);
                *(float2*)(cvt_out + cb1 + 32) =
                    make_float2(rna_tf32(c1x - h1x), rna_tf32(c1y - h1y));
            }
        }
    }
}

// ---------------- small kernels ----------------
__global__ void transpose_w(const float* __restrict__ in, float* __restrict__ out,
                            int K, int IC, int OC) {
    int i = blockIdx.x * blockDim.x + threadIdx.x;
    int total = K * IC * OC;
    if (i >= total) return;
    int oc = i % OC;
    int ic = (i / OC) % IC;
    int k  = i / (OC * IC);
    out[(k * OC + oc) * IC + ic] = in[i];
}

__global__ void norme_kernel(const float* __restrict__ emb, float* __restrict__ norme) {
    int k = blockIdx.x * blockDim.x + threadIdx.x;
    if (k >= 512) return;
    const float4* e = (const float4*)(emb + k * 128);
    float s = 0.f;
#pragma unroll 8
    for (int i = 0; i < 32; i++) {
        float4 v = e[i];
        s = fmaf(v.x, v.x, s); s = fmaf(v.y, v.y, s);
        s = fmaf(v.z, v.z, s); s = fmaf(v.w, v.w, s);
    }
    norme[k] = s;
}

__global__ void embT_kernel(const float* __restrict__ emb, float* __restrict__ embT) {
    int i = blockIdx.x * 256 + threadIdx.x;
    if (i >= 512 * 32) return;
    int c = i & 511, d4 = i >> 9;
    float4 v = *(const float4*)(emb + c * 128 + 4 * d4);
    *(float4*)(embT + (d4 * 512 + c) * 4) = v;
}

__global__ void pad_w1(const float* __restrict__ w, float* __restrict__ out) {
    int t = blockIdx.x * 256 + threadIdx.x;
    if (t >= 64 * 64) return;
    int r = t >> 6;
    out[t] = (r < 48) ? w[t] : 0.f;
}

__global__ void im2col_enc1(const float* __restrict__ x, float* __restrict__ col) {
    int t = blockIdx.x * 256 + threadIdx.x;
    int kidx = t & 63;
    int p = t >> 6;
    int ow = p & 127, oh = (p >> 7) & 127, n = p >> 14;
    float v = 0.f;
    if (kidx < 48) {
        int ic = kidx % 3;
        int kw = (kidx / 3) & 3;
        int kh = kidx / 12;
        int ih = 2 * oh - 1 + kh, iw = 2 * ow - 1 + kw;
        if ((unsigned)ih < 256u && (unsigned)iw < 256u)
            v = x[((n * 256 + ih) * 256 + iw) * 3 + ic];
    }
    col[t] = v;
}

// enc1 flat GEMM; writes cvt form directly (consumer is enc2 mma)
template<int IC, int OC, int BM, int TM, int TN, bool HAS_BIAS>
__global__ void __launch_bounds__(256, 2) flat_gemm_cvt(
    const float* __restrict__ in, const float* __restrict__ w,
    const float* __restrict__ bias, float* __restrict__ cvt)
{
    constexpr int BK = 32;
    constexpr int BN = OC;
    constexpr int TX = BN / TN;
    constexpr int ASTR = BM + 2;
    __shared__ __align__(16) float As[BK * ASTR];
    __shared__ __align__(16) float Bs[BK * BN];
    int tid = threadIdx.x;
    int m0 = blockIdx.x * BM;
    int tx = tid % TX, ty = tid / TX;
    int c4 = tid & 7;
    int mp = tid >> 3;
    unsigned long long acc2[TM / 2][TN];
#pragma unroll
    for (int i = 0; i < TM / 2; i++)
#pragma unroll
        for (int j = 0; j < TN; j++) acc2[i][j] = 0ull;

    for (int kc = 0; kc < IC / BK; kc++) {
        __syncthreads();
#pragma unroll
        for (int pass = 0; pass < BM / 32; pass++) {
            int m = mp + pass * 32;
            int p = m0 + m;
            float4 v = *(const float4*)(in + (long)p * IC + kc * BK + 4 * c4);
            int kk = 4 * c4;
            As[(kk + 0) * ASTR + m] = v.x;
            As[(kk + 1) * ASTR + m] = v.y;
            As[(kk + 2) * ASTR + m] = v.z;
            As[(kk + 3) * ASTR + m] = v.w;
        }
        {
            const float* wb = w + kc * BK * OC;
#pragma unroll
            for (int i = 0; i < (BK * BN / 4) / 256; i++) {
                int idx = tid + i * 256;
                int kr = idx / (BN / 4);
                int n4 = idx % (BN / 4);
                *(float4*)(Bs + kr * BN + 4 * n4) = *(const float4*)(wb + kr * OC + 4 * n4);
            }
        }
        __syncthreads();
#pragma unroll 8
        for (int k = 0; k < BK; k++) {
            unsigned long long a2[TM / 2], b2[TN];
            const double* ap = (const double*)(As + k * ASTR + ty * TM);
#pragma unroll
            for (int i = 0; i < TM / 2; i++) a2[i] = __double_as_longlong(ap[i]);
            float b[TN];
#pragma unroll
            for (int j = 0; j < TN / 4; j++)
                *(float4*)(b + 4 * j) = *(const float4*)(Bs + k * BN + tx * TN + 4 * j);
#pragma unroll
            for (int j = 0; j < TN; j++) b2[j] = pk2(b[j], b[j]);
#pragma unroll
            for (int i = 0; i < TM / 2; i++)
#pragma unroll
                for (int j = 0; j < TN; j++) fma2(acc2[i][j], a2[i], b2[j]);
        }
    }
    float bv[TN];
#pragma unroll
    for (int j = 0; j < TN; j++) bv[j] = HAS_BIAS ? bias[tx * TN + j] : 0.f;
    int base_m = m0 + ty * TM;
    int col0 = tx * TN;                       // TN=4 -> 4-aligned
    int kcq = col0 >> 5, off = col0 & 31;
#pragma unroll
    for (int i2 = 0; i2 < TM / 2; i2++) {
        float2 tv[TN];
#pragma unroll
        for (int j = 0; j < TN; j++) tv[j] = up2(acc2[i2][j]);
#pragma unroll
        for (int hh = 0; hh < 2; hh++) {
            int p = base_m + 2 * i2 + hh;
            float4 v;
            v.x = fmaxf((hh ? tv[0].y : tv[0].x) + bv[0], 0.f);
            v.y = fmaxf((hh ? tv[1].y : tv[1].x) + bv[1], 0.f);
            v.z = fmaxf((hh ? tv[2].y : tv[2].x) + bv[2], 0.f);
            v.w = fmaxf((hh ? tv[3].y : tv[3].x) + bv[3], 0.f);
            float4 hi = make_float4(rna_tf32(v.x), rna_tf32(v.y),
                                    rna_tf32(v.z), rna_tf32(v.w));
            float4 lo = make_float4(rna_tf32(v.x - hi.x), rna_tf32(v.y - hi.y),
                                    rna_tf32(v.z - hi.z), rna_tf32(v.w - hi.w));
            long base = (long)p * 2 * OC + kcq * 64 + off;
            *(float4*)(cvt + base) = hi;
            *(float4*)(cvt + base + 32) = lo;
        }
    }
}

// 1x1 conv (relu in) + residual; optional fp32 out + cvt out
template<bool RELU_OUT, bool WRITE_OUT, bool WRITE_CVT, bool CVT_RELU>
__global__ void conv1x1_res(const float* __restrict__ tin, const float* __restrict__ res,
                            const float* __restrict__ w, float* __restrict__ out,
                            float* __restrict__ cvt) {
    int t = blockIdx.x * 256 + threadIdx.x;
    int oc = t & 127;
    long p0 = (long)(t >> 7) * 4;
    float wv[32];
#pragma unroll
    for (int ic = 0; ic < 32; ic++) wv[ic] = w[ic * 128 + oc];
    float accp[4] = {0.f, 0.f, 0.f, 0.f};
#pragma unroll
    for (int ic4 = 0; ic4 < 8; ic4++) {
#pragma unroll
        for (int p = 0; p < 4; p++) {
            float4 tv = *(const float4*)(tin + (p0 + p) * 32 + 4 * ic4);
            tv = relu4(tv);
            accp[p] = fmaf(tv.x, wv[4 * ic4],     accp[p]);
            accp[p] = fmaf(tv.y, wv[4 * ic4 + 1], accp[p]);
            accp[p] = fmaf(tv.z, wv[4 * ic4 + 2], accp[p]);
            accp[p] = fmaf(tv.w, wv[4 * ic4 + 3], accp[p]);
        }
    }
    long o = p0 * 128 + oc;
    int kcq = oc >> 5, off = oc & 31;
#pragma unroll
    for (int p = 0; p < 4; p++) {
        float v = res[o + p * 128] + accp[p];
        if (RELU_OUT) v = fmaxf(v, 0.f);
        if (WRITE_OUT) out[o + p * 128] = v;
        if (WRITE_CVT) {
            float cvv = CVT_RELU ? fmaxf(v, 0.f) : v;
            float hi = rna_tf32(cvv);
            long base = (p0 + p) * 256 + kcq * 64 + off;
            cvt[base] = hi;
            cvt[base + 32] = rna_tf32(cvv - hi);
        }
    }
}

// VQ: also writes cvt(q) for the decoder conv
__global__ void __launch_bounds__(128) vq16(const float* __restrict__ f,
                                            const float* __restrict__ embT,
                                            const float* __restrict__ emb,
                                            const float* __restrict__ norme,
                                            float* __restrict__ q,
                                            float* __restrict__ qcvt) {
    __shared__ float4 xs4[16 * 32];
    __shared__ float rdist[16 * 128];
    __shared__ int   ridx[16 * 128];
    __shared__ int   best[16];
    int tid = threadIdx.x;
    long pixel0 = (long)blockIdx.x * 16;
    const float4* fin = (const float4*)(f + pixel0 * 128);
#pragma unroll
    for (int i = 0; i < 4; i++) xs4[tid + 128 * i] = fin[tid + 128 * i];
    __syncthreads();

    unsigned long long acc2[4][8];
#pragma unroll
    for (int j = 0; j < 4; j++)
#pragma unroll
        for (int p2 = 0; p2 < 8; p2++) acc2[j][p2] = 0ull;

    const float4* eT = (const float4*)embT;
    for (int d4 = 0; d4 < 32; d4++) {
        float4 ev[4];
#pragma unroll
        for (int j = 0; j < 4; j++) ev[j] = eT[d4 * 512 + 128 * j + tid];
        unsigned long long e2[4][4];
#pragma unroll
        for (int j = 0; j < 4; j++) {
            e2[j][0] = pk2(ev[j].x, ev[j].x);
            e2[j][1] = pk2(ev[j].y, ev[j].y);
            e2[j][2] = pk2(ev[j].z, ev[j].z);
            e2[j][3] = pk2(ev[j].w, ev[j].w);
        }
#pragma unroll
        for (int p2 = 0; p2 < 8; p2++) {
            float4 xa = xs4[(2 * p2) * 32 + d4];
            float4 xb = xs4[(2 * p2 + 1) * 32 + d4];
            unsigned long long xp0 = pk2(xa.x, xb.x);
            unsigned long long xp1 = pk2(xa.y, xb.y);
            unsigned long long xp2 = pk2(xa.z, xb.z);
            unsigned long long xp3 = pk2(xa.w, xb.w);
#pragma unroll
            for (int j = 0; j < 4; j++) {
                fma2(acc2[j][p2], xp0, e2[j][0]);
                fma2(acc2[j][p2], xp1, e2[j][1]);
                fma2(acc2[j][p2], xp2, e2[j][2]);
                fma2(acc2[j][p2], xp3, e2[j][3]);
            }
        }
    }
    float accs[4][16];
#pragma unroll
    for (int j = 0; j < 4; j++)
#pragma unroll
        for (int p2 = 0; p2 < 8; p2++) {
            float2 u = up2(acc2[j][p2]);
            accs[j][2 * p2] = u.x;
            accs[j][2 * p2 + 1] = u.y;
        }
    float nd[4];
#pragma unroll
    for (int j = 0; j < 4; j++) nd[j] = norme[tid + 128 * j];
#pragma unroll
    for (int p = 0; p < 16; p++) {
        float bd = 1e30f; int bi = 0;
#pragma unroll
        for (int j = 0; j < 4; j++) {
            float d = nd[j] - 2.f * accs[j][p];
            if (d < bd) { bd = d; bi = tid + 128 * j; }
        }
        rdist[p * 128 + tid] = bd;
        ridx[p * 128 + tid]  = bi;
    }
    __syncthreads();
    if (tid < 16) {
        float bd = 1e30f; int bi = 1 << 30;
        for (int u = 0; u < 128; u++) {
            float d = rdist[tid * 128 + u];
            int   i = ridx[tid * 128 + u];
            if (d < bd || (d == bd && i < bi)) { bd = d; bi = i; }
        }
        best[tid] = bi;
    }
    __syncthreads();
    int kcq = tid >> 5, off = tid & 31;
#pragma unroll
    for (int p = 0; p < 16; p++) {
        float e = emb[best[p] * 128 + tid];
        q[(pixel0 + p) * 128 + tid] = e;
        float hi = rna_tf32(e);
        long base = (pixel0 + p) * 256 + kcq * 64 + off;
        qcvt[base] = hi;
        qcvt[base + 32] = rna_tf32(e - hi);
    }
}

__global__ void dt2_kernel(const float* __restrict__ in, const float* __restrict__ wt,
                           const float* __restrict__ b, float* __restrict__ out) {
    int t = blockIdx.x * 256 + threadIdx.x;
    int ow = t & 255;
    int oh = (t >> 8) & 255;
    int n  = t >> 16;
    float a0 = b[0], a1 = b[1], a2 = b[2];
#pragma unroll
    for (int dh = 0; dh < 2; dh++) {
        int kh = (oh & 1) + 2 * dh;
        int ih2 = oh + kh - 2;
        if (ih2 < 0 || ih2 >= 256) continue;
        int ih = ih2 >> 1;
#pragma unroll
        for (int dw = 0; dw < 2; dw++) {
            int kw = (ow & 1) + 2 * dw;
            int iw2 = ow + kw - 2;
            if (iw2 < 0 || iw2 >= 256) continue;
            int iw = iw2 >> 1;
            const float4* xp = (const float4*)(in + ((n * 128 + ih) * 128 + iw) * 64);
            const float* wb = wt + (kh * 4 + kw) * 3 * 64;
            const float4* w0 = (const float4*)(wb);
            const float4* w1 = (const float4*)(wb + 64);
            const float4* w2 = (const float4*)(wb + 128);
#pragma unroll 4
            for (int ic4 = 0; ic4 < 16; ic4++) {
                float4 x4 = xp[ic4];
                a0 += dot4(x4, w0[ic4]);
                a1 += dot4(x4, w1[ic4]);
                a2 += dot4(x4, w2[ic4]);
            }
        }
    }
    float* op = out + (long)((n * 256 + oh) * 256 + ow) * 3;
    op[0] = a0; op[1] = a1; op[2] = a2;
}

extern "C" void kernel_launch(void* const* d_in, const int* in_sizes, int n_in,
                              void* d_out, int out_size) {
    const float* x       = (const float*)d_in[0];
    const float* emb     = (const float*)d_in[1];
    const float* enc_w1  = (const float*)d_in[2];
    const float* enc_b1  = (const float*)d_in[3];
    const float* enc_w2  = (const float*)d_in[4];
    const float* enc_b2  = (const float*)d_in[5];
    const float* enc_w3  = (const float*)d_in[6];
    const float* enc_b3  = (const float*)d_in[7];
    const float* erb1_w1 = (const float*)d_in[8];
    const float* erb1_w2 = (const float*)d_in[9];
    const float* erb2_w1 = (const float*)d_in[10];
    const float* erb2_w2 = (const float*)d_in[11];
    const float* dec_w   = (const float*)d_in[12];
    const float* dec_b   = (const float*)d_in[13];
    const float* drb1_w1 = (const float*)d_in[14];
    const float* drb1_w2 = (const float*)d_in[15];
    const float* drb2_w1 = (const float*)d_in[16];
    const float* drb2_w2 = (const float*)d_in[17];
    const float* dt1_w   = (const float*)d_in[18];
    const float* dt1_b   = (const float*)d_in[19];
    const float* dt2_w   = (const float*)d_in[20];
    const float* dt2_b   = (const float*)d_in[21];

    float *pA, *pCol, *pCvA, *pCvB, *pB1, *pB2, *pT, *pN, *pE, *pWdt2, *pW1p, *pWT;
    cudaGetSymbolAddress((void**)&pA,    g_A);
    cudaGetSymbolAddress((void**)&pCol,  g_col);
    cudaGetSymbolAddress((void**)&pCvA,  g_cvtA);
    cudaGetSymbolAddress((void**)&pCvB,  g_cvtB);
    cudaGetSymbolAddress((void**)&pB1,   g_B1);
    cudaGetSymbolAddress((void**)&pB2,   g_B2);
    cudaGetSymbolAddress((void**)&pT,    g_T);
    cudaGetSymbolAddress((void**)&pN,    g_norme);
    cudaGetSymbolAddress((void**)&pE,    g_embT);
    cudaGetSymbolAddress((void**)&pWdt2, g_wdt2);
    cudaGetSymbolAddress((void**)&pW1p,  g_w1p);
    cudaGetSymbolAddress((void**)&pWT,   g_wtens);

    float* yout = (float*)d_out;
    float* fout = yout + Y_SZ;
    float* qout = fout + F_SZ;

    const int SM128 = (2 * (16 * 132 * 2) + 2 * (16 * 132 * 2)) * 2 * 4;  // 135168
    const int SM64  = (2 * (16 * 132 * 2) + 2 * (16 * 68  * 2)) * 2 * 4;  // 102400
    const int SM32  = (2 * (16 * 132 * 2) + 2 * (16 * 36  * 2)) * 2 * 4;  // 86016
    cudaFuncSetAttribute(
        conv_mma<0, 4, 4, 2, 1, 128, 64, 128, 3, true, true, false, true, false>,
        cudaFuncAttributeMaxDynamicSharedMemorySize, SM128);
    cudaFuncSetAttribute(
        conv_mma<0, 3, 3, 1, 1, 64, 128, 128, 3, true, false, true, true, true>,
        cudaFuncAttributeMaxDynamicSharedMemorySize, SM128);
    cudaFuncSetAttribute(
        conv_mma<0, 3, 3, 1, 1, 64, 128, 32, 3, false, false, true, false, false>,
        cudaFuncAttributeMaxDynamicSharedMemorySize, SM32);
    cudaFuncSetAttribute(
        conv_mma<1, 4, 4, 1, 0, 64, 128, 64, 3, true, true, true, false, false>,
        cudaFuncAttributeMaxDynamicSharedMemorySize, SM64);

    // prep + enc1
    im2col_enc1<<<65536, 256>>>(x, pCol);
    pad_w1<<<16, 256>>>(enc_w1, pW1p);
    prep_w_tf32<16, 64, 128><<<512, 256>>>(enc_w2, pWT + WP_ENC2);
    flat_gemm_cvt<64, 64, 128, 8, 4, true><<<2048, 256>>>(pCol, pW1p, enc_b1, pCvA);
    prep_w_tf32<9, 128, 128><<<576, 256>>>(enc_w3, pWT + WP_ENC3);
    prep_w_tf32<9, 128, 32><<<144, 256>>>(erb1_w1, pWT + WP_ERB1);
    prep_w_tf32<9, 128, 32><<<144, 256>>>(erb2_w1, pWT + WP_ERB2);
    prep_w_tf32<9, 128, 128><<<576, 256>>>(dec_w, pWT + WP_DEC);
    prep_w_tf32<9, 128, 32><<<144, 256>>>(drb1_w1, pWT + WP_DRB1);
    prep_w_tf32<9, 128, 32><<<144, 256>>>(drb2_w1, pWT + WP_DRB2);
    prep_w_tf32<16, 128, 64><<<512, 256>>>(dt1_w, pWT + WP_DT1);
    transpose_w<<<12, 256>>>(dt2_w, pWdt2, 16, 64, 3);
    norme_kernel<<<2, 256>>>(emb, pN);
    embT_kernel<<<64, 256>>>(emb, pE);

    // Encoder (3-pass tf32)
    conv_mma<0, 4, 4, 2, 1, 128, 64, 128, 3, true, true, false, true, false>
        <<<512, 256, SM128>>>(pCvA, pWT + WP_ENC2, enc_b2, pB1, pCvB);
    conv_mma<0, 3, 3, 1, 1, 64, 128, 128, 3, true, false, true, true, true>
        <<<512, 256, SM128>>>(pCvB, pWT + WP_ENC3, enc_b3, pB2, pCvA);
    conv_mma<0, 3, 3, 1, 1, 64, 128, 32, 3, false, false, true, false, false>
        <<<512, 256, SM32>>>(pCvA, pWT + WP_ERB1, nullptr, pT, nullptr);
    conv1x1_res<false, true, true, true><<<8192, 256>>>(pT, pB2, erb1_w2, pB1, pCvB);
    conv_mma<0, 3, 3, 1, 1, 64, 128, 32, 3, false, false, true, false, false>
        <<<512, 256, SM32>>>(pCvB, pWT + WP_ERB2, nullptr, pT, nullptr);
    conv1x1_res<true, true, false, false><<<8192, 256>>>(pT, pB1, erb2_w2, fout, nullptr);

    // VQ (writes q + cvt(q))
    vq16<<<4096, 128>>>(fout, pE, emb, pN, qout, pCvA);

    // Decoder (3-pass tf32)
    conv_mma<0, 3, 3, 1, 1, 64, 128, 128, 3, true, false, true, true, true>
        <<<512, 256, SM128>>>(pCvA, pWT + WP_DEC, dec_b, pB1, pCvB);
    conv_mma<0, 3, 3, 1, 1, 64, 128, 32, 3, false, false, true, false, false>
        <<<512, 256, SM32>>>(pCvB, pWT + WP_DRB1, nullptr, pT, nullptr);
    conv1x1_res<false, true, true, true><<<8192, 256>>>(pT, pB1, drb1_w2, pB2, pCvA);
    conv_mma<0, 3, 3, 1, 1, 64, 128, 32, 3, false, false, true, false, false>
        <<<512, 256, SM32>>>(pCvA, pWT + WP_DRB2, nullptr, pT, nullptr);
    conv1x1_res<true, false, true, false><<<8192, 256>>>(pT, pB2, drb2_w2, nullptr, pCvB);
    conv_mma<1, 4, 4, 1, 0, 64, 128, 64, 3, true, true, true, false, false>
        <<<dim3(512, 4), 256, SM64>>>(pCvB, pWT + WP_DT1, dt1_b, pA, nullptr);
    dt2_kernel<<<4096, 256>>>(pA, pWdt2, dt2_b, yout);
}

// round 12
// speedup vs baseline: 1.2202x; 1.1314x over previous
#include <cuda_runtime.h>
#include <cuda_bf16.h>
#include <cstdint>

#define Y_SZ  (16*256*256*3)
#define F_SZ  (16*64*64*128)

__device__ __align__(16) float g_A[16*128*128*64];    // enc1 out / dt1 out
__device__ __align__(16) float g_col[16*128*128*64];  // enc1 im2col
__device__ __align__(16) float g_cvtA[16*128*128*64*2];
__device__ __align__(16) float g_cvtB[16*64*64*256];
__device__ __align__(16) float g_B1[16*64*64*128];
__device__ __align__(16) float g_B2[16*64*64*128];
__device__ __align__(16) float g_T[16*64*64*32];
__device__ __align__(16) float g_norme[512];
__device__ __align__(16) float g_embT[512*128];
__device__ __align__(16) float g_wdt2[16*3*64];
__device__ __align__(16) float g_w1p[64*64];
__device__ __align__(16) float g_wtens[700*1024];     // tf32 hi/lo weights (encoder)
__device__ __align__(16) __nv_bfloat16 g_wbf[1100*1024]; // bf16 triple weights (decoder)

#define WP_ENC2 0
#define WP_ENC3 270336
#define WP_ERB1 574464
#define WP_ERB2 657408
// bf16 weight offsets (elements)
#define WB_DEC  0
#define WB_DRB1 442368
#define WB_DRB2 552960
#define WB_DT1  663552

__device__ __forceinline__ float4 relu4(float4 a) {
    a.x = fmaxf(a.x, 0.f); a.y = fmaxf(a.y, 0.f);
    a.z = fmaxf(a.z, 0.f); a.w = fmaxf(a.w, 0.f);
    return a;
}
__device__ __forceinline__ float dot4(float4 a, float4 b) {
    return fmaf(a.x, b.x, fmaf(a.y, b.y, fmaf(a.z, b.z, a.w * b.w)));
}
__device__ __forceinline__ unsigned long long pk2(float x, float y) {
    unsigned long long r;
    asm("mov.b64 %0, {%1, %2};" : "=l"(r)
        : "r"(__float_as_uint(x)), "r"(__float_as_uint(y)));
    return r;
}
__device__ __forceinline__ float2 up2(unsigned long long v) {
    unsigned int lo, hi;
    asm("mov.b64 {%0, %1}, %2;" : "=r"(lo), "=r"(hi) : "l"(v));
    return make_float2(__uint_as_float(lo), __uint_as_float(hi));
}
__device__ __forceinline__ void fma2(unsigned long long& d,
                                     unsigned long long a, unsigned long long b) {
    asm("fma.rn.f32x2 %0, %1, %2, %0;" : "+l"(d) : "l"(a), "l"(b));
}
__device__ __forceinline__ float rna_tf32(float x) {
    uint32_t o;
    asm("cvt.rna.tf32.f32 %0, %1;" : "=r"(o) : "f"(x));
    return __uint_as_float(o);
}
__device__ __forceinline__ void mma8(float* c, const uint32_t* a, float2 b) {
    asm volatile(
        "mma.sync.aligned.m16n8k8.row.col.f32.tf32.tf32.f32 "
        "{%0,%1,%2,%3},{%4,%5,%6,%7},{%8,%9},{%0,%1,%2,%3};"
        : "+f"(c[0]), "+f"(c[1]), "+f"(c[2]), "+f"(c[3])
        : "r"(a[0]), "r"(a[1]), "r"(a[2]), "r"(a[3]),
          "r"(__float_as_uint(b.x)), "r"(__float_as_uint(b.y)));
}
__device__ __forceinline__ void mma16(float* c, const uint32_t* a, const uint32_t* b) {
    asm volatile(
        "mma.sync.aligned.m16n8k16.row.col.f32.bf16.bf16.f32 "
        "{%0,%1,%2,%3},{%4,%5,%6,%7},{%8,%9},{%0,%1,%2,%3};"
        : "+f"(c[0]), "+f"(c[1]), "+f"(c[2]), "+f"(c[3])
        : "r"(a[0]), "r"(a[1]), "r"(a[2]), "r"(a[3]), "r"(b[0]), "r"(b[1]));
}
__device__ __forceinline__ void ldmx4(uint32_t* r, uint32_t addr) {
    asm volatile("ldmatrix.sync.aligned.m8n8.x4.shared.b16 {%0,%1,%2,%3}, [%4];"
        : "=r"(r[0]), "=r"(r[1]), "=r"(r[2]), "=r"(r[3]) : "r"(addr));
}
__device__ __forceinline__ uint32_t smem_u32(const void* p) {
    uint32_t a;
    asm("{ .reg .u64 t; cvta.to.shared.u64 t, %1; cvt.u32.u64 %0, t; }"
        : "=r"(a) : "l"(p));
    return a;
}
__device__ __forceinline__ void cpasync16(uint32_t dst, const void* src) {
    asm volatile("cp.async.cg.shared.global [%0], [%1], 16;" :: "r"(dst), "l"(src));
}
__device__ __forceinline__ void cpasync16z(uint32_t dst, const void* src, int sz) {
    asm volatile("cp.async.cg.shared.global [%0], [%1], 16, %2;"
                 :: "r"(dst), "l"(src), "r"(sz));
}
__device__ __forceinline__ void cpasync_commit() {
    asm volatile("cp.async.commit_group;" ::: "memory");
}
__device__ __forceinline__ void cpasync_wait0() {
    asm volatile("cp.async.wait_group 0;" ::: "memory");
}
// write bf16 triple [hi, lo, hi]
__device__ __forceinline__ void wr3(__nv_bfloat16* dst, float v) {
    __nv_bfloat16 b1 = __float2bfloat16_rn(v);
    float r = v - __bfloat162float(b1);
    dst[0] = b1;
    dst[1] = __float2bfloat16_rn(r);
    dst[2] = b1;
}

// ---- tf32 weight prep (encoder) ----
template<int TAPS, int IC, int OC>
__global__ void prep_w_tf32(const float* __restrict__ w, float* __restrict__ out) {
    constexpr int KC = IC / 32;
    constexpr int BF = 32 * (OC + 4);
    int t = blockIdx.x * 256 + threadIdx.x;
    if (t >= TAPS * IC * OC) return;
    int oc = t % OC;
    int r = t / OC;
    int ic = r % IC;
    int tap = r / IC;
    int kc = ic >> 5, lk = ic & 31;
    int k8 = lk >> 3, t4 = lk & 3, half = (lk >> 2) & 1;
    float v = w[t];
    float hi = rna_tf32(v);
    float lo = rna_tf32(v - hi);
    long base = (long)(tap * KC + kc) * 2 * BF;
    int idx = ((k8 * 4 + t4) * (OC + 4) + oc) * 2 + half;
    out[base + idx] = hi;
    out[base + BF + idx] = lo;
}

// ---- bf16 weight prep (decoder): [tap][kc][oc][96], triple [b1,b1,b2] ----
template<int TAPS, int IC, int OC>
__global__ void prep_w_bf16(const float* __restrict__ w, __nv_bfloat16* __restrict__ out) {
    constexpr int KC = IC / 32;
    int t = blockIdx.x * 256 + threadIdx.x;
    if (t >= TAPS * IC * OC) return;
    int oc = t % OC;
    int r = t / OC;
    int ic = r % IC;
    int tap = r / IC;
    int kc = ic >> 5, lk = ic & 31;
    float v = w[t];
    __nv_bfloat16 b1 = __float2bfloat16_rn(v);
    float rr = v - __bfloat162float(b1);
    __nv_bfloat16 b2 = __float2bfloat16_rn(rr);
    long base = (((long)(tap * KC + kc)) * OC + oc) * 96 + 3 * lk;
    out[base] = b1;
    out[base + 1] = b1;
    out[base + 2] = b2;
}

// ================= tf32 mma conv (ENCODER, unchanged from R9) =================
template<int MODE, int KH, int KW, int STRIDE, int PAD, int IH, int IC, int OC,
         int NPASS, bool HAS_BIAS, bool RELU_OUT, bool WRITE_OUT, bool WRITE_CVT,
         bool CVT_RELU>
__global__ void __launch_bounds__(256, (OC >= 128) ? 1 : 2) conv_mma(
    const float* __restrict__ cv, const float* __restrict__ wp,
    const float* __restrict__ bias, float* __restrict__ out,
    float* __restrict__ cvt_out)
{
    constexpr int KC = IC / 32;
    constexpr int NTAPS = (MODE == 0) ? KH * KW : 4;
    constexpr int SE = (MODE == 0) ? STRIDE : 1;
    constexpr int BMp = 132;
    constexpr int BNp = OC + 4;
    constexpr int AF = 16 * BMp * 2;
    constexpr int BF = 16 * BNp * 2;
    constexpr int SS = 2 * AF + 2 * BF;
    constexpr int NT = OC / 16;
    constexpr int TOTAL = NTAPS * KC;

    extern __shared__ __align__(16) float sm[];

    int tid = threadIdx.x;
    int lane = tid & 31;
    int g = lane >> 2, t4 = lane & 3;
    int wid = tid >> 5;
    int wm = wid >> 1, wn = wid & 1;
    int m0 = blockIdx.x * 128;
    int po = 0, pw_ = 0;
    if (MODE == 1) { po = blockIdx.y >> 1; pw_ = blockIdx.y & 1; }
    int c4 = tid & 7, mp = tid >> 3;
    int k8 = c4 >> 1, h = c4 & 1;

    float acc[2][NT][4];
#pragma unroll
    for (int i = 0; i < 2; i++)
#pragma unroll
        for (int j = 0; j < NT; j++)
#pragma unroll
            for (int u = 0; u < 4; u++) acc[i][j][u] = 0.f;

    auto tapgeom = [&](int it, int& hoff, int& woff, int& wtap, int& kc) {
        int tap = it / KC; kc = it % KC;
        if (MODE == 0) {
            int kh = tap / KW, kw = tap % KW;
            hoff = kh - PAD; woff = kw - PAD; wtap = tap;
        } else {
            int dh = tap >> 1, dw = tap & 1;
            hoff = po + dh - 1; woff = pw_ + dw - 1;
            wtap = (po + 2 * dh) * 4 + (pw_ + 2 * dw);
        }
    };
    auto fillregs = [&](int it, float4* rh, float4* rl) {
        int hoff, woff, wtap, kc;
        tapgeom(it, hoff, woff, wtap, kc);
#pragma unroll
        for (int pass = 0; pass < 4; pass++) {
            int m = mp + 32 * pass;
            int p = m0 + m;
            int n_img = p >> 12, oh = (p >> 6) & 63, ow = p & 63;
            int ih = oh * SE + hoff, iw = ow * SE + woff;
            rh[pass] = make_float4(0.f, 0.f, 0.f, 0.f);
            rl[pass] = make_float4(0.f, 0.f, 0.f, 0.f);
            if ((unsigned)ih < (unsigned)IH && (unsigned)iw < (unsigned)IH) {
                long P = ((long)n_img * IH + ih) * IH + iw;
                const float* b = cv + P * 2 * IC + kc * 64 + 4 * c4;
                rh[pass] = *(const float4*)(b);
                rl[pass] = *(const float4*)(b + 32);
            }
        }
    };
    auto stsregs = [&](int s, const float4* rh, const float4* rl) {
        float* Ah = sm + s * SS;
        float* Al = Ah + AF;
#pragma unroll
        for (int pass = 0; pass < 4; pass++) {
            int m = mp + 32 * pass;
            int rot = ((m + 4 * k8) & 127) * 2 + h;
            int r0 = (k8 * 4 + 0) * (2 * BMp) + rot;
            int r1 = (k8 * 4 + 1) * (2 * BMp) + rot;
            int r2 = (k8 * 4 + 2) * (2 * BMp) + rot;
            int r3 = (k8 * 4 + 3) * (2 * BMp) + rot;
            Ah[r0] = rh[pass].x; Ah[r1] = rh[pass].y;
            Ah[r2] = rh[pass].z; Ah[r3] = rh[pass].w;
            Al[r0] = rl[pass].x; Al[r1] = rl[pass].y;
            Al[r2] = rl[pass].z; Al[r3] = rl[pass].w;
        }
    };
    auto copyB = [&](int it, int s) {
        int hoff, woff, wtap, kc;
        tapgeom(it, hoff, woff, wtap, kc);
        const float* src = wp + (long)(wtap * KC + kc) * 2 * BF;
        uint32_t dst = smem_u32(sm + s * SS + 2 * AF);
        constexpr int NF4 = 2 * BF / 4;
#pragma unroll
        for (int i = 0; i < (NF4 + 255) / 256; i++) {
            int idx = tid + i * 256;
            if (idx < NF4) cpasync16(dst + idx * 16, src + idx * 4);
        }
        cpasync_commit();
    };
    auto do_mma = [&](int s) {
        const float* Ah = sm + s * SS;
        const float* Al = Ah + AF;
        const float* Bh = Ah + 2 * AF;
        const float* Bl = Bh + BF;
#pragma unroll
        for (int kk = 0; kk < 4; kk++) {
            uint32_t ah[2][4], al[2][4];
            const float2* arh = (const float2*)Ah + (kk * 4 + t4) * BMp;
            const float2* arl = (const float2*)Al + (kk * 4 + t4) * BMp;
#pragma unroll
            for (int mt = 0; mt < 2; mt++) {
                int c0 = (wm * 32 + mt * 16 + g + 4 * kk) & 127;
                int c1 = (wm * 32 + mt * 16 + g + 8 + 4 * kk) & 127;
                float2 q0 = arh[c0], q1 = arh[c1];
                ah[mt][0] = __float_as_uint(q0.x);
                ah[mt][1] = __float_as_uint(q1.x);
                ah[mt][2] = __float_as_uint(q0.y);
                ah[mt][3] = __float_as_uint(q1.y);
                float2 s0 = arl[c0], s1 = arl[c1];
                al[mt][0] = __float_as_uint(s0.x);
                al[mt][1] = __float_as_uint(s1.x);
                al[mt][2] = __float_as_uint(s0.y);
                al[mt][3] = __float_as_uint(s1.y);
            }
            float2 bh[NT], bl[NT];
            const float2* brh = (const float2*)Bh + (kk * 4 + t4) * BNp + wn * (OC / 2) + g;
            const float2* brl = (const float2*)Bl + (kk * 4 + t4) * BNp + wn * (OC / 2) + g;
#pragma unroll
            for (int nt = 0; nt < NT; nt++) { bh[nt] = brh[nt * 8]; bl[nt] = brl[nt * 8]; }
#pragma unroll
            for (int nt = 0; nt < NT; nt++)
#pragma unroll
                for (int mt = 0; mt < 2; mt++) mma8(acc[mt][nt], ah[mt], bh[nt]);
#pragma unroll
            for (int nt = 0; nt < NT; nt++)
#pragma unroll
                for (int mt = 0; mt < 2; mt++) mma8(acc[mt][nt], al[mt], bh[nt]);
#pragma unroll
            for (int nt = 0; nt < NT; nt++)
#pragma unroll
                for (int mt = 0; mt < 2; mt++) mma8(acc[mt][nt], ah[mt], bl[nt]);
            if (NPASS == 4) {
#pragma unroll
                for (int nt = 0; nt < NT; nt++)
#pragma unroll
                    for (int mt = 0; mt < 2; mt++) mma8(acc[mt][nt], al[mt], bl[nt]);
            }
        }
    };

    {
        float4 rh[4], rl[4];
        fillregs(0, rh, rl);
        stsregs(0, rh, rl);
        copyB(0, 0);
        cpasync_wait0();
        __syncthreads();
    }
    for (int it = 0; it < TOTAL; it++) {
        int cur = it & 1, nxt = cur ^ 1;
        float4 rh[4], rl[4];
        bool have = (it + 1 < TOTAL);
        if (have) {
            fillregs(it + 1, rh, rl);
            copyB(it + 1, nxt);
        }
        do_mma(cur);
        if (have) stsregs(nxt, rh, rl);
        cpasync_wait0();
        __syncthreads();
    }

#pragma unroll
    for (int mt = 0; mt < 2; mt++) {
        int r0 = m0 + wm * 32 + mt * 16 + g;
        int r1 = r0 + 8;
        long o0 = (long)r0 * OC;
        long o1 = (long)r1 * OC;
#pragma unroll
        for (int nt = 0; nt < NT; nt++) {
            int nb = wn * (OC / 2) + nt * 8 + 2 * t4;
            float b0v = HAS_BIAS ? bias[nb] : 0.f;
            float b1v = HAS_BIAS ? bias[nb + 1] : 0.f;
            float2 v0 = make_float2(acc[mt][nt][0] + b0v, acc[mt][nt][1] + b1v);
            float2 v1 = make_float2(acc[mt][nt][2] + b0v, acc[mt][nt][3] + b1v);
            if (RELU_OUT) {
                v0.x = fmaxf(v0.x, 0.f); v0.y = fmaxf(v0.y, 0.f);
                v1.x = fmaxf(v1.x, 0.f); v1.y = fmaxf(v1.y, 0.f);
            }
            if (WRITE_OUT) {
                *(float2*)(out + o0 + nb) = v0;
                *(float2*)(out + o1 + nb) = v1;
            }
            if (WRITE_CVT) {
                float c0x = CVT_RELU ? fmaxf(v0.x, 0.f) : v0.x;
                float c0y = CVT_RELU ? fmaxf(v0.y, 0.f) : v0.y;
                float c1x = CVT_RELU ? fmaxf(v1.x, 0.f) : v1.x;
                float c1y = CVT_RELU ? fmaxf(v1.y, 0.f) : v1.y;
                float h0x = rna_tf32(c0x), h0y = rna_tf32(c0y);
                float h1x = rna_tf32(c1x), h1y = rna_tf32(c1y);
                long cb0 = (long)r0 * 2 * OC + ((nb >> 5) << 6) + (nb & 31);
                long cb1 = (long)r1 * 2 * OC + ((nb >> 5) << 6) + (nb & 31);
                *(float2*)(cvt_out + cb0) = make_float2(h0x, h0y);
                *(float2*)(cvt_out + cb0 + 32) =
                    make_float2(rna_tf32(c0x - h0x), rna_tf32(c0y - h0y));
                *(float2*)(cvt_out + cb1) = make_float2(h1x, h1y);
                *(float2*)(cvt_out + cb1 + 32) =
                    make_float2(rna_tf32(c1x - h1x), rna_tf32(c1y - h1y));
            }
        }
    }
}

// ================= bf16 triple-channel mma conv (DECODER) =================
// cv3: [p][KC][96 bf16] activations (triple [hi,lo,hi]); wp3: [tap][kc][oc][96] ([b1,b1,b2]).
template<int MODE, int KH, int KW, int IH, int IC, int OC,
         bool HAS_BIAS, bool RELU_OUT, bool WRITE_OUT, bool WRITE_CVT3, bool CVT_RELU>
__global__ void __launch_bounds__(256, 2) conv_bf16(
    const __nv_bfloat16* __restrict__ cv3, const __nv_bfloat16* __restrict__ wp3,
    const float* __restrict__ bias, float* __restrict__ out,
    __nv_bfloat16* __restrict__ cvt_out)
{
    constexpr int KC = IC / 32;
    constexpr int NTAPS = (MODE == 0) ? KH * KW : 4;
    constexpr int AU = 128 * 13;             // A 16B-units (208B rows)
    constexpr int BU = OC * 13;
    constexpr int SU = AU + BU;              // stage units
    constexpr int NT = OC / 16;
    constexpr int TOTAL = NTAPS * KC;

    extern __shared__ __align__(16) char smb[];
    uint32_t sbase = smem_u32(smb);

    int tid = threadIdx.x;
    int lane = tid & 31;
    int g = lane >> 2, t4 = lane & 3;
    int wid = tid >> 5;
    int wm = wid >> 1, wn = wid & 1;
    int m0 = blockIdx.x * 128;
    int po = 0, pw_ = 0;
    if (MODE == 1) { po = blockIdx.y >> 1; pw_ = blockIdx.y & 1; }

    float acc[2][NT][4];
#pragma unroll
    for (int i = 0; i < 2; i++)
#pragma unroll
        for (int j = 0; j < NT; j++)
#pragma unroll
            for (int u = 0; u < 4; u++) acc[i][j][u] = 0.f;

    auto tapgeom = [&](int it, int& hoff, int& woff, int& wtap, int& kc) {
        int tap = it / KC; kc = it % KC;
        if (MODE == 0) {
            int kh = tap / KW, kw = tap % KW;
            hoff = kh - 1; woff = kw - 1; wtap = tap;
        } else {
            int dh = tap >> 1, dw = tap & 1;
            hoff = po + dh - 1; woff = pw_ + dw - 1;
            wtap = (po + 2 * dh) * 4 + (pw_ + 2 * dw);
        }
    };
    auto copyA = [&](int it, int s) {
        int hoff, woff, wtap, kc;
        tapgeom(it, hoff, woff, wtap, kc);
        uint32_t dst0 = sbase + s * SU * 16;
#pragma unroll
        for (int i = 0; i < 6; i++) {
            int idx = tid + i * 256;
            int m = idx / 12, c = idx % 12;
            int p = m0 + m;
            int n_img = p >> 12, oh = (p >> 6) & 63, ow = p & 63;
            int ih = oh + hoff, iw = ow + woff;
            bool valid = (unsigned)ih < (unsigned)IH && (unsigned)iw < (unsigned)IH;
            long P = valid ? (((long)n_img * IH + ih) * IH + iw) : 0;
            const char* src = (const char*)cv3 + (P * KC + kc) * 192 + c * 16;
            cpasync16z(dst0 + (m * 13 + c) * 16, src, valid ? 16 : 0);
        }
    };
    auto copyB = [&](int it, int s) {
        int hoff, woff, wtap, kc;
        tapgeom(it, hoff, woff, wtap, kc);
        const char* src0 = (const char*)(wp3 + ((long)(wtap * KC + kc) * OC) * 96);
        uint32_t dst0 = sbase + s * SU * 16 + AU * 16;
        constexpr int NCH = OC * 12;
#pragma unroll
        for (int i = 0; i < (NCH + 255) / 256; i++) {
            int idx = tid + i * 256;
            if (idx < NCH) {
                int row = idx / 12, c = idx % 12;
                cpasync16(dst0 + (row * 13 + c) * 16, src0 + idx * 16);
            }
        }
    };
    int l7 = lane & 7, q = lane >> 3;
    uint32_t arow = ((q & 1) ? 8 : 0) + l7;
    uint32_t acol = (q >> 1) * 16;
    uint32_t brow = ((q >> 1) ? 8 : 0) + l7;
    uint32_t bcol = (q & 1) * 16;
    auto do_mma = [&](int s) {
        uint32_t Ab = sbase + s * SU * 16;
        uint32_t Bb = Ab + AU * 16;
#pragma unroll
        for (int ks = 0; ks < 6; ks++) {
            uint32_t a[2][4];
#pragma unroll
            for (int mt = 0; mt < 2; mt++)
                ldmx4(a[mt], Ab + (wm * 32 + mt * 16 + arow) * 208 + ks * 32 + acol);
            uint32_t b[NT][2];
#pragma unroll
            for (int np = 0; np < NT / 2; np++) {
                uint32_t n0 = wn * (OC / 2) + np * 16;
                uint32_t r[4];
                ldmx4(r, Bb + (n0 + brow) * 208 + ks * 32 + bcol);
                b[2 * np][0] = r[0]; b[2 * np][1] = r[1];
                b[2 * np + 1][0] = r[2]; b[2 * np + 1][1] = r[3];
            }
#pragma unroll
            for (int nt = 0; nt < NT; nt++)
#pragma unroll
                for (int mt = 0; mt < 2; mt++) mma16(acc[mt][nt], a[mt], b[nt]);
        }
    };

    copyA(0, 0); copyB(0, 0); cpasync_commit();
    cpasync_wait0();
    __syncthreads();
    for (int it = 0; it < TOTAL; it++) {
        int cur = it & 1, nxt = cur ^ 1;
        if (it + 1 < TOTAL) {
            copyA(it + 1, nxt);
            copyB(it + 1, nxt);
            cpasync_commit();
        }
        do_mma(cur);
        cpasync_wait0();
        __syncthreads();
    }

    // ---- epilogue
#pragma unroll
    for (int mt = 0; mt < 2; mt++) {
        int r0 = m0 + wm * 32 + mt * 16 + g;
        int r1 = r0 + 8;
        long o0, o1;
        if (MODE == 0) {
            o0 = (long)r0 * OC;
            o1 = (long)r1 * OC;
        } else {
            int n0 = r0 >> 12, a0 = (r0 >> 6) & 63, b0 = r0 & 63;
            int n1 = r1 >> 12, a1 = (r1 >> 6) & 63, b1 = r1 & 63;
            o0 = (((long)n0 * 128 + 2 * a0 + po) * 128 + 2 * b0 + pw_) * OC;
            o1 = (((long)n1 * 128 + 2 * a1 + po) * 128 + 2 * b1 + pw_) * OC;
        }
#pragma unroll
        for (int nt = 0; nt < NT; nt++) {
            int nb = wn * (OC / 2) + nt * 8 + 2 * t4;
            float b0v = HAS_BIAS ? bias[nb] : 0.f;
            float b1v = HAS_BIAS ? bias[nb + 1] : 0.f;
            float2 v0 = make_float2(acc[mt][nt][0] + b0v, acc[mt][nt][1] + b1v);
            float2 v1 = make_float2(acc[mt][nt][2] + b0v, acc[mt][nt][3] + b1v);
            if (RELU_OUT) {
                v0.x = fmaxf(v0.x, 0.f); v0.y = fmaxf(v0.y, 0.f);
                v1.x = fmaxf(v1.x, 0.f); v1.y = fmaxf(v1.y, 0.f);
            }
            if (WRITE_OUT) {
                *(float2*)(out + o0 + nb) = v0;
                *(float2*)(out + o1 + nb) = v1;
            }
            if (WRITE_CVT3) {
                constexpr int KC2 = OC / 32;
                float c0x = CVT_RELU ? fmaxf(v0.x, 0.f) : v0.x;
                float c0y = CVT_RELU ? fmaxf(v0.y, 0.f) : v0.y;
                float c1x = CVT_RELU ? fmaxf(v1.x, 0.f) : v1.x;
                float c1y = CVT_RELU ? fmaxf(v1.y, 0.f) : v1.y;
                long cb0 = ((long)r0 * KC2 + (nb >> 5)) * 96 + 3 * (nb & 31);
                long cb1 = ((long)r1 * KC2 + (nb >> 5)) * 96 + 3 * (nb & 31);
                wr3(cvt_out + cb0, c0x);
                wr3(cvt_out + cb0 + 3, c0y);
                wr3(cvt_out + cb1, c1x);
                wr3(cvt_out + cb1 + 3, c1y);
            }
        }
    }
}

// ---------------- small kernels ----------------
__global__ void transpose_w(const float* __restrict__ in, float* __restrict__ out,
                            int K, int IC, int OC) {
    int i = blockIdx.x * blockDim.x + threadIdx.x;
    int total = K * IC * OC;
    if (i >= total) return;
    int oc = i % OC;
    int ic = (i / OC) % IC;
    int k  = i / (OC * IC);
    out[(k * OC + oc) * IC + ic] = in[i];
}

__global__ void norme_kernel(const float* __restrict__ emb, float* __restrict__ norme) {
    int k = blockIdx.x * blockDim.x + threadIdx.x;
    if (k >= 512) return;
    const float4* e = (const float4*)(emb + k * 128);
    float s = 0.f;
#pragma unroll 8
    for (int i = 0; i < 32; i++) {
        float4 v = e[i];
        s = fmaf(v.x, v.x, s); s = fmaf(v.y, v.y, s);
        s = fmaf(v.z, v.z, s); s = fmaf(v.w, v.w, s);
    }
    norme[k] = s;
}

__global__ void embT_kernel(const float* __restrict__ emb, float* __restrict__ embT) {
    int i = blockIdx.x * 256 + threadIdx.x;
    if (i >= 512 * 32) return;
    int c = i & 511, d4 = i >> 9;
    float4 v = *(const float4*)(emb + c * 128 + 4 * d4);
    *(float4*)(embT + (d4 * 512 + c) * 4) = v;
}

__global__ void pad_w1(const float* __restrict__ w, float* __restrict__ out) {
    int t = blockIdx.x * 256 + threadIdx.x;
    if (t >= 64 * 64) return;
    int r = t >> 6;
    out[t] = (r < 48) ? w[t] : 0.f;
}

__global__ void im2col_enc1(const float* __restrict__ x, float* __restrict__ col) {
    int t = blockIdx.x * 256 + threadIdx.x;
    int kidx = t & 63;
    int p = t >> 6;
    int ow = p & 127, oh = (p >> 7) & 127, n = p >> 14;
    float v = 0.f;
    if (kidx < 48) {
        int ic = kidx % 3;
        int kw = (kidx / 3) & 3;
        int kh = kidx / 12;
        int ih = 2 * oh - 1 + kh, iw = 2 * ow - 1 + kw;
        if ((unsigned)ih < 256u && (unsigned)iw < 256u)
            v = x[((n * 256 + ih) * 256 + iw) * 3 + ic];
    }
    col[t] = v;
}

template<int IC, int OC, int BM, int TM, int TN, bool HAS_BIAS>
__global__ void __launch_bounds__(256, 2) flat_gemm_cvt(
    const float* __restrict__ in, const float* __restrict__ w,
    const float* __restrict__ bias, float* __restrict__ cvt)
{
    constexpr int BK = 32;
    constexpr int BN = OC;
    constexpr int TX = BN / TN;
    constexpr int ASTR = BM + 2;
    __shared__ __align__(16) float As[BK * ASTR];
    __shared__ __align__(16) float Bs[BK * BN];
    int tid = threadIdx.x;
    int m0 = blockIdx.x * BM;
    int tx = tid % TX, ty = tid / TX;
    int c4 = tid & 7;
    int mp = tid >> 3;
    unsigned long long acc2[TM / 2][TN];
#pragma unroll
    for (int i = 0; i < TM / 2; i++)
#pragma unroll
        for (int j = 0; j < TN; j++) acc2[i][j] = 0ull;

    for (int kc = 0; kc < IC / BK; kc++) {
        __syncthreads();
#pragma unroll
        for (int pass = 0; pass < BM / 32; pass++) {
            int m = mp + pass * 32;
            int p = m0 + m;
            float4 v = *(const float4*)(in + (long)p * IC + kc * BK + 4 * c4);
            int kk = 4 * c4;
            As[(kk + 0) * ASTR + m] = v.x;
            As[(kk + 1) * ASTR + m] = v.y;
            As[(kk + 2) * ASTR + m] = v.z;
            As[(kk + 3) * ASTR + m] = v.w;
        }
        {
            const float* wb = w + kc * BK * OC;
#pragma unroll
            for (int i = 0; i < (BK * BN / 4) / 256; i++) {
                int idx = tid + i * 256;
                int kr = idx / (BN / 4);
                int n4 = idx % (BN / 4);
                *(float4*)(Bs + kr * BN + 4 * n4) = *(const float4*)(wb + kr * OC + 4 * n4);
            }
        }
        __syncthreads();
#pragma unroll 8
        for (int k = 0; k < BK; k++) {
            unsigned long long a2[TM / 2], b2[TN];
            const double* ap = (const double*)(As + k * ASTR + ty * TM);
#pragma unroll
            for (int i = 0; i < TM / 2; i++) a2[i] = __double_as_longlong(ap[i]);
            float b[TN];
#pragma unroll
            for (int j = 0; j < TN / 4; j++)
                *(float4*)(b + 4 * j) = *(const float4*)(Bs + k * BN + tx * TN + 4 * j);
#pragma unroll
            for (int j = 0; j < TN; j++) b2[j] = pk2(b[j], b[j]);
#pragma unroll
            for (int i = 0; i < TM / 2; i++)
#pragma unroll
                for (int j = 0; j < TN; j++) fma2(acc2[i][j], a2[i], b2[j]);
        }
    }
    float bv[TN];
#pragma unroll
    for (int j = 0; j < TN; j++) bv[j] = HAS_BIAS ? bias[tx * TN + j] : 0.f;
    int base_m = m0 + ty * TM;
    int col0 = tx * TN;
    int kcq = col0 >> 5, off = col0 & 31;
#pragma unroll
    for (int i2 = 0; i2 < TM / 2; i2++) {
        float2 tv[TN];
#pragma unroll
        for (int j = 0; j < TN; j++) tv[j] = up2(acc2[i2][j]);
#pragma unroll
        for (int hh = 0; hh < 2; hh++) {
            int p = base_m + 2 * i2 + hh;
            float4 v;
            v.x = fmaxf((hh ? tv[0].y : tv[0].x) + bv[0], 0.f);
            v.y = fmaxf((hh ? tv[1].y : tv[1].x) + bv[1], 0.f);
            v.z = fmaxf((hh ? tv[2].y : tv[2].x) + bv[2], 0.f);
            v.w = fmaxf((hh ? tv[3].y : tv[3].x) + bv[3], 0.f);
            float4 hi = make_float4(rna_tf32(v.x), rna_tf32(v.y),
                                    rna_tf32(v.z), rna_tf32(v.w));
            float4 lo = make_float4(rna_tf32(v.x - hi.x), rna_tf32(v.y - hi.y),
                                    rna_tf32(v.z - hi.z), rna_tf32(v.w - hi.w));
            long base = (long)p * 2 * OC + kcq * 64 + off;
            *(float4*)(cvt + base) = hi;
            *(float4*)(cvt + base + 32) = lo;
        }
    }
}

// 1x1 conv (relu in) + residual; CVTM: 0 none, 1 tf32 hi/lo, 2 bf16 triple
template<bool RELU_OUT, bool WRITE_OUT, int CVTM, bool CVT_RELU>
__global__ void conv1x1_res(const float* __restrict__ tin, const float* __restrict__ res,
                            const float* __restrict__ w, float* __restrict__ out,
                            float* __restrict__ cvt, __nv_bfloat16* __restrict__ cvt3) {
    int t = blockIdx.x * 256 + threadIdx.x;
    int oc = t & 127;
    long p0 = (long)(t >> 7) * 4;
    float wv[32];
#pragma unroll
    for (int ic = 0; ic < 32; ic++) wv[ic] = w[ic * 128 + oc];
    float accp[4] = {0.f, 0.f, 0.f, 0.f};
#pragma unroll
    for (int ic4 = 0; ic4 < 8; ic4++) {
#pragma unroll
        for (int p = 0; p < 4; p++) {
            float4 tv = *(const float4*)(tin + (p0 + p) * 32 + 4 * ic4);
            tv = relu4(tv);
            accp[p] = fmaf(tv.x, wv[4 * ic4],     accp[p]);
            accp[p] = fmaf(tv.y, wv[4 * ic4 + 1], accp[p]);
            accp[p] = fmaf(tv.z, wv[4 * ic4 + 2], accp[p]);
            accp[p] = fmaf(tv.w, wv[4 * ic4 + 3], accp[p]);
        }
    }
    long o = p0 * 128 + oc;
    int kcq = oc >> 5, off = oc & 31;
#pragma unroll
    for (int p = 0; p < 4; p++) {
        float v = res[o + p * 128] + accp[p];
        if (RELU_OUT) v = fmaxf(v, 0.f);
        if (WRITE_OUT) out[o + p * 128] = v;
        if (CVTM == 1) {
            float cvv = CVT_RELU ? fmaxf(v, 0.f) : v;
            float hi = rna_tf32(cvv);
            long base = (p0 + p) * 256 + kcq * 64 + off;
            cvt[base] = hi;
            cvt[base + 32] = rna_tf32(cvv - hi);
        }
        if (CVTM == 2) {
            float cvv = CVT_RELU ? fmaxf(v, 0.f) : v;
            long base = ((p0 + p) * 4 + kcq) * 96 + 3 * off;
            wr3(cvt3 + base, cvv);
        }
    }
}

// VQ: writes q (fp32) + bf16 triple cvt for the decoder conv
__global__ void __launch_bounds__(128) vq16(const float* __restrict__ f,
                                            const float* __restrict__ embT,
                                            const float* __restrict__ emb,
                                            const float* __restrict__ norme,
                                            float* __restrict__ q,
                                            __nv_bfloat16* __restrict__ qcvt3) {
    __shared__ float4 xs4[16 * 32];
    __shared__ float rdist[16 * 128];
    __shared__ int   ridx[16 * 128];
    __shared__ int   best[16];
    int tid = threadIdx.x;
    long pixel0 = (long)blockIdx.x * 16;
    const float4* fin = (const float4*)(f + pixel0 * 128);
#pragma unroll
    for (int i = 0; i < 4; i++) xs4[tid + 128 * i] = fin[tid + 128 * i];
    __syncthreads();

    unsigned long long acc2[4][8];
#pragma unroll
    for (int j = 0; j < 4; j++)
#pragma unroll
        for (int p2 = 0; p2 < 8; p2++) acc2[j][p2] = 0ull;

    const float4* eT = (const float4*)embT;
    for (int d4 = 0; d4 < 32; d4++) {
        float4 ev[4];
#pragma unroll
        for (int j = 0; j < 4; j++) ev[j] = eT[d4 * 512 + 128 * j + tid];
        unsigned long long e2[4][4];
#pragma unroll
        for (int j = 0; j < 4; j++) {
            e2[j][0] = pk2(ev[j].x, ev[j].x);
            e2[j][1] = pk2(ev[j].y, ev[j].y);
            e2[j][2] = pk2(ev[j].z, ev[j].z);
            e2[j][3] = pk2(ev[j].w, ev[j].w);
        }
#pragma unroll
        for (int p2 = 0; p2 < 8; p2++) {
            float4 xa = xs4[(2 * p2) * 32 + d4];
            float4 xb = xs4[(2 * p2 + 1) * 32 + d4];
            unsigned long long xp0 = pk2(xa.x, xb.x);
            unsigned long long xp1 = pk2(xa.y, xb.y);
            unsigned long long xp2 = pk2(xa.z, xb.z);
            unsigned long long xp3 = pk2(xa.w, xb.w);
#pragma unroll
            for (int j = 0; j < 4; j++) {
                fma2(acc2[j][p2], xp0, e2[j][0]);
                fma2(acc2[j][p2], xp1, e2[j][1]);
                fma2(acc2[j][p2], xp2, e2[j][2]);
                fma2(acc2[j][p2], xp3, e2[j][3]);
            }
        }
    }
    float accs[4][16];
#pragma unroll
    for (int j = 0; j < 4; j++)
#pragma unroll
        for (int p2 = 0; p2 < 8; p2++) {
            float2 u = up2(acc2[j][p2]);
            accs[j][2 * p2] = u.x;
            accs[j][2 * p2 + 1] = u.y;
        }
    float nd[4];
#pragma unroll
    for (int j = 0; j < 4; j++) nd[j] = norme[tid + 128 * j];
#pragma unroll
    for (int p = 0; p < 16; p++) {
        float bd = 1e30f; int bi = 0;
#pragma unroll
        for (int j = 0; j < 4; j++) {
            float d = nd[j] - 2.f * accs[j][p];
            if (d < bd) { bd = d; bi = tid + 128 * j; }
        }
        rdist[p * 128 + tid] = bd;
        ridx[p * 128 + tid]  = bi;
    }
    __syncthreads();
    if (tid < 16) {
        float bd = 1e30f; int bi = 1 << 30;
        for (int u = 0; u < 128; u++) {
            float d = rdist[tid * 128 + u];
            int   i = ridx[tid * 128 + u];
            if (d < bd || (d == bd && i < bi)) { bd = d; bi = i; }
        }
        best[tid] = bi;
    }
    __syncthreads();
    int kcq = tid >> 5, off = tid & 31;
#pragma unroll
    for (int p = 0; p < 16; p++) {
        float e = emb[best[p] * 128 + tid];
        q[(pixel0 + p) * 128 + tid] = e;
        long base = ((pixel0 + p) * 4 + kcq) * 96 + 3 * off;
        wr3(qcvt3 + base, e);
    }
}

__global__ void dt2_kernel(const float* __restrict__ in, const float* __restrict__ wt,
                           const float* __restrict__ b, float* __restrict__ out) {
    int t = blockIdx.x * 256 + threadIdx.x;
    int ow = t & 255;
    int oh = (t >> 8) & 255;
    int n  = t >> 16;
    float a0 = b[0], a1 = b[1], a2 = b[2];
#pragma unroll
    for (int dh = 0; dh < 2; dh++) {
        int kh = (oh & 1) + 2 * dh;
        int ih2 = oh + kh - 2;
        if (ih2 < 0 || ih2 >= 256) continue;
        int ih = ih2 >> 1;
#pragma unroll
        for (int dw = 0; dw < 2; dw++) {
            int kw = (ow & 1) + 2 * dw;
            int iw2 = ow + kw - 2;
            if (iw2 < 0 || iw2 >= 256) continue;
            int iw = iw2 >> 1;
            const float4* xp = (const float4*)(in + ((n * 128 + ih) * 128 + iw) * 64);
            const float* wb = wt + (kh * 4 + kw) * 3 * 64;
            const float4* w0 = (const float4*)(wb);
            const float4* w1 = (const float4*)(wb + 64);
            const float4* w2 = (const float4*)(wb + 128);
#pragma unroll 4
            for (int ic4 = 0; ic4 < 16; ic4++) {
                float4 x4 = xp[ic4];
                a0 += dot4(x4, w0[ic4]);
                a1 += dot4(x4, w1[ic4]);
                a2 += dot4(x4, w2[ic4]);
            }
        }
    }
    float* op = out + (long)((n * 256 + oh) * 256 + ow) * 3;
    op[0] = a0; op[1] = a1; op[2] = a2;
}

extern "C" void kernel_launch(void* const* d_in, const int* in_sizes, int n_in,
                              void* d_out, int out_size) {
    const float* x       = (const float*)d_in[0];
    const float* emb     = (const float*)d_in[1];
    const float* enc_w1  = (const float*)d_in[2];
    const float* enc_b1  = (const float*)d_in[3];
    const float* enc_w2  = (const float*)d_in[4];
    const float* enc_b2  = (const float*)d_in[5];
    const float* enc_w3  = (const float*)d_in[6];
    const float* enc_b3  = (const float*)d_in[7];
    const float* erb1_w1 = (const float*)d_in[8];
    const float* erb1_w2 = (const float*)d_in[9];
    const float* erb2_w1 = (const float*)d_in[10];
    const float* erb2_w2 = (const float*)d_in[11];
    const float* dec_w   = (const float*)d_in[12];
    const float* dec_b   = (const float*)d_in[13];
    const float* drb1_w1 = (const float*)d_in[14];
    const float* drb1_w2 = (const float*)d_in[15];
    const float* drb2_w1 = (const float*)d_in[16];
    const float* drb2_w2 = (const float*)d_in[17];
    const float* dt1_w   = (const float*)d_in[18];
    const float* dt1_b   = (const float*)d_in[19];
    const float* dt2_w   = (const float*)d_in[20];
    const float* dt2_b   = (const float*)d_in[21];

    float *pA, *pCol, *pCvA, *pCvB, *pB1, *pB2, *pT, *pN, *pE, *pWdt2, *pW1p, *pWT;
    __nv_bfloat16* pWB;
    cudaGetSymbolAddress((void**)&pA,    g_A);
    cudaGetSymbolAddress((void**)&pCol,  g_col);
    cudaGetSymbolAddress((void**)&pCvA,  g_cvtA);
    cudaGetSymbolAddress((void**)&pCvB,  g_cvtB);
    cudaGetSymbolAddress((void**)&pB1,   g_B1);
    cudaGetSymbolAddress((void**)&pB2,   g_B2);
    cudaGetSymbolAddress((void**)&pT,    g_T);
    cudaGetSymbolAddress((void**)&pN,    g_norme);
    cudaGetSymbolAddress((void**)&pE,    g_embT);
    cudaGetSymbolAddress((void**)&pWdt2, g_wdt2);
    cudaGetSymbolAddress((void**)&pW1p,  g_w1p);
    cudaGetSymbolAddress((void**)&pWT,   g_wtens);
    cudaGetSymbolAddress((void**)&pWB,   g_wbf);

    float* yout = (float*)d_out;
    float* fout = yout + Y_SZ;
    float* qout = fout + F_SZ;
    __nv_bfloat16* cv3A = (__nv_bfloat16*)pCvA;
    __nv_bfloat16* cv3B = (__nv_bfloat16*)pCvB;

    const int SM128 = (2 * (16 * 132 * 2) + 2 * (16 * 132 * 2)) * 2 * 4;  // 135168
    const int SM32  = (2 * (16 * 132 * 2) + 2 * (16 * 36  * 2)) * 2 * 4;  // 86016
    const int SB128 = (128 + 128) * 13 * 16 * 2;  // 106496
    const int SB64  = (128 + 64)  * 13 * 16 * 2;  // 79872
    const int SB32  = (128 + 32)  * 13 * 16 * 2;  // 66560
    cudaFuncSetAttribute(
        conv_mma<0, 4, 4, 2, 1, 128, 64, 128, 3, true, true, false, true, false>,
        cudaFuncAttributeMaxDynamicSharedMemorySize, SM128);
    cudaFuncSetAttribute(
        conv_mma<0, 3, 3, 1, 1, 64, 128, 128, 3, true, false, true, true, true>,
        cudaFuncAttributeMaxDynamicSharedMemorySize, SM128);
    cudaFuncSetAttribute(
        conv_mma<0, 3, 3, 1, 1, 64, 128, 32, 3, false, false, true, false, false>,
        cudaFuncAttributeMaxDynamicSharedMemorySize, SM32);
    cudaFuncSetAttribute(
        conv_bf16<0, 3, 3, 64, 128, 128, true, false, true, true, true>,
        cudaFuncAttributeMaxDynamicSharedMemorySize, SB128);
    cudaFuncSetAttribute(
        conv_bf16<0, 3, 3, 64, 128, 32, false, false, true, false, false>,
        cudaFuncAttributeMaxDynamicSharedMemorySize, SB32);
    cudaFuncSetAttribute(
        conv_bf16<1, 4, 4, 64, 128, 64, true, true, true, false, false>,
        cudaFuncAttributeMaxDynamicSharedMemorySize, SB64);

    // prep + enc1
    im2col_enc1<<<65536, 256>>>(x, pCol);
    pad_w1<<<16, 256>>>(enc_w1, pW1p);
    prep_w_tf32<16, 64, 128><<<512, 256>>>(enc_w2, pWT + WP_ENC2);
    flat_gemm_cvt<64, 64, 128, 8, 4, true><<<2048, 256>>>(pCol, pW1p, enc_b1, pCvA);
    prep_w_tf32<9, 128, 128><<<576, 256>>>(enc_w3, pWT + WP_ENC3);
    prep_w_tf32<9, 128, 32><<<144, 256>>>(erb1_w1, pWT + WP_ERB1);
    prep_w_tf32<9, 128, 32><<<144, 256>>>(erb2_w1, pWT + WP_ERB2);
    prep_w_bf16<9, 128, 128><<<576, 256>>>(dec_w, pWB + WB_DEC);
    prep_w_bf16<9, 128, 32><<<144, 256>>>(drb1_w1, pWB + WB_DRB1);
    prep_w_bf16<9, 128, 32><<<144, 256>>>(drb2_w1, pWB + WB_DRB2);
    prep_w_bf16<16, 128, 64><<<512, 256>>>(dt1_w, pWB + WB_DT1);
    transpose_w<<<12, 256>>>(dt2_w, pWdt2, 16, 64, 3);
    norme_kernel<<<2, 256>>>(emb, pN);
    embT_kernel<<<64, 256>>>(emb, pE);

    // Encoder (tf32 3-pass, unchanged)
    conv_mma<0, 4, 4, 2, 1, 128, 64, 128, 3, true, true, false, true, false>
        <<<512, 256, SM128>>>(pCvA, pWT + WP_ENC2, enc_b2, pB1, pCvB);
    conv_mma<0, 3, 3, 1, 1, 64, 128, 128, 3, true, false, true, true, true>
        <<<512, 256, SM128>>>(pCvB, pWT + WP_ENC3, enc_b3, pB2, pCvA);
    conv_mma<0, 3, 3, 1, 1, 64, 128, 32, 3, false, false, true, false, false>
        <<<512, 256, SM32>>>(pCvA, pWT + WP_ERB1, nullptr, pT, nullptr);
    conv1x1_res<false, true, 1, true><<<8192, 256>>>(pT, pB2, erb1_w2, pB1, pCvB, nullptr);
    conv_mma<0, 3, 3, 1, 1, 64, 128, 32, 3, false, false, true, false, false>
        <<<512, 256, SM32>>>(pCvB, pWT + WP_ERB2, nullptr, pT, nullptr);
    conv1x1_res<true, true, 0, false><<<8192, 256>>>(pT, pB1, erb2_w2, fout, nullptr, nullptr);

    // VQ (q + bf16 triple cvt)
    vq16<<<4096, 128>>>(fout, pE, emb, pN, qout, cv3A);

    // Decoder (bf16 triple-channel)
    conv_bf16<0, 3, 3, 64, 128, 128, true, false, true, true, true>
        <<<512, 256, SB128>>>(cv3A, pWB + WB_DEC, dec_b, pB1, cv3B);
    conv_bf16<0, 3, 3, 64, 128, 32, false, false, true, false, false>
        <<<512, 256, SB32>>>(cv3B, pWB + WB_DRB1, nullptr, pT, nullptr);
    conv1x1_res<false, true, 2, true><<<8192, 256>>>(pT, pB1, drb1_w2, pB2, nullptr, cv3A);
    conv_bf16<0, 3, 3, 64, 128, 32, false, false, true, false, false>
        <<<512, 256, SB32>>>(cv3A, pWB + WB_DRB2, nullptr, pT, nullptr);
    conv1x1_res<true, false, 2, false><<<8192, 256>>>(pT, pB2, drb2_w2, nullptr, nullptr, cv3B);
    conv_bf16<1, 4, 4, 64, 128, 64, true, true, true, false, false>
        <<<dim3(512, 4), 256, SB64>>>(cv3B, pWB + WB_DT1, dt1_b, pA, nullptr);
    dt2_kernel<<<4096, 256>>>(pA, pWdt2, dt2_b, yout);
}

// round 13
// speedup vs baseline: 1.2332x; 1.0107x over previous
#include <cuda_runtime.h>
#include <cuda_bf16.h>
#include <cstdint>

#define Y_SZ  (16*256*256*3)
#define F_SZ  (16*64*64*128)

__device__ __align__(16) float g_A[16*128*128*64];    // enc1 out / dt1 out
__device__ __align__(16) float g_col[16*128*128*64];  // enc1 im2col
__device__ __align__(16) float g_cvtA[16*128*128*64*2];
__device__ __align__(16) float g_cvtB[16*64*64*256];
__device__ __align__(16) float g_B1[16*64*64*128];
__device__ __align__(16) float g_B2[16*64*64*128];
__device__ __align__(16) float g_T[16*64*64*32];
__device__ __align__(16) float g_norme[512];
__device__ __align__(16) float g_embT[512*128];
__device__ __align__(16) float g_wdt2[16*3*64];
__device__ __align__(16) float g_w1p[64*64];
__device__ __align__(16) float g_wtens[800*1024];     // tf32 hi/lo weights (encoder)
__device__ __align__(16) __nv_bfloat16 g_wbf[1100*1024]; // bf16 triple weights (decoder)

// tf32 weight chunk offsets (floats); chunk size = 2*32*(OCW+4)
#define WP_ENC2 0
#define WP_ENC3 278528
#define WP_ERB1 591872
#define WP_ERB2 674816
// bf16 weight offsets (elements)
#define WB_DEC  0
#define WB_DRB1 442368
#define WB_DRB2 552960
#define WB_DT1  663552

__device__ __forceinline__ float4 relu4(float4 a) {
    a.x = fmaxf(a.x, 0.f); a.y = fmaxf(a.y, 0.f);
    a.z = fmaxf(a.z, 0.f); a.w = fmaxf(a.w, 0.f);
    return a;
}
__device__ __forceinline__ float dot4(float4 a, float4 b) {
    return fmaf(a.x, b.x, fmaf(a.y, b.y, fmaf(a.z, b.z, a.w * b.w)));
}
__device__ __forceinline__ unsigned long long pk2(float x, float y) {
    unsigned long long r;
    asm("mov.b64 %0, {%1, %2};" : "=l"(r)
        : "r"(__float_as_uint(x)), "r"(__float_as_uint(y)));
    return r;
}
__device__ __forceinline__ float2 up2(unsigned long long v) {
    unsigned int lo, hi;
    asm("mov.b64 {%0, %1}, %2;" : "=r"(lo), "=r"(hi) : "l"(v));
    return make_float2(__uint_as_float(lo), __uint_as_float(hi));
}
__device__ __forceinline__ void fma2(unsigned long long& d,
                                     unsigned long long a, unsigned long long b) {
    asm("fma.rn.f32x2 %0, %1, %2, %0;" : "+l"(d) : "l"(a), "l"(b));
}
__device__ __forceinline__ float rna_tf32(float x) {
    uint32_t o;
    asm("cvt.rna.tf32.f32 %0, %1;" : "=r"(o) : "f"(x));
    return __uint_as_float(o);
}
__device__ __forceinline__ void mma8(float* c, const uint32_t* a, float2 b) {
    asm volatile(
        "mma.sync.aligned.m16n8k8.row.col.f32.tf32.tf32.f32 "
        "{%0,%1,%2,%3},{%4,%5,%6,%7},{%8,%9},{%0,%1,%2,%3};"
        : "+f"(c[0]), "+f"(c[1]), "+f"(c[2]), "+f"(c[3])
        : "r"(a[0]), "r"(a[1]), "r"(a[2]), "r"(a[3]),
          "r"(__float_as_uint(b.x)), "r"(__float_as_uint(b.y)));
}
__device__ __forceinline__ void mma16(float* c, const uint32_t* a, const uint32_t* b) {
    asm volatile(
        "mma.sync.aligned.m16n8k16.row.col.f32.bf16.bf16.f32 "
        "{%0,%1,%2,%3},{%4,%5,%6,%7},{%8,%9},{%0,%1,%2,%3};"
        : "+f"(c[0]), "+f"(c[1]), "+f"(c[2]), "+f"(c[3])
        : "r"(a[0]), "r"(a[1]), "r"(a[2]), "r"(a[3]), "r"(b[0]), "r"(b[1]));
}
__device__ __forceinline__ void ldmx4(uint32_t* r, uint32_t addr) {
    asm volatile("ldmatrix.sync.aligned.m8n8.x4.shared.b16 {%0,%1,%2,%3}, [%4];"
        : "=r"(r[0]), "=r"(r[1]), "=r"(r[2]), "=r"(r[3]) : "r"(addr));
}
__device__ __forceinline__ uint32_t smem_u32(const void* p) {
    uint32_t a;
    asm("{ .reg .u64 t; cvta.to.shared.u64 t, %1; cvt.u32.u64 %0, t; }"
        : "=r"(a) : "l"(p));
    return a;
}
__device__ __forceinline__ void cpasync16(uint32_t dst, const void* src) {
    asm volatile("cp.async.cg.shared.global [%0], [%1], 16;" :: "r"(dst), "l"(src));
}
__device__ __forceinline__ void cpasync16z(uint32_t dst, const void* src, int sz) {
    asm volatile("cp.async.cg.shared.global [%0], [%1], 16, %2;"
                 :: "r"(dst), "l"(src), "r"(sz));
}
__device__ __forceinline__ void cpasync_commit() {
    asm volatile("cp.async.commit_group;" ::: "memory");
}
__device__ __forceinline__ void cpasync_wait0() {
    asm volatile("cp.async.wait_group 0;" ::: "memory");
}
// write bf16 triple [hi, lo, hi]
__device__ __forceinline__ void wr3(__nv_bfloat16* dst, float v) {
    __nv_bfloat16 b1 = __float2bfloat16_rn(v);
    float r = v - __bfloat162float(b1);
    dst[0] = b1;
    dst[1] = __float2bfloat16_rn(r);
    dst[2] = b1;
}

// ---- tf32 weight prep: [tap][ic][oc] -> per-(tap,kc,nh) hi/lo images of width OCW ----
template<int TAPS, int IC, int OC, int OCW>
__global__ void prep_w_tf32(const float* __restrict__ w, float* __restrict__ out) {
    constexpr int KC = IC / 32;
    constexpr int NH = OC / OCW;
    constexpr int BF = 32 * (OCW + 4);
    int t = blockIdx.x * 256 + threadIdx.x;
    if (t >= TAPS * IC * OC) return;
    int oc = t % OC;
    int r = t / OC;
    int ic = r % IC;
    int tap = r / IC;
    int kc = ic >> 5, lk = ic & 31;
    int k8 = lk >> 3, t4 = lk & 3, half = (lk >> 2) & 1;
    int nh = oc / OCW, ocl = oc % OCW;
    float v = w[t];
    float hi = rna_tf32(v);
    float lo = rna_tf32(v - hi);
    long base = (long)((tap * KC + kc) * NH + nh) * 2 * BF;
    int idx = ((k8 * 4 + t4) * (OCW + 4) + ocl) * 2 + half;
    out[base + idx] = hi;
    out[base + BF + idx] = lo;
}

// ---- bf16 weight prep (decoder): [tap][kc][oc][96], triple [b1,b1,b2] ----
template<int TAPS, int IC, int OC>
__global__ void prep_w_bf16(const float* __restrict__ w, __nv_bfloat16* __restrict__ out) {
    constexpr int KC = IC / 32;
    int t = blockIdx.x * 256 + threadIdx.x;
    if (t >= TAPS * IC * OC) return;
    int oc = t % OC;
    int r = t / OC;
    int ic = r % IC;
    int tap = r / IC;
    int kc = ic >> 5, lk = ic & 31;
    float v = w[t];
    __nv_bfloat16 b1 = __float2bfloat16_rn(v);
    float rr = v - __bfloat162float(b1);
    __nv_bfloat16 b2 = __float2bfloat16_rn(rr);
    long base = (((long)(tap * KC + kc)) * OC + oc) * 96 + 3 * lk;
    out[base] = b1;
    out[base + 1] = b1;
    out[base + 2] = b2;
}

// ================= tf32 mma conv (ENCODER), N-split via blockIdx.y =================
template<int KH, int KW, int STRIDE, int PAD, int IH, int IC, int OC, int OCW,
         int NPASS, bool HAS_BIAS, bool RELU_OUT, bool WRITE_OUT, bool WRITE_CVT,
         bool CVT_RELU>
__global__ void __launch_bounds__(256, 2) conv_mma(
    const float* __restrict__ cv, const float* __restrict__ wp,
    const float* __restrict__ bias, float* __restrict__ out,
    float* __restrict__ cvt_out)
{
    constexpr int KC = IC / 32;
    constexpr int NTAPS = KH * KW;
    constexpr int NH = OC / OCW;
    constexpr int BMp = 132;
    constexpr int BNp = OCW + 4;
    constexpr int AF = 16 * BMp * 2;
    constexpr int BF = 16 * BNp * 2;
    constexpr int SS = 2 * AF + 2 * BF;
    constexpr int NT = OCW / 16;
    constexpr int TOTAL = NTAPS * KC;

    extern __shared__ __align__(16) float sm[];

    int tid = threadIdx.x;
    int lane = tid & 31;
    int g = lane >> 2, t4 = lane & 3;
    int wid = tid >> 5;
    int wm = wid >> 1, wn = wid & 1;
    int m0 = blockIdx.x * 128;
    int nh = (NH > 1) ? blockIdx.y : 0;
    int c4 = tid & 7, mp = tid >> 3;
    int k8 = c4 >> 1, h = c4 & 1;

    float acc[2][NT][4];
#pragma unroll
    for (int i = 0; i < 2; i++)
#pragma unroll
        for (int j = 0; j < NT; j++)
#pragma unroll
            for (int u = 0; u < 4; u++) acc[i][j][u] = 0.f;

    auto tapgeom = [&](int it, int& hoff, int& woff, int& wtap, int& kc) {
        int tap = it / KC; kc = it % KC;
        int kh = tap / KW, kw = tap % KW;
        hoff = kh - PAD; woff = kw - PAD; wtap = tap;
    };
    auto fillregs = [&](int it, float4* rh, float4* rl) {
        int hoff, woff, wtap, kc;
        tapgeom(it, hoff, woff, wtap, kc);
#pragma unroll
        for (int pass = 0; pass < 4; pass++) {
            int m = mp + 32 * pass;
            int p = m0 + m;
            int n_img = p >> 12, oh = (p >> 6) & 63, ow = p & 63;
            int ih = oh * STRIDE + hoff, iw = ow * STRIDE + woff;
            rh[pass] = make_float4(0.f, 0.f, 0.f, 0.f);
            rl[pass] = make_float4(0.f, 0.f, 0.f, 0.f);
            if ((unsigned)ih < (unsigned)IH && (unsigned)iw < (unsigned)IH) {
                long P = ((long)n_img * IH + ih) * IH + iw;
                const float* b = cv + P * 2 * IC + kc * 64 + 4 * c4;
                rh[pass] = *(const float4*)(b);
                rl[pass] = *(const float4*)(b + 32);
            }
        }
    };
    auto stsregs = [&](int s, const float4* rh, const float4* rl) {
        float* Ah = sm + s * SS;
        float* Al = Ah + AF;
#pragma unroll
        for (int pass = 0; pass < 4; pass++) {
            int m = mp + 32 * pass;
            int rot = ((m + 4 * k8) & 127) * 2 + h;
            int r0 = (k8 * 4 + 0) * (2 * BMp) + rot;
            int r1 = (k8 * 4 + 1) * (2 * BMp) + rot;
            int r2 = (k8 * 4 + 2) * (2 * BMp) + rot;
            int r3 = (k8 * 4 + 3) * (2 * BMp) + rot;
            Ah[r0] = rh[pass].x; Ah[r1] = rh[pass].y;
            Ah[r2] = rh[pass].z; Ah[r3] = rh[pass].w;
            Al[r0] = rl[pass].x; Al[r1] = rl[pass].y;
            Al[r2] = rl[pass].z; Al[r3] = rl[pass].w;
        }
    };
    auto copyB = [&](int it, int s) {
        int hoff, woff, wtap, kc;
        tapgeom(it, hoff, woff, wtap, kc);
        const float* src = wp + (long)((wtap * KC + kc) * NH + nh) * 2 * BF;
        uint32_t dst = smem_u32(sm + s * SS + 2 * AF);
        constexpr int NF4 = 2 * BF / 4;
#pragma unroll
        for (int i = 0; i < (NF4 + 255) / 256; i++) {
            int idx = tid + i * 256;
            if (idx < NF4) cpasync16(dst + idx * 16, src + idx * 4);
        }
        cpasync_commit();
    };
    auto do_mma = [&](int s) {
        const float* Ah = sm + s * SS;
        const float* Al = Ah + AF;
        const float* Bh = Ah + 2 * AF;
        const float* Bl = Bh + BF;
#pragma unroll
        for (int kk = 0; kk < 4; kk++) {
            uint32_t ah[2][4], al[2][4];
            const float2* arh = (const float2*)Ah + (kk * 4 + t4) * BMp;
            const float2* arl = (const float2*)Al + (kk * 4 + t4) * BMp;
#pragma unroll
            for (int mt = 0; mt < 2; mt++) {
                int c0 = (wm * 32 + mt * 16 + g + 4 * kk) & 127;
                int c1 = (wm * 32 + mt * 16 + g + 8 + 4 * kk) & 127;
                float2 q0 = arh[c0], q1 = arh[c1];
                ah[mt][0] = __float_as_uint(q0.x);
                ah[mt][1] = __float_as_uint(q1.x);
                ah[mt][2] = __float_as_uint(q0.y);
                ah[mt][3] = __float_as_uint(q1.y);
                float2 s0 = arl[c0], s1 = arl[c1];
                al[mt][0] = __float_as_uint(s0.x);
                al[mt][1] = __float_as_uint(s1.x);
                al[mt][2] = __float_as_uint(s0.y);
                al[mt][3] = __float_as_uint(s1.y);
            }
            float2 bh[NT], bl[NT];
            const float2* brh = (const float2*)Bh + (kk * 4 + t4) * BNp + wn * (OCW / 2) + g;
            const float2* brl = (const float2*)Bl + (kk * 4 + t4) * BNp + wn * (OCW / 2) + g;
#pragma unroll
            for (int nt = 0; nt < NT; nt++) { bh[nt] = brh[nt * 8]; bl[nt] = brl[nt * 8]; }
#pragma unroll
            for (int nt = 0; nt < NT; nt++)
#pragma unroll
                for (int mt = 0; mt < 2; mt++) mma8(acc[mt][nt], ah[mt], bh[nt]);
#pragma unroll
            for (int nt = 0; nt < NT; nt++)
#pragma unroll
                for (int mt = 0; mt < 2; mt++) mma8(acc[mt][nt], al[mt], bh[nt]);
#pragma unroll
            for (int nt = 0; nt < NT; nt++)
#pragma unroll
                for (int mt = 0; mt < 2; mt++) mma8(acc[mt][nt], ah[mt], bl[nt]);
            if (NPASS == 4) {
#pragma unroll
                for (int nt = 0; nt < NT; nt++)
#pragma unroll
                    for (int mt = 0; mt < 2; mt++) mma8(acc[mt][nt], al[mt], bl[nt]);
            }
        }
    };

    {
        float4 rh[4], rl[4];
        fillregs(0, rh, rl);
        stsregs(0, rh, rl);
        copyB(0, 0);
        cpasync_wait0();
        __syncthreads();
    }
    for (int it = 0; it < TOTAL; it++) {
        int cur = it & 1, nxt = cur ^ 1;
        float4 rh[4], rl[4];
        bool have = (it + 1 < TOTAL);
        if (have) {
            fillregs(it + 1, rh, rl);
            copyB(it + 1, nxt);
        }
        do_mma(cur);
        if (have) stsregs(nxt, rh, rl);
        cpasync_wait0();
        __syncthreads();
    }

#pragma unroll
    for (int mt = 0; mt < 2; mt++) {
        int r0 = m0 + wm * 32 + mt * 16 + g;
        int r1 = r0 + 8;
        long o0 = (long)r0 * OC;
        long o1 = (long)r1 * OC;
#pragma unroll
        for (int nt = 0; nt < NT; nt++) {
            int nb = nh * OCW + wn * (OCW / 2) + nt * 8 + 2 * t4;
            float b0v = HAS_BIAS ? bias[nb] : 0.f;
            float b1v = HAS_BIAS ? bias[nb + 1] : 0.f;
            float2 v0 = make_float2(acc[mt][nt][0] + b0v, acc[mt][nt][1] + b1v);
            float2 v1 = make_float2(acc[mt][nt][2] + b0v, acc[mt][nt][3] + b1v);
            if (RELU_OUT) {
                v0.x = fmaxf(v0.x, 0.f); v0.y = fmaxf(v0.y, 0.f);
                v1.x = fmaxf(v1.x, 0.f); v1.y = fmaxf(v1.y, 0.f);
            }
            if (WRITE_OUT) {
                *(float2*)(out + o0 + nb) = v0;
                *(float2*)(out + o1 + nb) = v1;
            }
            if (WRITE_CVT) {
                float c0x = CVT_RELU ? fmaxf(v0.x, 0.f) : v0.x;
                float c0y = CVT_RELU ? fmaxf(v0.y, 0.f) : v0.y;
                float c1x = CVT_RELU ? fmaxf(v1.x, 0.f) : v1.x;
                float c1y = CVT_RELU ? fmaxf(v1.y, 0.f) : v1.y;
                float h0x = rna_tf32(c0x), h0y = rna_tf32(c0y);
                float h1x = rna_tf32(c1x), h1y = rna_tf32(c1y);
                long cb0 = (long)r0 * 2 * OC + ((nb >> 5) << 6) + (nb & 31);
                long cb1 = (long)r1 * 2 * OC + ((nb >> 5) << 6) + (nb & 31);
                *(float2*)(cvt_out + cb0) = make_float2(h0x, h0y);
                *(float2*)(cvt_out + cb0 + 32) =
                    make_float2(rna_tf32(c0x - h0x), rna_tf32(c0y - h0y));
                *(float2*)(cvt_out + cb1) = make_float2(h1x, h1y);
                *(float2*)(cvt_out + cb1 + 32) =
                    make_float2(rna_tf32(c1x - h1x), rna_tf32(c1y - h1y));
            }
        }
    }
}

// ================= bf16 triple-channel mma conv (DECODER) =================
template<int MODE, int KH, int KW, int IH, int IC, int OC,
         bool HAS_BIAS, bool RELU_OUT, bool WRITE_OUT, bool WRITE_CVT3, bool CVT_RELU>
__global__ void __launch_bounds__(256, 2) conv_bf16(
    const __nv_bfloat16* __restrict__ cv3, const __nv_bfloat16* __restrict__ wp3,
    const float* __restrict__ bias, float* __restrict__ out,
    __nv_bfloat16* __restrict__ cvt_out)
{
    constexpr int KC = IC / 32;
    constexpr int NTAPS = (MODE == 0) ? KH * KW : 4;
    constexpr int AU = 128 * 13;
    constexpr int BU = OC * 13;
    constexpr int SU = AU + BU;
    constexpr int NT = OC / 16;
    constexpr int TOTAL = NTAPS * KC;

    extern __shared__ __align__(16) char smb[];
    uint32_t sbase = smem_u32(smb);

    int tid = threadIdx.x;
    int lane = tid & 31;
    int g = lane >> 2, t4 = lane & 3;
    int wid = tid >> 5;
    int wm = wid >> 1, wn = wid & 1;
    int m0 = blockIdx.x * 128;
    int po = 0, pw_ = 0;
    if (MODE == 1) { po = blockIdx.y >> 1; pw_ = blockIdx.y & 1; }

    float acc[2][NT][4];
#pragma unroll
    for (int i = 0; i < 2; i++)
#pragma unroll
        for (int j = 0; j < NT; j++)
#pragma unroll
            for (int u = 0; u < 4; u++) acc[i][j][u] = 0.f;

    auto tapgeom = [&](int it, int& hoff, int& woff, int& wtap, int& kc) {
        int tap = it / KC; kc = it % KC;
        if (MODE == 0) {
            int kh = tap / KW, kw = tap % KW;
            hoff = kh - 1; woff = kw - 1; wtap = tap;
        } else {
            int dh = tap >> 1, dw = tap & 1;
            hoff = po + dh - 1; woff = pw_ + dw - 1;
            wtap = (po + 2 * dh) * 4 + (pw_ + 2 * dw);
        }
    };
    auto copyA = [&](int it, int s) {
        int hoff, woff, wtap, kc;
        tapgeom(it, hoff, woff, wtap, kc);
        uint32_t dst0 = sbase + s * SU * 16;
#pragma unroll
        for (int i = 0; i < 6; i++) {
            int idx = tid + i * 256;
            int m = idx / 12, c = idx % 12;
            int p = m0 + m;
            int n_img = p >> 12, oh = (p >> 6) & 63, ow = p & 63;
            int ih = oh + hoff, iw = ow + woff;
            bool valid = (unsigned)ih < (unsigned)IH && (unsigned)iw < (unsigned)IH;
            long P = valid ? (((long)n_img * IH + ih) * IH + iw) : 0;
            const char* src = (const char*)cv3 + (P * KC + kc) * 192 + c * 16;
            cpasync16z(dst0 + (m * 13 + c) * 16, src, valid ? 16 : 0);
        }
    };
    auto copyB = [&](int it, int s) {
        int hoff, woff, wtap, kc;
        tapgeom(it, hoff, woff, wtap, kc);
        const char* src0 = (const char*)(wp3 + ((long)(wtap * KC + kc) * OC) * 96);
        uint32_t dst0 = sbase + s * SU * 16 + AU * 16;
        constexpr int NCH = OC * 12;
#pragma unroll
        for (int i = 0; i < (NCH + 255) / 256; i++) {
            int idx = tid + i * 256;
            if (idx < NCH) {
                int row = idx / 12, c = idx % 12;
                cpasync16(dst0 + (row * 13 + c) * 16, src0 + idx * 16);
            }
        }
    };
    int l7 = lane & 7, q = lane >> 3;
    uint32_t arow = ((q & 1) ? 8 : 0) + l7;
    uint32_t acol = (q >> 1) * 16;
    uint32_t brow = ((q >> 1) ? 8 : 0) + l7;
    uint32_t bcol = (q & 1) * 16;
    auto do_mma = [&](int s) {
        uint32_t Ab = sbase + s * SU * 16;
        uint32_t Bb = Ab + AU * 16;
#pragma unroll
        for (int ks = 0; ks < 6; ks++) {
            uint32_t a[2][4];
#pragma unroll
            for (int mt = 0; mt < 2; mt++)
                ldmx4(a[mt], Ab + (wm * 32 + mt * 16 + arow) * 208 + ks * 32 + acol);
            uint32_t b[NT][2];
#pragma unroll
            for (int np = 0; np < NT / 2; np++) {
                uint32_t n0 = wn * (OC / 2) + np * 16;
                uint32_t r[4];
                ldmx4(r, Bb + (n0 + brow) * 208 + ks * 32 + bcol);
                b[2 * np][0] = r[0]; b[2 * np][1] = r[1];
                b[2 * np + 1][0] = r[2]; b[2 * np + 1][1] = r[3];
            }
#pragma unroll
            for (int nt = 0; nt < NT; nt++)
#pragma unroll
                for (int mt = 0; mt < 2; mt++) mma16(acc[mt][nt], a[mt], b[nt]);
        }
    };

    copyA(0, 0); copyB(0, 0); cpasync_commit();
    cpasync_wait0();
    __syncthreads();
    for (int it = 0; it < TOTAL; it++) {
        int cur = it & 1, nxt = cur ^ 1;
        if (it + 1 < TOTAL) {
            copyA(it + 1, nxt);
            copyB(it + 1, nxt);
            cpasync_commit();
        }
        do_mma(cur);
        cpasync_wait0();
        __syncthreads();
    }

#pragma unroll
    for (int mt = 0; mt < 2; mt++) {
        int r0 = m0 + wm * 32 + mt * 16 + g;
        int r1 = r0 + 8;
        long o0, o1;
        if (MODE == 0) {
            o0 = (long)r0 * OC;
            o1 = (long)r1 * OC;
        } else {
            int n0 = r0 >> 12, a0 = (r0 >> 6) & 63, b0 = r0 & 63;
            int n1 = r1 >> 12, a1 = (r1 >> 6) & 63, b1 = r1 & 63;
            o0 = (((long)n0 * 128 + 2 * a0 + po) * 128 + 2 * b0 + pw_) * OC;
            o1 = (((long)n1 * 128 + 2 * a1 + po) * 128 + 2 * b1 + pw_) * OC;
        }
#pragma unroll
        for (int nt = 0; nt < NT; nt++) {
            int nb = wn * (OC / 2) + nt * 8 + 2 * t4;
            float b0v = HAS_BIAS ? bias[nb] : 0.f;
            float b1v = HAS_BIAS ? bias[nb + 1] : 0.f;
            float2 v0 = make_float2(acc[mt][nt][0] + b0v, acc[mt][nt][1] + b1v);
            float2 v1 = make_float2(acc[mt][nt][2] + b0v, acc[mt][nt][3] + b1v);
            if (RELU_OUT) {
                v0.x = fmaxf(v0.x, 0.f); v0.y = fmaxf(v0.y, 0.f);
                v1.x = fmaxf(v1.x, 0.f); v1.y = fmaxf(v1.y, 0.f);
            }
            if (WRITE_OUT) {
                *(float2*)(out + o0 + nb) = v0;
                *(float2*)(out + o1 + nb) = v1;
            }
            if (WRITE_CVT3) {
                constexpr int KC2 = OC / 32;
                float c0x = CVT_RELU ? fmaxf(v0.x, 0.f) : v0.x;
                float c0y = CVT_RELU ? fmaxf(v0.y, 0.f) : v0.y;
                float c1x = CVT_RELU ? fmaxf(v1.x, 0.f) : v1.x;
                float c1y = CVT_RELU ? fmaxf(v1.y, 0.f) : v1.y;
                long cb0 = ((long)r0 * KC2 + (nb >> 5)) * 96 + 3 * (nb & 31);
                long cb1 = ((long)r1 * KC2 + (nb >> 5)) * 96 + 3 * (nb & 31);
                wr3(cvt_out + cb0, c0x);
                wr3(cvt_out + cb0 + 3, c0y);
                wr3(cvt_out + cb1, c1x);
                wr3(cvt_out + cb1 + 3, c1y);
            }
        }
    }
}

// ---------------- small kernels ----------------
__global__ void transpose_w(const float* __restrict__ in, float* __restrict__ out,
                            int K, int IC, int OC) {
    int i = blockIdx.x * blockDim.x + threadIdx.x;
    int total = K * IC * OC;
    if (i >= total) return;
    int oc = i % OC;
    int ic = (i / OC) % IC;
    int k  = i / (OC * IC);
    out[(k * OC + oc) * IC + ic] = in[i];
}

__global__ void norme_kernel(const float* __restrict__ emb, float* __restrict__ norme) {
    int k = blockIdx.x * blockDim.x + threadIdx.x;
    if (k >= 512) return;
    const float4* e = (const float4*)(emb + k * 128);
    float s = 0.f;
#pragma unroll 8
    for (int i = 0; i < 32; i++) {
        float4 v = e[i];
        s = fmaf(v.x, v.x, s); s = fmaf(v.y, v.y, s);
        s = fmaf(v.z, v.z, s); s = fmaf(v.w, v.w, s);
    }
    norme[k] = s;
}

__global__ void embT_kernel(const float* __restrict__ emb, float* __restrict__ embT) {
    int i = blockIdx.x * 256 + threadIdx.x;
    if (i >= 512 * 32) return;
    int c = i & 511, d4 = i >> 9;
    float4 v = *(const float4*)(emb + c * 128 + 4 * d4);
    *(float4*)(embT + (d4 * 512 + c) * 4) = v;
}

__global__ void pad_w1(const float* __restrict__ w, float* __restrict__ out) {
    int t = blockIdx.x * 256 + threadIdx.x;
    if (t >= 64 * 64) return;
    int r = t >> 6;
    out[t] = (r < 48) ? w[t] : 0.f;
}

__global__ void im2col_enc1(const float* __restrict__ x, float* __restrict__ col) {
    int t = blockIdx.x * 256 + threadIdx.x;
    int kidx = t & 63;
    int p = t >> 6;
    int ow = p & 127, oh = (p >> 7) & 127, n = p >> 14;
    float v = 0.f;
    if (kidx < 48) {
        int ic = kidx % 3;
        int kw = (kidx / 3) & 3;
        int kh = kidx / 12;
        int ih = 2 * oh - 1 + kh, iw = 2 * ow - 1 + kw;
        if ((unsigned)ih < 256u && (unsigned)iw < 256u)
            v = x[((n * 256 + ih) * 256 + iw) * 3 + ic];
    }
    col[t] = v;
}

template<int IC, int OC, int BM, int TM, int TN, bool HAS_BIAS>
__global__ void __launch_bounds__(256, 2) flat_gemm_cvt(
    const float* __restrict__ in, const float* __restrict__ w,
    const float* __restrict__ bias, float* __restrict__ cvt)
{
    constexpr int BK = 32;
    constexpr int BN = OC;
    constexpr int TX = BN / TN;
    constexpr int ASTR = BM + 2;
    __shared__ __align__(16) float As[BK * ASTR];
    __shared__ __align__(16) float Bs[BK * BN];
    int tid = threadIdx.x;
    int m0 = blockIdx.x * BM;
    int tx = tid % TX, ty = tid / TX;
    int c4 = tid & 7;
    int mp = tid >> 3;
    unsigned long long acc2[TM / 2][TN];
#pragma unroll
    for (int i = 0; i < TM / 2; i++)
#pragma unroll
        for (int j = 0; j < TN; j++) acc2[i][j] = 0ull;

    for (int kc = 0; kc < IC / BK; kc++) {
        __syncthreads();
#pragma unroll
        for (int pass = 0; pass < BM / 32; pass++) {
            int m = mp + pass * 32;
            int p = m0 + m;
            float4 v = *(const float4*)(in + (long)p * IC + kc * BK + 4 * c4);
            int kk = 4 * c4;
            As[(kk + 0) * ASTR + m] = v.x;
            As[(kk + 1) * ASTR + m] = v.y;
            As[(kk + 2) * ASTR + m] = v.z;
            As[(kk + 3) * ASTR + m] = v.w;
        }
        {
            const float* wb = w + kc * BK * OC;
#pragma unroll
            for (int i = 0; i < (BK * BN / 4) / 256; i++) {
                int idx = tid + i * 256;
                int kr = idx / (BN / 4);
                int n4 = idx % (BN / 4);
                *(float4*)(Bs + kr * BN + 4 * n4) = *(const float4*)(wb + kr * OC + 4 * n4);
            }
        }
        __syncthreads();
#pragma unroll 8
        for (int k = 0; k < BK; k++) {
            unsigned long long a2[TM / 2], b2[TN];
            const double* ap = (const double*)(As + k * ASTR + ty * TM);
#pragma unroll
            for (int i = 0; i < TM / 2; i++) a2[i] = __double_as_longlong(ap[i]);
            float b[TN];
#pragma unroll
            for (int j = 0; j < TN / 4; j++)
                *(float4*)(b + 4 * j) = *(const float4*)(Bs + k * BN + tx * TN + 4 * j);
#pragma unroll
            for (int j = 0; j < TN; j++) b2[j] = pk2(b[j], b[j]);
#pragma unroll
            for (int i = 0; i < TM / 2; i++)
#pragma unroll
                for (int j = 0; j < TN; j++) fma2(acc2[i][j], a2[i], b2[j]);
        }
    }
    float bv[TN];
#pragma unroll
    for (int j = 0; j < TN; j++) bv[j] = HAS_BIAS ? bias[tx * TN + j] : 0.f;
    int base_m = m0 + ty * TM;
    int col0 = tx * TN;
    int kcq = col0 >> 5, off = col0 & 31;
#pragma unroll
    for (int i2 = 0; i2 < TM / 2; i2++) {
        float2 tv[TN];
#pragma unroll
        for (int j = 0; j < TN; j++) tv[j] = up2(acc2[i2][j]);
#pragma unroll
        for (int hh = 0; hh < 2; hh++) {
            int p = base_m + 2 * i2 + hh;
            float4 v;
            v.x = fmaxf((hh ? tv[0].y : tv[0].x) + bv[0], 0.f);
            v.y = fmaxf((hh ? tv[1].y : tv[1].x) + bv[1], 0.f);
            v.z = fmaxf((hh ? tv[2].y : tv[2].x) + bv[2], 0.f);
            v.w = fmaxf((hh ? tv[3].y : tv[3].x) + bv[3], 0.f);
            float4 hi = make_float4(rna_tf32(v.x), rna_tf32(v.y),
                                    rna_tf32(v.z), rna_tf32(v.w));
            float4 lo = make_float4(rna_tf32(v.x - hi.x), rna_tf32(v.y - hi.y),
                                    rna_tf32(v.z - hi.z), rna_tf32(v.w - hi.w));
            long base = (long)p * 2 * OC + kcq * 64 + off;
            *(float4*)(cvt + base) = hi;
            *(float4*)(cvt + base + 32) = lo;
        }
    }
}

// 1x1 conv (relu in) + residual; CVTM: 0 none, 1 tf32 hi/lo, 2 bf16 triple
template<bool RELU_OUT, bool WRITE_OUT, int CVTM, bool CVT_RELU>
__global__ void conv1x1_res(const float* __restrict__ tin, const float* __restrict__ res,
                            const float* __restrict__ w, float* __restrict__ out,
                            float* __restrict__ cvt, __nv_bfloat16* __restrict__ cvt3) {
    int t = blockIdx.x * 256 + threadIdx.x;
    int oc = t & 127;
    long p0 = (long)(t >> 7) * 4;
    float wv[32];
#pragma unroll
    for (int ic = 0; ic < 32; ic++) wv[ic] = w[ic * 128 + oc];
    float accp[4] = {0.f, 0.f, 0.f, 0.f};
#pragma unroll
    for (int ic4 = 0; ic4 < 8; ic4++) {
#pragma unroll
        for (int p = 0; p < 4; p++) {
            float4 tv = *(const float4*)(tin + (p0 + p) * 32 + 4 * ic4);
            tv = relu4(tv);
            accp[p] = fmaf(tv.x, wv[4 * ic4],     accp[p]);
            accp[p] = fmaf(tv.y, wv[4 * ic4 + 1], accp[p]);
            accp[p] = fmaf(tv.z, wv[4 * ic4 + 2], accp[p]);
            accp[p] = fmaf(tv.w, wv[4 * ic4 + 3], accp[p]);
        }
    }
    long o = p0 * 128 + oc;
    int kcq = oc >> 5, off = oc & 31;
#pragma unroll
    for (int p = 0; p < 4; p++) {
        float v = res[o + p * 128] + accp[p];
        if (RELU_OUT) v = fmaxf(v, 0.f);
        if (WRITE_OUT) out[o + p * 128] = v;
        if (CVTM == 1) {
            float cvv = CVT_RELU ? fmaxf(v, 0.f) : v;
            float hi = rna_tf32(cvv);
            long base = (p0 + p) * 256 + kcq * 64 + off;
            cvt[base] = hi;
            cvt[base + 32] = rna_tf32(cvv - hi);
        }
        if (CVTM == 2) {
            float cvv = CVT_RELU ? fmaxf(v, 0.f) : v;
            long base = ((p0 + p) * 4 + kcq) * 96 + 3 * off;
            wr3(cvt3 + base, cvv);
        }
    }
}

// VQ: writes q (fp32) + bf16 triple cvt for the decoder conv
__global__ void __launch_bounds__(128) vq16(const float* __restrict__ f,
                                            const float* __restrict__ embT,
                                            const float* __restrict__ emb,
                                            const float* __restrict__ norme,
                                            float* __restrict__ q,
                                            __nv_bfloat16* __restrict__ qcvt3) {
    __shared__ float4 xs4[16 * 32];
    __shared__ float rdist[16 * 128];
    __shared__ int   ridx[16 * 128];
    __shared__ int   best[16];
    int tid = threadIdx.x;
    long pixel0 = (long)blockIdx.x * 16;
    const float4* fin = (const float4*)(f + pixel0 * 128);
#pragma unroll
    for (int i = 0; i < 4; i++) xs4[tid + 128 * i] = fin[tid + 128 * i];
    __syncthreads();

    unsigned long long acc2[4][8];
#pragma unroll
    for (int j = 0; j < 4; j++)
#pragma unroll
        for (int p2 = 0; p2 < 8; p2++) acc2[j][p2] = 0ull;

    const float4* eT = (const float4*)embT;
    for (int d4 = 0; d4 < 32; d4++) {
        float4 ev[4];
#pragma unroll
        for (int j = 0; j < 4; j++) ev[j] = eT[d4 * 512 + 128 * j + tid];
        unsigned long long e2[4][4];
#pragma unroll
        for (int j = 0; j < 4; j++) {
            e2[j][0] = pk2(ev[j].x, ev[j].x);
            e2[j][1] = pk2(ev[j].y, ev[j].y);
            e2[j][2] = pk2(ev[j].z, ev[j].z);
            e2[j][3] = pk2(ev[j].w, ev[j].w);
        }
#pragma unroll
        for (int p2 = 0; p2 < 8; p2++) {
            float4 xa = xs4[(2 * p2) * 32 + d4];
            float4 xb = xs4[(2 * p2 + 1) * 32 + d4];
            unsigned long long xp0 = pk2(xa.x, xb.x);
            unsigned long long xp1 = pk2(xa.y, xb.y);
            unsigned long long xp2 = pk2(xa.z, xb.z);
            unsigned long long xp3 = pk2(xa.w, xb.w);
#pragma unroll
            for (int j = 0; j < 4; j++) {
                fma2(acc2[j][p2], xp0, e2[j][0]);
                fma2(acc2[j][p2], xp1, e2[j][1]);
                fma2(acc2[j][p2], xp2, e2[j][2]);
                fma2(acc2[j][p2], xp3, e2[j][3]);
            }
        }
    }
    float accs[4][16];
#pragma unroll
    for (int j = 0; j < 4; j++)
#pragma unroll
        for (int p2 = 0; p2 < 8; p2++) {
            float2 u = up2(acc2[j][p2]);
            accs[j][2 * p2] = u.x;
            accs[j][2 * p2 + 1] = u.y;
        }
    float nd[4];
#pragma unroll
    for (int j = 0; j < 4; j++) nd[j] = norme[tid + 128 * j];
#pragma unroll
    for (int p = 0; p < 16; p++) {
        float bd = 1e30f; int bi = 0;
#pragma unroll
        for (int j = 0; j < 4; j++) {
            float d = nd[j] - 2.f * accs[j][p];
            if (d < bd) { bd = d; bi = tid + 128 * j; }
        }
        rdist[p * 128 + tid] = bd;
        ridx[p * 128 + tid]  = bi;
    }
    __syncthreads();
    if (tid < 16) {
        float bd = 1e30f; int bi = 1 << 30;
        for (int u = 0; u < 128; u++) {
            float d = rdist[tid * 128 + u];
            int   i = ridx[tid * 128 + u];
            if (d < bd || (d == bd && i < bi)) { bd = d; bi = i; }
        }
        best[tid] = bi;
    }
    __syncthreads();
    int kcq = tid >> 5, off = tid & 31;
#pragma unroll
    for (int p = 0; p < 16; p++) {
        float e = emb[best[p] * 128 + tid];
        q[(pixel0 + p) * 128 + tid] = e;
        long base = ((pixel0 + p) * 4 + kcq) * 96 + 3 * off;
        wr3(qcvt3 + base, e);
    }
}

__global__ void dt2_kernel(const float* __restrict__ in, const float* __restrict__ wt,
                           const float* __restrict__ b, float* __restrict__ out) {
    int t = blockIdx.x * 256 + threadIdx.x;
    int ow = t & 255;
    int oh = (t >> 8) & 255;
    int n  = t >> 16;
    float a0 = b[0], a1 = b[1], a2 = b[2];
#pragma unroll
    for (int dh = 0; dh < 2; dh++) {
        int kh = (oh & 1) + 2 * dh;
        int ih2 = oh + kh - 2;
        if (ih2 < 0 || ih2 >= 256) continue;
        int ih = ih2 >> 1;
#pragma unroll
        for (int dw = 0; dw < 2; dw++) {
            int kw = (ow & 1) + 2 * dw;
            int iw2 = ow + kw - 2;
            if (iw2 < 0 || iw2 >= 256) continue;
            int iw = iw2 >> 1;
            const float4* xp = (const float4*)(in + ((n * 128 + ih) * 128 + iw) * 64);
            const float* wb = wt + (kh * 4 + kw) * 3 * 64;
            const float4* w0 = (const float4*)(wb);
            const float4* w1 = (const float4*)(wb + 64);
            const float4* w2 = (const float4*)(wb + 128);
#pragma unroll 4
            for (int ic4 = 0; ic4 < 16; ic4++) {
                float4 x4 = xp[ic4];
                a0 += dot4(x4, w0[ic4]);
                a1 += dot4(x4, w1[ic4]);
                a2 += dot4(x4, w2[ic4]);
            }
        }
    }
    float* op = out + (long)((n * 256 + oh) * 256 + ow) * 3;
    op[0] = a0; op[1] = a1; op[2] = a2;
}

extern "C" void kernel_launch(void* const* d_in, const int* in_sizes, int n_in,
                              void* d_out, int out_size) {
    const float* x       = (const float*)d_in[0];
    const float* emb     = (const float*)d_in[1];
    const float* enc_w1  = (const float*)d_in[2];
    const float* enc_b1  = (const float*)d_in[3];
    const float* enc_w2  = (const float*)d_in[4];
    const float* enc_b2  = (const float*)d_in[5];
    const float* enc_w3  = (const float*)d_in[6];
    const float* enc_b3  = (const float*)d_in[7];
    const float* erb1_w1 = (const float*)d_in[8];
    const float* erb1_w2 = (const float*)d_in[9];
    const float* erb2_w1 = (const float*)d_in[10];
    const float* erb2_w2 = (const float*)d_in[11];
    const float* dec_w   = (const float*)d_in[12];
    const float* dec_b   = (const float*)d_in[13];
    const float* drb1_w1 = (const float*)d_in[14];
    const float* drb1_w2 = (const float*)d_in[15];
    const float* drb2_w1 = (const float*)d_in[16];
    const float* drb2_w2 = (const float*)d_in[17];
    const float* dt1_w   = (const float*)d_in[18];
    const float* dt1_b   = (const float*)d_in[19];
    const float* dt2_w   = (const float*)d_in[20];
    const float* dt2_b   = (const float*)d_in[21];

    float *pA, *pCol, *pCvA, *pCvB, *pB1, *pB2, *pT, *pN, *pE, *pWdt2, *pW1p, *pWT;
    __nv_bfloat16* pWB;
    cudaGetSymbolAddress((void**)&pA,    g_A);
    cudaGetSymbolAddress((void**)&pCol,  g_col);
    cudaGetSymbolAddress((void**)&pCvA,  g_cvtA);
    cudaGetSymbolAddress((void**)&pCvB,  g_cvtB);
    cudaGetSymbolAddress((void**)&pB1,   g_B1);
    cudaGetSymbolAddress((void**)&pB2,   g_B2);
    cudaGetSymbolAddress((void**)&pT,    g_T);
    cudaGetSymbolAddress((void**)&pN,    g_norme);
    cudaGetSymbolAddress((void**)&pE,    g_embT);
    cudaGetSymbolAddress((void**)&pWdt2, g_wdt2);
    cudaGetSymbolAddress((void**)&pW1p,  g_w1p);
    cudaGetSymbolAddress((void**)&pWT,   g_wtens);
    cudaGetSymbolAddress((void**)&pWB,   g_wbf);

    float* yout = (float*)d_out;
    float* fout = yout + Y_SZ;
    float* qout = fout + F_SZ;
    __nv_bfloat16* cv3A = (__nv_bfloat16*)pCvA;
    __nv_bfloat16* cv3B = (__nv_bfloat16*)pCvB;

    // tf32 conv smem: stage = 2*AF + 2*BF floats; AF = 4224
    const int SMT64 = (2 * 4224 + 2 * (16 * 68 * 2)) * 2 * 4;   // 102400 (OCW=64, 2 CTA/SM)
    const int SMT32 = (2 * 4224 + 2 * (16 * 36 * 2)) * 2 * 4;   // 86016  (OCW=32, 2 CTA/SM)
    const int SB128 = (128 + 128) * 13 * 16 * 2;  // 106496
    const int SB64  = (128 + 64)  * 13 * 16 * 2;  // 79872
    const int SB32  = (128 + 32)  * 13 * 16 * 2;  // 66560
    cudaFuncSetAttribute(
        conv_mma<4, 4, 2, 1, 128, 64, 128, 64, 3, true, true, false, true, false>,
        cudaFuncAttributeMaxDynamicSharedMemorySize, SMT64);
    cudaFuncSetAttribute(
        conv_mma<3, 3, 1, 1, 64, 128, 128, 64, 3, true, false, true, true, true>,
        cudaFuncAttributeMaxDynamicSharedMemorySize, SMT64);
    cudaFuncSetAttribute(
        conv_mma<3, 3, 1, 1, 64, 128, 32, 32, 3, false, false, true, false, false>,
        cudaFuncAttributeMaxDynamicSharedMemorySize, SMT32);
    cudaFuncSetAttribute(
        conv_bf16<0, 3, 3, 64, 128, 128, true, false, true, true, true>,
        cudaFuncAttributeMaxDynamicSharedMemorySize, SB128);
    cudaFuncSetAttribute(
        conv_bf16<0, 3, 3, 64, 128, 32, false, false, true, false, false>,
        cudaFuncAttributeMaxDynamicSharedMemorySize, SB32);
    cudaFuncSetAttribute(
        conv_bf16<1, 4, 4, 64, 128, 64, true, true, true, false, false>,
        cudaFuncAttributeMaxDynamicSharedMemorySize, SB64);

    // prep + enc1
    im2col_enc1<<<65536, 256>>>(x, pCol);
    pad_w1<<<16, 256>>>(enc_w1, pW1p);
    prep_w_tf32<16, 64, 128, 64><<<512, 256>>>(enc_w2, pWT + WP_ENC2);
    flat_gemm_cvt<64, 64, 128, 8, 4, true><<<2048, 256>>>(pCol, pW1p, enc_b1, pCvA);
    prep_w_tf32<9, 128, 128, 64><<<576, 256>>>(enc_w3, pWT + WP_ENC3);
    prep_w_tf32<9, 128, 32, 32><<<144, 256>>>(erb1_w1, pWT + WP_ERB1);
    prep_w_tf32<9, 128, 32, 32><<<144, 256>>>(erb2_w1, pWT + WP_ERB2);
    prep_w_bf16<9, 128, 128><<<576, 256>>>(dec_w, pWB + WB_DEC);
    prep_w_bf16<9, 128, 32><<<144, 256>>>(drb1_w1, pWB + WB_DRB1);
    prep_w_bf16<9, 128, 32><<<144, 256>>>(drb2_w1, pWB + WB_DRB2);
    prep_w_bf16<16, 128, 64><<<512, 256>>>(dt1_w, pWB + WB_DT1);
    transpose_w<<<12, 256>>>(dt2_w, pWdt2, 16, 64, 3);
    norme_kernel<<<2, 256>>>(emb, pN);
    embT_kernel<<<64, 256>>>(emb, pE);

    // Encoder (tf32 3-pass, N-split -> 2 CTAs/SM)
    conv_mma<4, 4, 2, 1, 128, 64, 128, 64, 3, true, true, false, true, false>
        <<<dim3(512, 2), 256, SMT64>>>(pCvA, pWT + WP_ENC2, enc_b2, pB1, pCvB);
    conv_mma<3, 3, 1, 1, 64, 128, 128, 64, 3, true, false, true, true, true>
        <<<dim3(512, 2), 256, SMT64>>>(pCvB, pWT + WP_ENC3, enc_b3, pB2, pCvA);
    conv_mma<3, 3, 1, 1, 64, 128, 32, 32, 3, false, false, true, false, false>
        <<<512, 256, SMT32>>>(pCvA, pWT + WP_ERB1, nullptr, pT, nullptr);
    conv1x1_res<false, true, 1, true><<<8192, 256>>>(pT, pB2, erb1_w2, pB1, pCvB, nullptr);
    conv_mma<3, 3, 1, 1, 64, 128, 32, 32, 3, false, false, true, false, false>
        <<<512, 256, SMT32>>>(pCvB, pWT + WP_ERB2, nullptr, pT, nullptr);
    conv1x1_res<true, true, 0, false><<<8192, 256>>>(pT, pB1, erb2_w2, fout, nullptr, nullptr);

    // VQ (q + bf16 triple cvt)
    vq16<<<4096, 128>>>(fout, pE, emb, pN, qout, cv3A);

    // Decoder (bf16 triple-channel)
    conv_bf16<0, 3, 3, 64, 128, 128, true, false, true, true, true>
        <<<512, 256, SB128>>>(cv3A, pWB + WB_DEC, dec_b, pB1, cv3B);
    conv_bf16<0, 3, 3, 64, 128, 32, false, false, true, false, false>
        <<<512, 256, SB32>>>(cv3B, pWB + WB_DRB1, nullptr, pT, nullptr);
    conv1x1_res<false, true, 2, true><<<8192, 256>>>(pT, pB1, drb1_w2, pB2, nullptr, cv3A);
    conv_bf16<0, 3, 3, 64, 128, 32, false, false, true, false, false>
        <<<512, 256, SB32>>>(cv3A, pWB + WB_DRB2, nullptr, pT, nullptr);
    conv1x1_res<true, false, 2, false><<<8192, 256>>>(pT, pB2, drb2_w2, nullptr, nullptr, cv3B);
    conv_bf16<1, 4, 4, 64, 128, 64, true, true, true, false, false>
        <<<dim3(512, 4), 256, SB64>>>(cv3B, pWB + WB_DT1, dt1_b, pA, nullptr);
    dt2_kernel<<<4096, 256>>>(pA, pWdt2, dt2_b, yout);
}

// round 15
// speedup vs baseline: 1.2984x; 1.0528x over previous
#include <cuda_runtime.h>
#include <cuda_fp16.h>
#include <cstdint>

#define Y_SZ  (16*256*256*3)
#define F_SZ  (16*64*64*128)

__device__ __align__(16) float g_A[16*128*128*64];    // enc1 out / dt1 out
__device__ __align__(16) float g_col[16*128*128*64];  // enc1 im2col
__device__ __align__(16) float g_cvtA[16*128*128*64*2];
__device__ __align__(16) float g_cvtB[16*64*64*256];
__device__ __align__(16) float g_B1[16*64*64*128];
__device__ __align__(16) float g_B2[16*64*64*128];
__device__ __align__(16) float g_T[16*64*64*32];
__device__ __align__(16) float g_norme[512];
__device__ __align__(16) float g_embT[512*128];
__device__ __align__(16) float g_wdt2[16*3*64];
__device__ __align__(16) float g_w1p[64*64];
__device__ __align__(16) __half g_wh[2200*1024];      // fp16 triple weights (all convs)

// fp16 weight offsets (elements = TAPS*IC*OC*3)
#define WH_ENC2 0
#define WH_ENC3 393216
#define WH_ERB1 835584
#define WH_ERB2 946176
#define WH_DEC  1056768
#define WH_DRB1 1499136
#define WH_DRB2 1609728
#define WH_DT1  1720320

__device__ __forceinline__ float4 relu4(float4 a) {
    a.x = fmaxf(a.x, 0.f); a.y = fmaxf(a.y, 0.f);
    a.z = fmaxf(a.z, 0.f); a.w = fmaxf(a.w, 0.f);
    return a;
}
__device__ __forceinline__ float dot4(float4 a, float4 b) {
    return fmaf(a.x, b.x, fmaf(a.y, b.y, fmaf(a.z, b.z, a.w * b.w)));
}
__device__ __forceinline__ unsigned long long pk2(float x, float y) {
    unsigned long long r;
    asm("mov.b64 %0, {%1, %2};" : "=l"(r)
        : "r"(__float_as_uint(x)), "r"(__float_as_uint(y)));
    return r;
}
__device__ __forceinline__ float2 up2(unsigned long long v) {
    unsigned int lo, hi;
    asm("mov.b64 {%0, %1}, %2;" : "=r"(lo), "=r"(hi) : "l"(v));
    return make_float2(__uint_as_float(lo), __uint_as_float(hi));
}
__device__ __forceinline__ void fma2(unsigned long long& d,
                                     unsigned long long a, unsigned long long b) {
    asm("fma.rn.f32x2 %0, %1, %2, %0;" : "+l"(d) : "l"(a), "l"(b));
}
__device__ __forceinline__ void mma16h(float* c, const uint32_t* a, const uint32_t* b) {
    asm volatile(
        "mma.sync.aligned.m16n8k16.row.col.f32.f16.f16.f32 "
        "{%0,%1,%2,%3},{%4,%5,%6,%7},{%8,%9},{%0,%1,%2,%3};"
        : "+f"(c[0]), "+f"(c[1]), "+f"(c[2]), "+f"(c[3])
        : "r"(a[0]), "r"(a[1]), "r"(a[2]), "r"(a[3]), "r"(b[0]), "r"(b[1]));
}
__device__ __forceinline__ void ldmx4(uint32_t* r, uint32_t addr) {
    asm volatile("ldmatrix.sync.aligned.m8n8.x4.shared.b16 {%0,%1,%2,%3}, [%4];"
        : "=r"(r[0]), "=r"(r[1]), "=r"(r[2]), "=r"(r[3]) : "r"(addr));
}
__device__ __forceinline__ uint32_t smem_u32(const void* p) {
    uint32_t a;
    asm("{ .reg .u64 t; cvta.to.shared.u64 t, %1; cvt.u32.u64 %0, t; }"
        : "=r"(a) : "l"(p));
    return a;
}
__device__ __forceinline__ void cpasync16(uint32_t dst, const void* src) {
    asm volatile("cp.async.cg.shared.global [%0], [%1], 16;" :: "r"(dst), "l"(src));
}
__device__ __forceinline__ void cpasync16z(uint32_t dst, const void* src, int sz) {
    asm volatile("cp.async.cg.shared.global [%0], [%1], 16, %2;"
                 :: "r"(dst), "l"(src), "r"(sz));
}
__device__ __forceinline__ void cpasync_commit() {
    asm volatile("cp.async.commit_group;" ::: "memory");
}
__device__ __forceinline__ void cpasync_wait0() {
    asm volatile("cp.async.wait_group 0;" ::: "memory");
}
// write fp16 triple [h1, h2, h1]  (h1+h2 captures ~22 mantissa bits)
__device__ __forceinline__ void wr3h(__half* dst, float v) {
    __half h1 = __float2half_rn(v);
    float r = v - __half2float(h1);
    dst[0] = h1;
    dst[1] = __float2half_rn(r);
    dst[2] = h1;
}

// ---- fp16 weight prep: [tap][ic][oc] -> [tap][kc][oc][96], triple [g1,g1,g2] ----
template<int TAPS, int IC, int OC>
__global__ void prep_w_half(const float* __restrict__ w, __half* __restrict__ out) {
    constexpr int KC = IC / 32;
    int t = blockIdx.x * 256 + threadIdx.x;
    if (t >= TAPS * IC * OC) return;
    int oc = t % OC;
    int r = t / OC;
    int ic = r % IC;
    int tap = r / IC;
    int kc = ic >> 5, lk = ic & 31;
    float v = w[t];
    __half g1 = __float2half_rn(v);
    float rr = v - __half2float(g1);
    __half g2 = __float2half_rn(rr);
    long base = (((long)(tap * KC + kc)) * OC + oc) * 96 + 3 * lk;
    out[base] = g1;
    out[base + 1] = g1;
    out[base + 2] = g2;
}

// ================= fp16 triple-channel mma conv (ALL conv layers) =================
// cv3: [p][KC][96 half] activations ([h1,h2,h1]); wp3: [tap][kc][oc][96] ([g1,g1,g2]).
// MODE 0: conv KHxKW stride/pad, output on 64x64 grid (65536 px).
// MODE 1: dt1 deconv parity class (blockIdx.y), output scatter to 128x128.
template<int MODE, int KH, int KW, int STRIDE, int PAD, int IH, int IC, int OC,
         bool HAS_BIAS, bool RELU_OUT, bool WRITE_OUT, bool WRITE_CVT3, bool CVT_RELU>
__global__ void __launch_bounds__(256, 2) conv_h(
    const __half* __restrict__ cv3, const __half* __restrict__ wp3,
    const float* __restrict__ bias, float* __restrict__ out,
    __half* __restrict__ cvt_out)
{
    constexpr int KC = IC / 32;
    constexpr int NTAPS = (MODE == 0) ? KH * KW : 4;
    constexpr int SE = (MODE == 0) ? STRIDE : 1;
    constexpr int AU = 128 * 13;             // A 16B-units (208B rows)
    constexpr int BU = OC * 13;
    constexpr int SU = AU + BU;
    constexpr int NT = OC / 16;
    constexpr int TOTAL = NTAPS * KC;

    extern __shared__ __align__(16) char smb[];
    uint32_t sbase = smem_u32(smb);

    int tid = threadIdx.x;
    int lane = tid & 31;
    int g = lane >> 2, t4 = lane & 3;
    int wid = tid >> 5;
    int wm = wid >> 1, wn = wid & 1;
    int m0 = blockIdx.x * 128;
    int po = 0, pw_ = 0;
    if (MODE == 1) { po = blockIdx.y >> 1; pw_ = blockIdx.y & 1; }

    float acc[2][NT][4];
#pragma unroll
    for (int i = 0; i < 2; i++)
#pragma unroll
        for (int j = 0; j < NT; j++)
#pragma unroll
            for (int u = 0; u < 4; u++) acc[i][j][u] = 0.f;

    auto tapgeom = [&](int it, int& hoff, int& woff, int& wtap, int& kc) {
        int tap = it / KC; kc = it % KC;
        if (MODE == 0) {
            int kh = tap / KW, kw = tap % KW;
            hoff = kh - PAD; woff = kw - PAD; wtap = tap;
        } else {
            int dh = tap >> 1, dw = tap & 1;
            hoff = po + dh - 1; woff = pw_ + dw - 1;
            wtap = (po + 2 * dh) * 4 + (pw_ + 2 * dw);
        }
    };
    auto copyA = [&](int it, int s) {
        int hoff, woff, wtap, kc;
        tapgeom(it, hoff, woff, wtap, kc);
        uint32_t dst0 = sbase + s * SU * 16;
#pragma unroll
        for (int i = 0; i < 6; i++) {
            int idx = tid + i * 256;
            int m = idx / 12, c = idx % 12;
            int p = m0 + m;
            int n_img = p >> 12, oh = (p >> 6) & 63, ow = p & 63;
            int ih = oh * SE + hoff, iw = ow * SE + woff;
            bool valid = (unsigned)ih < (unsigned)IH && (unsigned)iw < (unsigned)IH;
            long P = valid ? (((long)n_img * IH + ih) * IH + iw) : 0;
            const char* src = (const char*)cv3 + (P * KC + kc) * 192 + c * 16;
            cpasync16z(dst0 + (m * 13 + c) * 16, src, valid ? 16 : 0);
        }
    };
    auto copyB = [&](int it, int s) {
        int hoff, woff, wtap, kc;
        tapgeom(it, hoff, woff, wtap, kc);
        const char* src0 = (const char*)(wp3 + ((long)(wtap * KC + kc) * OC) * 96);
        uint32_t dst0 = sbase + s * SU * 16 + AU * 16;
        constexpr int NCH = OC * 12;
#pragma unroll
        for (int i = 0; i < (NCH + 255) / 256; i++) {
            int idx = tid + i * 256;
            if (idx < NCH) {
                int row = idx / 12, c = idx % 12;
                cpasync16(dst0 + (row * 13 + c) * 16, src0 + idx * 16);
            }
        }
    };
    int l7 = lane & 7, q = lane >> 3;
    uint32_t arow = ((q & 1) ? 8 : 0) + l7;
    uint32_t acol = (q >> 1) * 16;
    uint32_t brow = ((q >> 1) ? 8 : 0) + l7;
    uint32_t bcol = (q & 1) * 16;
    auto do_mma = [&](int s) {
        uint32_t Ab = sbase + s * SU * 16;
        uint32_t Bb = Ab + AU * 16;
#pragma unroll
        for (int ks = 0; ks < 6; ks++) {
            uint32_t a[2][4];
#pragma unroll
            for (int mt = 0; mt < 2; mt++)
                ldmx4(a[mt], Ab + (wm * 32 + mt * 16 + arow) * 208 + ks * 32 + acol);
            uint32_t b[NT][2];
#pragma unroll
            for (int np = 0; np < NT / 2; np++) {
                uint32_t n0 = wn * (OC / 2) + np * 16;
                uint32_t r[4];
                ldmx4(r, Bb + (n0 + brow) * 208 + ks * 32 + bcol);
                b[2 * np][0] = r[0]; b[2 * np][1] = r[1];
                b[2 * np + 1][0] = r[2]; b[2 * np + 1][1] = r[3];
            }
#pragma unroll
            for (int nt = 0; nt < NT; nt++)
#pragma unroll
                for (int mt = 0; mt < 2; mt++) mma16h(acc[mt][nt], a[mt], b[nt]);
        }
    };

    copyA(0, 0); copyB(0, 0); cpasync_commit();
    cpasync_wait0();
    __syncthreads();
    for (int it = 0; it < TOTAL; it++) {
        int cur = it & 1, nxt = cur ^ 1;
        if (it + 1 < TOTAL) {
            copyA(it + 1, nxt);
            copyB(it + 1, nxt);
            cpasync_commit();
        }
        do_mma(cur);
        cpasync_wait0();
        __syncthreads();
    }

    // ---- epilogue
#pragma unroll
    for (int mt = 0; mt < 2; mt++) {
        int r0 = m0 + wm * 32 + mt * 16 + g;
        int r1 = r0 + 8;
        long o0, o1;
        if (MODE == 0) {
            o0 = (long)r0 * OC;
            o1 = (long)r1 * OC;
        } else {
            int n0 = r0 >> 12, a0 = (r0 >> 6) & 63, b0 = r0 & 63;
            int n1 = r1 >> 12, a1 = (r1 >> 6) & 63, b1 = r1 & 63;
            o0 = (((long)n0 * 128 + 2 * a0 + po) * 128 + 2 * b0 + pw_) * OC;
            o1 = (((long)n1 * 128 + 2 * a1 + po) * 128 + 2 * b1 + pw_) * OC;
        }
#pragma unroll
        for (int nt = 0; nt < NT; nt++) {
            int nb = wn * (OC / 2) + nt * 8 + 2 * t4;
            float b0v = HAS_BIAS ? bias[nb] : 0.f;
            float b1v = HAS_BIAS ? bias[nb + 1] : 0.f;
            float2 v0 = make_float2(acc[mt][nt][0] + b0v, acc[mt][nt][1] + b1v);
            float2 v1 = make_float2(acc[mt][nt][2] + b0v, acc[mt][nt][3] + b1v);
            if (RELU_OUT) {
                v0.x = fmaxf(v0.x, 0.f); v0.y = fmaxf(v0.y, 0.f);
                v1.x = fmaxf(v1.x, 0.f); v1.y = fmaxf(v1.y, 0.f);
            }
            if (WRITE_OUT) {
                *(float2*)(out + o0 + nb) = v0;
                *(float2*)(out + o1 + nb) = v1;
            }
            if (WRITE_CVT3) {
                constexpr int KC2 = OC / 32;
                float c0x = CVT_RELU ? fmaxf(v0.x, 0.f) : v0.x;
                float c0y = CVT_RELU ? fmaxf(v0.y, 0.f) : v0.y;
                float c1x = CVT_RELU ? fmaxf(v1.x, 0.f) : v1.x;
                float c1y = CVT_RELU ? fmaxf(v1.y, 0.f) : v1.y;
                long cb0 = ((long)r0 * KC2 + (nb >> 5)) * 96 + 3 * (nb & 31);
                long cb1 = ((long)r1 * KC2 + (nb >> 5)) * 96 + 3 * (nb & 31);
                wr3h(cvt_out + cb0, c0x);
                wr3h(cvt_out + cb0 + 3, c0y);
                wr3h(cvt_out + cb1, c1x);
                wr3h(cvt_out + cb1 + 3, c1y);
            }
        }
    }
}

// ---------------- small kernels ----------------
__global__ void transpose_w(const float* __restrict__ in, float* __restrict__ out,
                            int K, int IC, int OC) {
    int i = blockIdx.x * blockDim.x + threadIdx.x;
    int total = K * IC * OC;
    if (i >= total) return;
    int oc = i % OC;
    int ic = (i / OC) % IC;
    int k  = i / (OC * IC);
    out[(k * OC + oc) * IC + ic] = in[i];
}

__global__ void norme_kernel(const float* __restrict__ emb, float* __restrict__ norme) {
    int k = blockIdx.x * blockDim.x + threadIdx.x;
    if (k >= 512) return;
    const float4* e = (const float4*)(emb + k * 128);
    float s = 0.f;
#pragma unroll 8
    for (int i = 0; i < 32; i++) {
        float4 v = e[i];
        s = fmaf(v.x, v.x, s); s = fmaf(v.y, v.y, s);
        s = fmaf(v.z, v.z, s); s = fmaf(v.w, v.w, s);
    }
    norme[k] = s;
}

__global__ void embT_kernel(const float* __restrict__ emb, float* __restrict__ embT) {
    int i = blockIdx.x * 256 + threadIdx.x;
    if (i >= 512 * 32) return;
    int c = i & 511, d4 = i >> 9;
    float4 v = *(const float4*)(emb + c * 128 + 4 * d4);
    *(float4*)(embT + (d4 * 512 + c) * 4) = v;
}

__global__ void pad_w1(const float* __restrict__ w, float* __restrict__ out) {
    int t = blockIdx.x * 256 + threadIdx.x;
    if (t >= 64 * 64) return;
    int r = t >> 6;
    out[t] = (r < 48) ? w[t] : 0.f;
}

__global__ void im2col_enc1(const float* __restrict__ x, float* __restrict__ col) {
    int t = blockIdx.x * 256 + threadIdx.x;
    int kidx = t & 63;
    int p = t >> 6;
    int ow = p & 127, oh = (p >> 7) & 127, n = p >> 14;
    float v = 0.f;
    if (kidx < 48) {
        int ic = kidx % 3;
        int kw = (kidx / 3) & 3;
        int kh = kidx / 12;
        int ih = 2 * oh - 1 + kh, iw = 2 * ow - 1 + kw;
        if ((unsigned)ih < 256u && (unsigned)iw < 256u)
            v = x[((n * 256 + ih) * 256 + iw) * 3 + ic];
    }
    col[t] = v;
}

// enc1 flat GEMM (f32x2); writes fp16-triple cvt (consumer = enc2 conv_h)
template<int IC, int OC, int BM, int TM, int TN, bool HAS_BIAS>
__global__ void __launch_bounds__(256, 2) flat_gemm_cvt(
    const float* __restrict__ in, const float* __restrict__ w,
    const float* __restrict__ bias, __half* __restrict__ cvt)
{
    constexpr int BK = 32;
    constexpr int BN = OC;
    constexpr int TX = BN / TN;
    constexpr int ASTR = BM + 2;
    constexpr int KCO = OC / 32;
    __shared__ __align__(16) float As[BK * ASTR];
    __shared__ __align__(16) float Bs[BK * BN];
    int tid = threadIdx.x;
    int m0 = blockIdx.x * BM;
    int tx = tid % TX, ty = tid / TX;
    int c4 = tid & 7;
    int mp = tid >> 3;
    unsigned long long acc2[TM / 2][TN];
#pragma unroll
    for (int i = 0; i < TM / 2; i++)
#pragma unroll
        for (int j = 0; j < TN; j++) acc2[i][j] = 0ull;

    for (int kc = 0; kc < IC / BK; kc++) {
        __syncthreads();
#pragma unroll
        for (int pass = 0; pass < BM / 32; pass++) {
            int m = mp + pass * 32;
            int p = m0 + m;
            float4 v = *(const float4*)(in + (long)p * IC + kc * BK + 4 * c4);
            int kk = 4 * c4;
            As[(kk + 0) * ASTR + m] = v.x;
            As[(kk + 1) * ASTR + m] = v.y;
            As[(kk + 2) * ASTR + m] = v.z;
            As[(kk + 3) * ASTR + m] = v.w;
        }
        {
            const float* wb = w + kc * BK * OC;
#pragma unroll
            for (int i = 0; i < (BK * BN / 4) / 256; i++) {
                int idx = tid + i * 256;
                int kr = idx / (BN / 4);
                int n4 = idx % (BN / 4);
                *(float4*)(Bs + kr * BN + 4 * n4) = *(const float4*)(wb + kr * OC + 4 * n4);
            }
        }
        __syncthreads();
#pragma unroll 8
        for (int k = 0; k < BK; k++) {
            unsigned long long a2[TM / 2], b2[TN];
            const double* ap = (const double*)(As + k * ASTR + ty * TM);
#pragma unroll
            for (int i = 0; i < TM / 2; i++) a2[i] = __double_as_longlong(ap[i]);
            float b[TN];
#pragma unroll
            for (int j = 0; j < TN / 4; j++)
                *(float4*)(b + 4 * j) = *(const float4*)(Bs + k * BN + tx * TN + 4 * j);
#pragma unroll
            for (int j = 0; j < TN; j++) b2[j] = pk2(b[j], b[j]);
#pragma unroll
            for (int i = 0; i < TM / 2; i++)
#pragma unroll
                for (int j = 0; j < TN; j++) fma2(acc2[i][j], a2[i], b2[j]);
        }
    }
    float bv[TN];
#pragma unroll
    for (int j = 0; j < TN; j++) bv[j] = HAS_BIAS ? bias[tx * TN + j] : 0.f;
    int base_m = m0 + ty * TM;
    int col0 = tx * TN;
    int kcq = col0 >> 5, off = col0 & 31;
#pragma unroll
    for (int i2 = 0; i2 < TM / 2; i2++) {
        float2 tv[TN];
#pragma unroll
        for (int j = 0; j < TN; j++) tv[j] = up2(acc2[i2][j]);
#pragma unroll
        for (int hh = 0; hh < 2; hh++) {
            int p = base_m + 2 * i2 + hh;
            long base = ((long)p * KCO + kcq) * 96 + 3 * off;
#pragma unroll
            for (int j = 0; j < TN; j++) {
                float v = fmaxf((hh ? tv[j].y : tv[j].x) + bv[j], 0.f);
                wr3h(cvt + base + 3 * j, v);
            }
        }
    }
}

// 1x1 conv (relu in) + residual; CVTM: 0 none, 2 fp16 triple
template<bool RELU_OUT, bool WRITE_OUT, int CVTM, bool CVT_RELU>
__global__ void conv1x1_res(const float* __restrict__ tin, const float* __restrict__ res,
                            const float* __restrict__ w, float* __restrict__ out,
                            __half* __restrict__ cvt3) {
    int t = blockIdx.x * 256 + threadIdx.x;
    int oc = t & 127;
    long p0 = (long)(t >> 7) * 4;
    float wv[32];
#pragma unroll
    for (int ic = 0; ic < 32; ic++) wv[ic] = w[ic * 128 + oc];
    float accp[4] = {0.f, 0.f, 0.f, 0.f};
#pragma unroll
    for (int ic4 = 0; ic4 < 8; ic4++) {
#pragma unroll
        for (int p = 0; p < 4; p++) {
            float4 tv = *(const float4*)(tin + (p0 + p) * 32 + 4 * ic4);
            tv = relu4(tv);
            accp[p] = fmaf(tv.x, wv[4 * ic4],     accp[p]);
            accp[p] = fmaf(tv.y, wv[4 * ic4 + 1], accp[p]);
            accp[p] = fmaf(tv.z, wv[4 * ic4 + 2], accp[p]);
            accp[p] = fmaf(tv.w, wv[4 * ic4 + 3], accp[p]);
        }
    }
    long o = p0 * 128 + oc;
    int kcq = oc >> 5, off = oc & 31;
#pragma unroll
    for (int p = 0; p < 4; p++) {
        float v = res[o + p * 128] + accp[p];
        if (RELU_OUT) v = fmaxf(v, 0.f);
        if (WRITE_OUT) out[o + p * 128] = v;
        if (CVTM == 2) {
            float cvv = CVT_RELU ? fmaxf(v, 0.f) : v;
            long base = ((p0 + p) * 4 + kcq) * 96 + 3 * off;
            wr3h(cvt3 + base, cvv);
        }
    }
}

// VQ: writes q (fp32) + fp16-triple cvt for the decoder conv
__global__ void __launch_bounds__(128) vq16(const float* __restrict__ f,
                                            const float* __restrict__ embT,
                                            const float* __restrict__ emb,
                                            const float* __restrict__ norme,
                                            float* __restrict__ q,
                                            __half* __restrict__ qcvt3) {
    __shared__ float4 xs4[16 * 32];
    __shared__ float rdist[16 * 128];
    __shared__ int   ridx[16 * 128];
    __shared__ int   best[16];
    int tid = threadIdx.x;
    long pixel0 = (long)blockIdx.x * 16;
    const float4* fin = (const float4*)(f + pixel0 * 128);
#pragma unroll
    for (int i = 0; i < 4; i++) xs4[tid + 128 * i] = fin[tid + 128 * i];
    __syncthreads();

    unsigned long long acc2[4][8];
#pragma unroll
    for (int j = 0; j < 4; j++)
#pragma unroll
        for (int p2 = 0; p2 < 8; p2++) acc2[j][p2] = 0ull;

    const float4* eT = (const float4*)embT;
    for (int d4 = 0; d4 < 32; d4++) {
        float4 ev[4];
#pragma unroll
        for (int j = 0; j < 4; j++) ev[j] = eT[d4 * 512 + 128 * j + tid];
        unsigned long long e2[4][4];
#pragma unroll
        for (int j = 0; j < 4; j++) {
            e2[j][0] = pk2(ev[j].x, ev[j].x);
            e2[j][1] = pk2(ev[j].y, ev[j].y);
            e2[j][2] = pk2(ev[j].z, ev[j].z);
            e2[j][3] = pk2(ev[j].w, ev[j].w);
        }
#pragma unroll
        for (int p2 = 0; p2 < 8; p2++) {
            float4 xa = xs4[(2 * p2) * 32 + d4];
            float4 xb = xs4[(2 * p2 + 1) * 32 + d4];
            unsigned long long xp0 = pk2(xa.x, xb.x);
            unsigned long long xp1 = pk2(xa.y, xb.y);
            unsigned long long xp2 = pk2(xa.z, xb.z);
            unsigned long long xp3 = pk2(xa.w, xb.w);
#pragma unroll
            for (int j = 0; j < 4; j++) {
                fma2(acc2[j][p2], xp0, e2[j][0]);
                fma2(acc2[j][p2], xp1, e2[j][1]);
                fma2(acc2[j][p2], xp2, e2[j][2]);
                fma2(acc2[j][p2], xp3, e2[j][3]);
            }
        }
    }
    float accs[4][16];
#pragma unroll
    for (int j = 0; j < 4; j++)
#pragma unroll
        for (int p2 = 0; p2 < 8; p2++) {
            float2 u = up2(acc2[j][p2]);
            accs[j][2 * p2] = u.x;
            accs[j][2 * p2 + 1] = u.y;
        }
    float nd[4];
#pragma unroll
    for (int j = 0; j < 4; j++) nd[j] = norme[tid + 128 * j];
#pragma unroll
    for (int p = 0; p < 16; p++) {
        float bd = 1e30f; int bi = 0;
#pragma unroll
        for (int j = 0; j < 4; j++) {
            float d = nd[j] - 2.f * accs[j][p];
            if (d < bd) { bd = d; bi = tid + 128 * j; }
        }
        rdist[p * 128 + tid] = bd;
        ridx[p * 128 + tid]  = bi;
    }
    __syncthreads();
    if (tid < 16) {
        float bd = 1e30f; int bi = 1 << 30;
        for (int u = 0; u < 128; u++) {
            float d = rdist[tid * 128 + u];
            int   i = ridx[tid * 128 + u];
            if (d < bd || (d == bd && i < bi)) { bd = d; bi = i; }
        }
        best[tid] = bi;
    }
    __syncthreads();
    int kcq = tid >> 5, off = tid & 31;
#pragma unroll
    for (int p = 0; p < 16; p++) {
        float e = emb[best[p] * 128 + tid];
        q[(pixel0 + p) * 128 + tid] = e;
        long base = ((pixel0 + p) * 4 + kcq) * 96 + 3 * off;
        wr3h(qcvt3 + base, e);
    }
}

__global__ void dt2_kernel(const float* __restrict__ in, const float* __restrict__ wt,
                           const float* __restrict__ b, float* __restrict__ out) {
    int t = blockIdx.x * 256 + threadIdx.x;
    int ow = t & 255;
    int oh = (t >> 8) & 255;
    int n  = t >> 16;
    float a0 = b[0], a1 = b[1], a2 = b[2];
#pragma unroll
    for (int dh = 0; dh < 2; dh++) {
        int kh = (oh & 1) + 2 * dh;
        int ih2 = oh + kh - 2;
        if (ih2 < 0 || ih2 >= 256) continue;
        int ih = ih2 >> 1;
#pragma unroll
        for (int dw = 0; dw < 2; dw++) {
            int kw = (ow & 1) + 2 * dw;
            int iw2 = ow + kw - 2;
            if (iw2 < 0 || iw2 >= 256) continue;
            int iw = iw2 >> 1;
            const float4* xp = (const float4*)(in + ((n * 128 + ih) * 128 + iw) * 64);
            const float* wb = wt + (kh * 4 + kw) * 3 * 64;
            const float4* w0 = (const float4*)(wb);
            const float4* w1 = (const float4*)(wb + 64);
            const float4* w2 = (const float4*)(wb + 128);
#pragma unroll 4
            for (int ic4 = 0; ic4 < 16; ic4++) {
                float4 x4 = xp[ic4];
                a0 += dot4(x4, w0[ic4]);
                a1 += dot4(x4, w1[ic4]);
                a2 += dot4(x4, w2[ic4]);
            }
        }
    }
    float* op = out + (long)((n * 256 + oh) * 256 + ow) * 3;
    op[0] = a0; op[1] = a1; op[2] = a2;
}

extern "C" void kernel_launch(void* const* d_in, const int* in_sizes, int n_in,
                              void* d_out, int out_size) {
    const float* x       = (const float*)d_in[0];
    const float* emb     = (const float*)d_in[1];
    const float* enc_w1  = (const float*)d_in[2];
    const float* enc_b1  = (const float*)d_in[3];
    const float* enc_w2  = (const float*)d_in[4];
    const float* enc_b2  = (const float*)d_in[5];
    const float* enc_w3  = (const float*)d_in[6];
    const float* enc_b3  = (const float*)d_in[7];
    const float* erb1_w1 = (const float*)d_in[8];
    const float* erb1_w2 = (const float*)d_in[9];
    const float* erb2_w1 = (const float*)d_in[10];
    const float* erb2_w2 = (const float*)d_in[11];
    const float* dec_w   = (const float*)d_in[12];
    const float* dec_b   = (const float*)d_in[13];
    const float* drb1_w1 = (const float*)d_in[14];
    const float* drb1_w2 = (const float*)d_in[15];
    const float* drb2_w1 = (const float*)d_in[16];
    const float* drb2_w2 = (const float*)d_in[17];
    const float* dt1_w   = (const float*)d_in[18];
    const float* dt1_b   = (const float*)d_in[19];
    const float* dt2_w   = (const float*)d_in[20];
    const float* dt2_b   = (const float*)d_in[21];

    float *pA, *pCol, *pCvA, *pCvB, *pB1, *pB2, *pT, *pN, *pE, *pWdt2, *pW1p;
    __half* pWH;
    cudaGetSymbolAddress((void**)&pA,    g_A);
    cudaGetSymbolAddress((void**)&pCol,  g_col);
    cudaGetSymbolAddress((void**)&pCvA,  g_cvtA);
    cudaGetSymbolAddress((void**)&pCvB,  g_cvtB);
    cudaGetSymbolAddress((void**)&pB1,   g_B1);
    cudaGetSymbolAddress((void**)&pB2,   g_B2);
    cudaGetSymbolAddress((void**)&pT,    g_T);
    cudaGetSymbolAddress((void**)&pN,    g_norme);
    cudaGetSymbolAddress((void**)&pE,    g_embT);
    cudaGetSymbolAddress((void**)&pWdt2, g_wdt2);
    cudaGetSymbolAddress((void**)&pW1p,  g_w1p);
    cudaGetSymbolAddress((void**)&pWH,   g_wh);

    float* yout = (float*)d_out;
    float* fout = yout + Y_SZ;
    float* qout = fout + F_SZ;
    __half* cv3A = (__half*)pCvA;
    __half* cv3B = (__half*)pCvB;

    const int SH128 = (128 + 128) * 13 * 16 * 2;  // 106496
    const int SH64  = (128 + 64)  * 13 * 16 * 2;  // 79872
    const int SH32  = (128 + 32)  * 13 * 16 * 2;  // 66560
    cudaFuncSetAttribute(
        conv_h<0, 4, 4, 2, 1, 128, 64, 128, true, true, false, true, false>,
        cudaFuncAttributeMaxDynamicSharedMemorySize, SH128);
    cudaFuncSetAttribute(
        conv_h<0, 3, 3, 1, 1, 64, 128, 128, true, false, true, true, true>,
        cudaFuncAttributeMaxDynamicSharedMemorySize, SH128);
    cudaFuncSetAttribute(
        conv_h<0, 3, 3, 1, 1, 64, 128, 32, false, false, true, false, false>,
        cudaFuncAttributeMaxDynamicSharedMemorySize, SH32);
    cudaFuncSetAttribute(
        conv_h<1, 4, 4, 1, 0, 64, 128, 64, true, true, true, false, false>,
        cudaFuncAttributeMaxDynamicSharedMemorySize, SH64);

    // prep + enc1
    im2col_enc1<<<65536, 256>>>(x, pCol);
    pad_w1<<<16, 256>>>(enc_w1, pW1p);
    prep_w_half<16, 64, 128><<<512, 256>>>(enc_w2, pWH + WH_ENC2);
    flat_gemm_cvt<64, 64, 128, 8, 4, true><<<2048, 256>>>(pCol, pW1p, enc_b1, cv3A);
    prep_w_half<9, 128, 128><<<576, 256>>>(enc_w3, pWH + WH_ENC3);
    prep_w_half<9, 128, 32><<<144, 256>>>(erb1_w1, pWH + WH_ERB1);
    prep_w_half<9, 128, 32><<<144, 256>>>(erb2_w1, pWH + WH_ERB2);
    prep_w_half<9, 128, 128><<<576, 256>>>(dec_w, pWH + WH_DEC);
    prep_w_half<9, 128, 32><<<144, 256>>>(drb1_w1, pWH + WH_DRB1);
    prep_w_half<9, 128, 32><<<144, 256>>>(drb2_w1, pWH + WH_DRB2);
    prep_w_half<16, 128, 64><<<512, 256>>>(dt1_w, pWH + WH_DT1);
    transpose_w<<<12, 256>>>(dt2_w, pWdt2, 16, 64, 3);
    norme_kernel<<<2, 256>>>(emb, pN);
    embT_kernel<<<64, 256>>>(emb, pE);

    // Encoder (fp16 triple-channel, tf32-equivalent precision)
    conv_h<0, 4, 4, 2, 1, 128, 64, 128, true, true, false, true, false>
        <<<512, 256, SH128>>>(cv3A, pWH + WH_ENC2, enc_b2, nullptr, cv3B);
    conv_h<0, 3, 3, 1, 1, 64, 128, 128, true, false, true, true, true>
        <<<512, 256, SH128>>>(cv3B, pWH + WH_ENC3, enc_b3, pB2, cv3A);
    conv_h<0, 3, 3, 1, 1, 64, 128, 32, false, false, true, false, false>
        <<<512, 256, SH32>>>(cv3A, pWH + WH_ERB1, nullptr, pT, nullptr);
    conv1x1_res<false, true, 2, true><<<8192, 256>>>(pT, pB2, erb1_w2, pB1, cv3B);
    conv_h<0, 3, 3, 1, 1, 64, 128, 32, false, false, true, false, false>
        <<<512, 256, SH32>>>(cv3B, pWH + WH_ERB2, nullptr, pT, nullptr);
    conv1x1_res<true, true, 0, false><<<8192, 256>>>(pT, pB1, erb2_w2, fout, nullptr);

    // VQ (q + fp16 triple cvt)
    vq16<<<4096, 128>>>(fout, pE, emb, pN, qout, cv3A);

    // Decoder (fp16 triple-channel)
    conv_h<0, 3, 3, 1, 1, 64, 128, 128, true, false, true, true, true>
        <<<512, 256, SH128>>>(cv3A, pWH + WH_DEC, dec_b, pB1, cv3B);
    conv_h<0, 3, 3, 1, 1, 64, 128, 32, false, false, true, false, false>
        <<<512, 256, SH32>>>(cv3B, pWH + WH_DRB1, nullptr, pT, nullptr);
    conv1x1_res<false, true, 2, true><<<8192, 256>>>(pT, pB1, drb1_w2, pB2, cv3A);
    conv_h<0, 3, 3, 1, 1, 64, 128, 32, false, false, true, false, false>
        <<<512, 256, SH32>>>(cv3A, pWH + WH_DRB2, nullptr, pT, nullptr);
    conv1x1_res<true, false, 2, false><<<8192, 256>>>(pT, pB2, drb2_w2, nullptr, cv3B);
    conv_h<1, 4, 4, 1, 0, 64, 128, 64, true, true, true, false, false>
        <<<dim3(512, 4), 256, SH64>>>(cv3B, pWH + WH_DT1, dt1_b, pA, nullptr);
    dt2_kernel<<<4096, 256>>>(pA, pWdt2, dt2_b, yout);
}

// round 16
// speedup vs baseline: 1.4407x; 1.1096x over previous
#include <cuda_runtime.h>
#include <cuda_fp16.h>
#include <cstdint>

#define Y_SZ  (16*256*256*3)
#define F_SZ  (16*64*64*128)

__device__ __align__(16) float g_A[16*128*128*64];    // enc1 out / dt1 out
__device__ __align__(16) float g_col[16*128*128*64];  // enc1 im2col
__device__ __align__(16) float g_cvtA[16*128*128*64*2];
__device__ __align__(16) float g_cvtB[16*64*64*256];
__device__ __align__(16) float g_B1[16*64*64*128];
__device__ __align__(16) float g_B2[16*64*64*128];
__device__ __align__(16) float g_T[16*64*64*32];
__device__ __align__(16) float g_norme[512];
__device__ __align__(16) float g_embT[512*128];
__device__ __align__(16) float g_wdt2[16*3*64];
__device__ __align__(16) float g_w1p[64*64];
__device__ __align__(16) __half g_wh[2200*1024];      // fp16 triple weights (all convs)

#define WH_ENC2 0
#define WH_ENC3 393216
#define WH_ERB1 835584
#define WH_ERB2 946176
#define WH_DEC  1056768
#define WH_DRB1 1499136
#define WH_DRB2 1609728
#define WH_DT1  1720320

__device__ __forceinline__ float4 relu4(float4 a) {
    a.x = fmaxf(a.x, 0.f); a.y = fmaxf(a.y, 0.f);
    a.z = fmaxf(a.z, 0.f); a.w = fmaxf(a.w, 0.f);
    return a;
}
__device__ __forceinline__ float dot4(float4 a, float4 b) {
    return fmaf(a.x, b.x, fmaf(a.y, b.y, fmaf(a.z, b.z, a.w * b.w)));
}
__device__ __forceinline__ unsigned long long pk2(float x, float y) {
    unsigned long long r;
    asm("mov.b64 %0, {%1, %2};" : "=l"(r)
        : "r"(__float_as_uint(x)), "r"(__float_as_uint(y)));
    return r;
}
__device__ __forceinline__ float2 up2(unsigned long long v) {
    unsigned int lo, hi;
    asm("mov.b64 {%0, %1}, %2;" : "=r"(lo), "=r"(hi) : "l"(v));
    return make_float2(__uint_as_float(lo), __uint_as_float(hi));
}
__device__ __forceinline__ void fma2(unsigned long long& d,
                                     unsigned long long a, unsigned long long b) {
    asm("fma.rn.f32x2 %0, %1, %2, %0;" : "+l"(d) : "l"(a), "l"(b));
}
__device__ __forceinline__ void mma16h(float* c, const uint32_t* a, const uint32_t* b) {
    asm volatile(
        "mma.sync.aligned.m16n8k16.row.col.f32.f16.f16.f32 "
        "{%0,%1,%2,%3},{%4,%5,%6,%7},{%8,%9},{%0,%1,%2,%3};"
        : "+f"(c[0]), "+f"(c[1]), "+f"(c[2]), "+f"(c[3])
        : "r"(a[0]), "r"(a[1]), "r"(a[2]), "r"(a[3]), "r"(b[0]), "r"(b[1]));
}
__device__ __forceinline__ void ldmx4(uint32_t* r, uint32_t addr) {
    asm volatile("ldmatrix.sync.aligned.m8n8.x4.shared.b16 {%0,%1,%2,%3}, [%4];"
        : "=r"(r[0]), "=r"(r[1]), "=r"(r[2]), "=r"(r[3]) : "r"(addr));
}
__device__ __forceinline__ uint32_t smem_u32(const void* p) {
    uint32_t a;
    asm("{ .reg .u64 t; cvta.to.shared.u64 t, %1; cvt.u32.u64 %0, t; }"
        : "=r"(a) : "l"(p));
    return a;
}
__device__ __forceinline__ void cpasync16(uint32_t dst, const void* src) {
    asm volatile("cp.async.cg.shared.global [%0], [%1], 16;" :: "r"(dst), "l"(src));
}
__device__ __forceinline__ void cpasync16z(uint32_t dst, const void* src, int sz) {
    asm volatile("cp.async.cg.shared.global [%0], [%1], 16, %2;"
                 :: "r"(dst), "l"(src), "r"(sz));
}
__device__ __forceinline__ void cpasync_commit() {
    asm volatile("cp.async.commit_group;" ::: "memory");
}
__device__ __forceinline__ void cpasync_wait0() {
    asm volatile("cp.async.wait_group 0;" ::: "memory");
}
// write fp16 triple [h1, h2, h1] (scalar path; used where stores are thread-contiguous)
__device__ __forceinline__ void wr3h(__half* dst, float v) {
    __half h1 = __float2half_rn(v);
    float r = v - __half2float(h1);
    dst[0] = h1;
    dst[1] = __float2half_rn(r);
    dst[2] = h1;
}
// write two adjacent triples (6 halves) as 3 packed uint32 stores (dst must be 4B-aligned)
__device__ __forceinline__ void wr6h(__half* dst, float a, float b) {
    __half a1 = __float2half_rn(a);
    __half a2 = __float2half_rn(a - __half2float(a1));
    __half b1 = __float2half_rn(b);
    __half b2 = __float2half_rn(b - __half2float(b1));
    uint32_t u0 = (uint32_t)__half_as_ushort(a1) | ((uint32_t)__half_as_ushort(a2) << 16);
    uint32_t u1 = (uint32_t)__half_as_ushort(a1) | ((uint32_t)__half_as_ushort(b1) << 16);
    uint32_t u2 = (uint32_t)__half_as_ushort(b2) | ((uint32_t)__half_as_ushort(b1) << 16);
    uint32_t* d = (uint32_t*)dst;
    d[0] = u0; d[1] = u1; d[2] = u2;
}

// ---- fp16 weight prep: [tap][ic][oc] -> [tap][kc][oc][96], triple [g1,g1,g2] ----
template<int TAPS, int IC, int OC>
__global__ void prep_w_half(const float* __restrict__ w, __half* __restrict__ out) {
    constexpr int KC = IC / 32;
    int t = blockIdx.x * 256 + threadIdx.x;
    if (t >= TAPS * IC * OC) return;
    int oc = t % OC;
    int r = t / OC;
    int ic = r % IC;
    int tap = r / IC;
    int kc = ic >> 5, lk = ic & 31;
    float v = w[t];
    __half g1 = __float2half_rn(v);
    float rr = v - __half2float(g1);
    __half g2 = __float2half_rn(rr);
    long base = (((long)(tap * KC + kc)) * OC + oc) * 96 + 3 * lk;
    out[base] = g1;
    out[base + 1] = g1;
    out[base + 2] = g2;
}

// ---- activation cvt: [p][IC] fp32 -> [p][KC][96] fp16 triple, fully coalesced ----
template<int IC, bool RELU>
__global__ void cvt3_act(const float* __restrict__ in, __half* __restrict__ out, int npx) {
    constexpr int KC = IC / 32;
    int t = blockIdx.x * 256 + threadIdx.x;
    if (t >= npx * KC) return;
    int kc = t % KC;
    long p = t / KC;
    const float4* src = (const float4*)(in + p * IC + kc * 32);
    __align__(16) __half trip[96];
#pragma unroll
    for (int i = 0; i < 8; i++) {
        float4 v = src[i];
        if (RELU) v = relu4(v);
        float vv[4] = {v.x, v.y, v.z, v.w};
#pragma unroll
        for (int j = 0; j < 4; j++) {
            __half h1 = __float2half_rn(vv[j]);
            float r = vv[j] - __half2float(h1);
            trip[3 * (4 * i + j)]     = h1;
            trip[3 * (4 * i + j) + 1] = __float2half_rn(r);
            trip[3 * (4 * i + j) + 2] = h1;
        }
    }
    uint4* dst = (uint4*)(out + (long)t * 96);
    const uint4* s = (const uint4*)trip;
#pragma unroll
    for (int u = 0; u < 12; u++) dst[u] = s[u];
}

// ================= fp16 triple-channel mma conv (ALL conv layers) =================
template<int MODE, int KH, int KW, int STRIDE, int PAD, int IH, int IC, int OC,
         bool HAS_BIAS, bool RELU_OUT, bool WRITE_OUT, bool WRITE_CVT3, bool CVT_RELU>
__global__ void __launch_bounds__(256, 2) conv_h(
    const __half* __restrict__ cv3, const __half* __restrict__ wp3,
    const float* __restrict__ bias, float* __restrict__ out,
    __half* __restrict__ cvt_out)
{
    constexpr int KC = IC / 32;
    constexpr int NTAPS = (MODE == 0) ? KH * KW : 4;
    constexpr int SE = (MODE == 0) ? STRIDE : 1;
    constexpr int AU = 128 * 13;
    constexpr int BU = OC * 13;
    constexpr int SU = AU + BU;
    constexpr int NT = OC / 16;
    constexpr int TOTAL = NTAPS * KC;

    extern __shared__ __align__(16) char smb[];
    uint32_t sbase = smem_u32(smb);

    int tid = threadIdx.x;
    int lane = tid & 31;
    int g = lane >> 2, t4 = lane & 3;
    int wid = tid >> 5;
    int wm = wid >> 1, wn = wid & 1;
    int m0 = blockIdx.x * 128;
    int po = 0, pw_ = 0;
    if (MODE == 1) { po = blockIdx.y >> 1; pw_ = blockIdx.y & 1; }

    float acc[2][NT][4];
#pragma unroll
    for (int i = 0; i < 2; i++)
#pragma unroll
        for (int j = 0; j < NT; j++)
#pragma unroll
            for (int u = 0; u < 4; u++) acc[i][j][u] = 0.f;

    auto tapgeom = [&](int it, int& hoff, int& woff, int& wtap, int& kc) {
        int tap = it / KC; kc = it % KC;
        if (MODE == 0) {
            int kh = tap / KW, kw = tap % KW;
            hoff = kh - PAD; woff = kw - PAD; wtap = tap;
        } else {
            int dh = tap >> 1, dw = tap & 1;
            hoff = po + dh - 1; woff = pw_ + dw - 1;
            wtap = (po + 2 * dh) * 4 + (pw_ + 2 * dw);
        }
    };
    auto copyA = [&](int it, int s) {
        int hoff, woff, wtap, kc;
        tapgeom(it, hoff, woff, wtap, kc);
        uint32_t dst0 = sbase + s * SU * 16;
#pragma unroll
        for (int i = 0; i < 6; i++) {
            int idx = tid + i * 256;
            int m = idx / 12, c = idx % 12;
            int p = m0 + m;
            int n_img = p >> 12, oh = (p >> 6) & 63, ow = p & 63;
            int ih = oh * SE + hoff, iw = ow * SE + woff;
            bool valid = (unsigned)ih < (unsigned)IH && (unsigned)iw < (unsigned)IH;
            long P = valid ? (((long)n_img * IH + ih) * IH + iw) : 0;
            const char* src = (const char*)cv3 + (P * KC + kc) * 192 + c * 16;
            cpasync16z(dst0 + (m * 13 + c) * 16, src, valid ? 16 : 0);
        }
    };
    auto copyB = [&](int it, int s) {
        int hoff, woff, wtap, kc;
        tapgeom(it, hoff, woff, wtap, kc);
        const char* src0 = (const char*)(wp3 + ((long)(wtap * KC + kc) * OC) * 96);
        uint32_t dst0 = sbase + s * SU * 16 + AU * 16;
        constexpr int NCH = OC * 12;
#pragma unroll
        for (int i = 0; i < (NCH + 255) / 256; i++) {
            int idx = tid + i * 256;
            if (idx < NCH) {
                int row = idx / 12, c = idx % 12;
                cpasync16(dst0 + (row * 13 + c) * 16, src0 + idx * 16);
            }
        }
    };
    int l7 = lane & 7, q = lane >> 3;
    uint32_t arow = ((q & 1) ? 8 : 0) + l7;
    uint32_t acol = (q >> 1) * 16;
    uint32_t brow = ((q >> 1) ? 8 : 0) + l7;
    uint32_t bcol = (q & 1) * 16;
    auto do_mma = [&](int s) {
        uint32_t Ab = sbase + s * SU * 16;
        uint32_t Bb = Ab + AU * 16;
#pragma unroll
        for (int ks = 0; ks < 6; ks++) {
            uint32_t a[2][4];
#pragma unroll
            for (int mt = 0; mt < 2; mt++)
                ldmx4(a[mt], Ab + (wm * 32 + mt * 16 + arow) * 208 + ks * 32 + acol);
            uint32_t b[NT][2];
#pragma unroll
            for (int np = 0; np < NT / 2; np++) {
                uint32_t n0 = wn * (OC / 2) + np * 16;
                uint32_t r[4];
                ldmx4(r, Bb + (n0 + brow) * 208 + ks * 32 + bcol);
                b[2 * np][0] = r[0]; b[2 * np][1] = r[1];
                b[2 * np + 1][0] = r[2]; b[2 * np + 1][1] = r[3];
            }
#pragma unroll
            for (int nt = 0; nt < NT; nt++)
#pragma unroll
                for (int mt = 0; mt < 2; mt++) mma16h(acc[mt][nt], a[mt], b[nt]);
        }
    };

    copyA(0, 0); copyB(0, 0); cpasync_commit();
    cpasync_wait0();
    __syncthreads();
    for (int it = 0; it < TOTAL; it++) {
        int cur = it & 1, nxt = cur ^ 1;
        if (it + 1 < TOTAL) {
            copyA(it + 1, nxt);
            copyB(it + 1, nxt);
            cpasync_commit();
        }
        do_mma(cur);
        cpasync_wait0();
        __syncthreads();
    }

    // ---- epilogue
#pragma unroll
    for (int mt = 0; mt < 2; mt++) {
        int r0 = m0 + wm * 32 + mt * 16 + g;
        int r1 = r0 + 8;
        long o0, o1;
        if (MODE == 0) {
            o0 = (long)r0 * OC;
            o1 = (long)r1 * OC;
        } else {
            int n0 = r0 >> 12, a0 = (r0 >> 6) & 63, b0 = r0 & 63;
            int n1 = r1 >> 12, a1 = (r1 >> 6) & 63, b1 = r1 & 63;
            o0 = (((long)n0 * 128 + 2 * a0 + po) * 128 + 2 * b0 + pw_) * OC;
            o1 = (((long)n1 * 128 + 2 * a1 + po) * 128 + 2 * b1 + pw_) * OC;
        }
#pragma unroll
        for (int nt = 0; nt < NT; nt++) {
            int nb = wn * (OC / 2) + nt * 8 + 2 * t4;
            float b0v = HAS_BIAS ? bias[nb] : 0.f;
            float b1v = HAS_BIAS ? bias[nb + 1] : 0.f;
            float2 v0 = make_float2(acc[mt][nt][0] + b0v, acc[mt][nt][1] + b1v);
            float2 v1 = make_float2(acc[mt][nt][2] + b0v, acc[mt][nt][3] + b1v);
            if (RELU_OUT) {
                v0.x = fmaxf(v0.x, 0.f); v0.y = fmaxf(v0.y, 0.f);
                v1.x = fmaxf(v1.x, 0.f); v1.y = fmaxf(v1.y, 0.f);
            }
            if (WRITE_OUT) {
                *(float2*)(out + o0 + nb) = v0;
                *(float2*)(out + o1 + nb) = v1;
            }
            if (WRITE_CVT3) {
                constexpr int KC2 = OC / 32;
                float c0x = CVT_RELU ? fmaxf(v0.x, 0.f) : v0.x;
                float c0y = CVT_RELU ? fmaxf(v0.y, 0.f) : v0.y;
                float c1x = CVT_RELU ? fmaxf(v1.x, 0.f) : v1.x;
                float c1y = CVT_RELU ? fmaxf(v1.y, 0.f) : v1.y;
                long cb0 = ((long)r0 * KC2 + (nb >> 5)) * 96 + 3 * (nb & 31);
                long cb1 = ((long)r1 * KC2 + (nb >> 5)) * 96 + 3 * (nb & 31);
                wr6h(cvt_out + cb0, c0x, c0y);
                wr6h(cvt_out + cb1, c1x, c1y);
            }
        }
    }
}

// ---------------- small kernels ----------------
__global__ void transpose_w(const float* __restrict__ in, float* __restrict__ out,
                            int K, int IC, int OC) {
    int i = blockIdx.x * blockDim.x + threadIdx.x;
    int total = K * IC * OC;
    if (i >= total) return;
    int oc = i % OC;
    int ic = (i / OC) % IC;
    int k  = i / (OC * IC);
    out[(k * OC + oc) * IC + ic] = in[i];
}

__global__ void norme_kernel(const float* __restrict__ emb, float* __restrict__ norme) {
    int k = blockIdx.x * blockDim.x + threadIdx.x;
    if (k >= 512) return;
    const float4* e = (const float4*)(emb + k * 128);
    float s = 0.f;
#pragma unroll 8
    for (int i = 0; i < 32; i++) {
        float4 v = e[i];
        s = fmaf(v.x, v.x, s); s = fmaf(v.y, v.y, s);
        s = fmaf(v.z, v.z, s); s = fmaf(v.w, v.w, s);
    }
    norme[k] = s;
}

__global__ void embT_kernel(const float* __restrict__ emb, float* __restrict__ embT) {
    int i = blockIdx.x * 256 + threadIdx.x;
    if (i >= 512 * 32) return;
    int c = i & 511, d4 = i >> 9;
    float4 v = *(const float4*)(emb + c * 128 + 4 * d4);
    *(float4*)(embT + (d4 * 512 + c) * 4) = v;
}

__global__ void pad_w1(const float* __restrict__ w, float* __restrict__ out) {
    int t = blockIdx.x * 256 + threadIdx.x;
    if (t >= 64 * 64) return;
    int r = t >> 6;
    out[t] = (r < 48) ? w[t] : 0.f;
}

__global__ void im2col_enc1(const float* __restrict__ x, float* __restrict__ col) {
    int t = blockIdx.x * 256 + threadIdx.x;
    int kidx = t & 63;
    int p = t >> 6;
    int ow = p & 127, oh = (p >> 7) & 127, n = p >> 14;
    float v = 0.f;
    if (kidx < 48) {
        int ic = kidx % 3;
        int kw = (kidx / 3) & 3;
        int kh = kidx / 12;
        int ih = 2 * oh - 1 + kh, iw = 2 * ow - 1 + kw;
        if ((unsigned)ih < 256u && (unsigned)iw < 256u)
            v = x[((n * 256 + ih) * 256 + iw) * 3 + ic];
    }
    col[t] = v;
}

// enc1 flat GEMM (f32x2), fp32 output with relu (cvt handled by cvt3_act)
template<int IC, int OC, int BM, int TM, int TN, bool HAS_BIAS, bool RELU_OUT>
__global__ void __launch_bounds__(256, 2) flat_gemm(
    const float* __restrict__ in, const float* __restrict__ w,
    const float* __restrict__ bias, float* __restrict__ out)
{
    constexpr int BK = 32;
    constexpr int BN = OC;
    constexpr int TX = BN / TN;
    constexpr int ASTR = BM + 2;
    __shared__ __align__(16) float As[BK * ASTR];
    __shared__ __align__(16) float Bs[BK * BN];
    int tid = threadIdx.x;
    int m0 = blockIdx.x * BM;
    int tx = tid % TX, ty = tid / TX;
    int c4 = tid & 7;
    int mp = tid >> 3;
    unsigned long long acc2[TM / 2][TN];
#pragma unroll
    for (int i = 0; i < TM / 2; i++)
#pragma unroll
        for (int j = 0; j < TN; j++) acc2[i][j] = 0ull;

    for (int kc = 0; kc < IC / BK; kc++) {
        __syncthreads();
#pragma unroll
        for (int pass = 0; pass < BM / 32; pass++) {
            int m = mp + pass * 32;
            int p = m0 + m;
            float4 v = *(const float4*)(in + (long)p * IC + kc * BK + 4 * c4);
            int kk = 4 * c4;
            As[(kk + 0) * ASTR + m] = v.x;
            As[(kk + 1) * ASTR + m] = v.y;
            As[(kk + 2) * ASTR + m] = v.z;
            As[(kk + 3) * ASTR + m] = v.w;
        }
        {
            const float* wb = w + kc * BK * OC;
#pragma unroll
            for (int i = 0; i < (BK * BN / 4) / 256; i++) {
                int idx = tid + i * 256;
                int kr = idx / (BN / 4);
                int n4 = idx % (BN / 4);
                *(float4*)(Bs + kr * BN + 4 * n4) = *(const float4*)(wb + kr * OC + 4 * n4);
            }
        }
        __syncthreads();
#pragma unroll 8
        for (int k = 0; k < BK; k++) {
            unsigned long long a2[TM / 2], b2[TN];
            const double* ap = (const double*)(As + k * ASTR + ty * TM);
#pragma unroll
            for (int i = 0; i < TM / 2; i++) a2[i] = __double_as_longlong(ap[i]);
            float b[TN];
#pragma unroll
            for (int j = 0; j < TN / 4; j++)
                *(float4*)(b + 4 * j) = *(const float4*)(Bs + k * BN + tx * TN + 4 * j);
#pragma unroll
            for (int j = 0; j < TN; j++) b2[j] = pk2(b[j], b[j]);
#pragma unroll
            for (int i = 0; i < TM / 2; i++)
#pragma unroll
                for (int j = 0; j < TN; j++) fma2(acc2[i][j], a2[i], b2[j]);
        }
    }
    float bv[TN];
#pragma unroll
    for (int j = 0; j < TN; j++) bv[j] = HAS_BIAS ? bias[tx * TN + j] : 0.f;
    int base_m = m0 + ty * TM;
#pragma unroll
    for (int i2 = 0; i2 < TM / 2; i2++) {
        float2 tv[TN];
#pragma unroll
        for (int j = 0; j < TN; j++) tv[j] = up2(acc2[i2][j]);
#pragma unroll
        for (int hh = 0; hh < 2; hh++) {
            int p = base_m + 2 * i2 + hh;
            float v[TN];
#pragma unroll
            for (int j = 0; j < TN; j++) {
                float t = (hh ? tv[j].y : tv[j].x) + bv[j];
                v[j] = RELU_OUT ? fmaxf(t, 0.f) : t;
            }
            long oaddr = (long)p * OC + tx * TN;
#pragma unroll
            for (int j = 0; j < TN / 4; j++)
                *(float4*)(out + oaddr + 4 * j) = *(float4*)(v + 4 * j);
        }
    }
}

// 1x1 conv (relu in) + residual; CVTM: 0 none, 2 fp16 triple
template<bool RELU_OUT, bool WRITE_OUT, int CVTM, bool CVT_RELU>
__global__ void conv1x1_res(const float* __restrict__ tin, const float* __restrict__ res,
                            const float* __restrict__ w, float* __restrict__ out,
                            __half* __restrict__ cvt3) {
    int t = blockIdx.x * 256 + threadIdx.x;
    int oc = t & 127;
    long p0 = (long)(t >> 7) * 4;
    float wv[32];
#pragma unroll
    for (int ic = 0; ic < 32; ic++) wv[ic] = w[ic * 128 + oc];
    float accp[4] = {0.f, 0.f, 0.f, 0.f};
#pragma unroll
    for (int ic4 = 0; ic4 < 8; ic4++) {
#pragma unroll
        for (int p = 0; p < 4; p++) {
            float4 tv = *(const float4*)(tin + (p0 + p) * 32 + 4 * ic4);
            tv = relu4(tv);
            accp[p] = fmaf(tv.x, wv[4 * ic4],     accp[p]);
            accp[p] = fmaf(tv.y, wv[4 * ic4 + 1], accp[p]);
            accp[p] = fmaf(tv.z, wv[4 * ic4 + 2], accp[p]);
            accp[p] = fmaf(tv.w, wv[4 * ic4 + 3], accp[p]);
        }
    }
    long o = p0 * 128 + oc;
    int kcq = oc >> 5, off = oc & 31;
#pragma unroll
    for (int p = 0; p < 4; p++) {
        float v = res[o + p * 128] + accp[p];
        if (RELU_OUT) v = fmaxf(v, 0.f);
        if (WRITE_OUT) out[o + p * 128] = v;
        if (CVTM == 2) {
            float cvv = CVT_RELU ? fmaxf(v, 0.f) : v;
            long base = ((p0 + p) * 4 + kcq) * 96 + 3 * off;
            wr3h(cvt3 + base, cvv);
        }
    }
}

// VQ: writes q (fp32) + fp16-triple cvt for the decoder conv
__global__ void __launch_bounds__(128) vq16(const float* __restrict__ f,
                                            const float* __restrict__ embT,
                                            const float* __restrict__ emb,
                                            const float* __restrict__ norme,
                                            float* __restrict__ q,
                                            __half* __restrict__ qcvt3) {
    __shared__ float4 xs4[16 * 32];
    __shared__ float rdist[16 * 128];
    __shared__ int   ridx[16 * 128];
    __shared__ int   best[16];
    int tid = threadIdx.x;
    long pixel0 = (long)blockIdx.x * 16;
    const float4* fin = (const float4*)(f + pixel0 * 128);
#pragma unroll
    for (int i = 0; i < 4; i++) xs4[tid + 128 * i] = fin[tid + 128 * i];
    __syncthreads();

    unsigned long long acc2[4][8];
#pragma unroll
    for (int j = 0; j < 4; j++)
#pragma unroll
        for (int p2 = 0; p2 < 8; p2++) acc2[j][p2] = 0ull;

    const float4* eT = (const float4*)embT;
    for (int d4 = 0; d4 < 32; d4++) {
        float4 ev[4];
#pragma unroll
        for (int j = 0; j < 4; j++) ev[j] = eT[d4 * 512 + 128 * j + tid];
        unsigned long long e2[4][4];
#pragma unroll
        for (int j = 0; j < 4; j++) {
            e2[j][0] = pk2(ev[j].x, ev[j].x);
            e2[j][1] = pk2(ev[j].y, ev[j].y);
            e2[j][2] = pk2(ev[j].z, ev[j].z);
            e2[j][3] = pk2(ev[j].w, ev[j].w);
        }
#pragma unroll
        for (int p2 = 0; p2 < 8; p2++) {
            float4 xa = xs4[(2 * p2) * 32 + d4];
            float4 xb = xs4[(2 * p2 + 1) * 32 + d4];
            unsigned long long xp0 = pk2(xa.x, xb.x);
            unsigned long long xp1 = pk2(xa.y, xb.y);
            unsigned long long xp2 = pk2(xa.z, xb.z);
            unsigned long long xp3 = pk2(xa.w, xb.w);
#pragma unroll
            for (int j = 0; j < 4; j++) {
                fma2(acc2[j][p2], xp0, e2[j][0]);
                fma2(acc2[j][p2], xp1, e2[j][1]);
                fma2(acc2[j][p2], xp2, e2[j][2]);
                fma2(acc2[j][p2], xp3, e2[j][3]);
            }
        }
    }
    float accs[4][16];
#pragma unroll
    for (int j = 0; j < 4; j++)
#pragma unroll
        for (int p2 = 0; p2 < 8; p2++) {
            float2 u = up2(acc2[j][p2]);
            accs[j][2 * p2] = u.x;
            accs[j][2 * p2 + 1] = u.y;
        }
    float nd[4];
#pragma unroll
    for (int j = 0; j < 4; j++) nd[j] = norme[tid + 128 * j];
#pragma unroll
    for (int p = 0; p < 16; p++) {
        float bd = 1e30f; int bi = 0;
#pragma unroll
        for (int j = 0; j < 4; j++) {
            float d = nd[j] - 2.f * accs[j][p];
            if (d < bd) { bd = d; bi = tid + 128 * j; }
        }
        rdist[p * 128 + tid] = bd;
        ridx[p * 128 + tid]  = bi;
    }
    __syncthreads();
    if (tid < 16) {
        float bd = 1e30f; int bi = 1 << 30;
        for (int u = 0; u < 128; u++) {
            float d = rdist[tid * 128 + u];
            int   i = ridx[tid * 128 + u];
            if (d < bd || (d == bd && i < bi)) { bd = d; bi = i; }
        }
        best[tid] = bi;
    }
    __syncthreads();
    int kcq = tid >> 5, off = tid & 31;
#pragma unroll
    for (int p = 0; p < 16; p++) {
        float e = emb[best[p] * 128 + tid];
        q[(pixel0 + p) * 128 + tid] = e;
        long base = ((pixel0 + p) * 4 + kcq) * 96 + 3 * off;
        wr3h(qcvt3 + base, e);
    }
}

__global__ void dt2_kernel(const float* __restrict__ in, const float* __restrict__ wt,
                           const float* __restrict__ b, float* __restrict__ out) {
    int t = blockIdx.x * 256 + threadIdx.x;
    int ow = t & 255;
    int oh = (t >> 8) & 255;
    int n  = t >> 16;
    float a0 = b[0], a1 = b[1], a2 = b[2];
#pragma unroll
    for (int dh = 0; dh < 2; dh++) {
        int kh = (oh & 1) + 2 * dh;
        int ih2 = oh + kh - 2;
        if (ih2 < 0 || ih2 >= 256) continue;
        int ih = ih2 >> 1;
#pragma unroll
        for (int dw = 0; dw < 2; dw++) {
            int kw = (ow & 1) + 2 * dw;
            int iw2 = ow + kw - 2;
            if (iw2 < 0 || iw2 >= 256) continue;
            int iw = iw2 >> 1;
            const float4* xp = (const float4*)(in + ((n * 128 + ih) * 128 + iw) * 64);
            const float* wb = wt + (kh * 4 + kw) * 3 * 64;
            const float4* w0 = (const float4*)(wb);
            const float4* w1 = (const float4*)(wb + 64);
            const float4* w2 = (const float4*)(wb + 128);
#pragma unroll 4
            for (int ic4 = 0; ic4 < 16; ic4++) {
                float4 x4 = xp[ic4];
                a0 += dot4(x4, w0[ic4]);
                a1 += dot4(x4, w1[ic4]);
                a2 += dot4(x4, w2[ic4]);
            }
        }
    }
    float* op = out + (long)((n * 256 + oh) * 256 + ow) * 3;
    op[0] = a0; op[1] = a1; op[2] = a2;
}

extern "C" void kernel_launch(void* const* d_in, const int* in_sizes, int n_in,
                              void* d_out, int out_size) {
    const float* x       = (const float*)d_in[0];
    const float* emb     = (const float*)d_in[1];
    const float* enc_w1  = (const float*)d_in[2];
    const float* enc_b1  = (const float*)d_in[3];
    const float* enc_w2  = (const float*)d_in[4];
    const float* enc_b2  = (const float*)d_in[5];
    const float* enc_w3  = (const float*)d_in[6];
    const float* enc_b3  = (const float*)d_in[7];
    const float* erb1_w1 = (const float*)d_in[8];
    const float* erb1_w2 = (const float*)d_in[9];
    const float* erb2_w1 = (const float*)d_in[10];
    const float* erb2_w2 = (const float*)d_in[11];
    const float* dec_w   = (const float*)d_in[12];
    const float* dec_b   = (const float*)d_in[13];
    const float* drb1_w1 = (const float*)d_in[14];
    const float* drb1_w2 = (const float*)d_in[15];
    const float* drb2_w1 = (const float*)d_in[16];
    const float* drb2_w2 = (const float*)d_in[17];
    const float* dt1_w   = (const float*)d_in[18];
    const float* dt1_b   = (const float*)d_in[19];
    const float* dt2_w   = (const float*)d_in[20];
    const float* dt2_b   = (const float*)d_in[21];

    float *pA, *pCol, *pCvA, *pCvB, *pB1, *pB2, *pT, *pN, *pE, *pWdt2, *pW1p;
    __half* pWH;
    cudaGetSymbolAddress((void**)&pA,    g_A);
    cudaGetSymbolAddress((void**)&pCol,  g_col);
    cudaGetSymbolAddress((void**)&pCvA,  g_cvtA);
    cudaGetSymbolAddress((void**)&pCvB,  g_cvtB);
    cudaGetSymbolAddress((void**)&pB1,   g_B1);
    cudaGetSymbolAddress((void**)&pB2,   g_B2);
    cudaGetSymbolAddress((void**)&pT,    g_T);
    cudaGetSymbolAddress((void**)&pN,    g_norme);
    cudaGetSymbolAddress((void**)&pE,    g_embT);
    cudaGetSymbolAddress((void**)&pWdt2, g_wdt2);
    cudaGetSymbolAddress((void**)&pW1p,  g_w1p);
    cudaGetSymbolAddress((void**)&pWH,   g_wh);

    float* yout = (float*)d_out;
    float* fout = yout + Y_SZ;
    float* qout = fout + F_SZ;
    __half* cv3A = (__half*)pCvA;
    __half* cv3B = (__half*)pCvB;

    const int SH128 = (128 + 128) * 13 * 16 * 2;  // 106496
    const int SH64  = (128 + 64)  * 13 * 16 * 2;  // 79872
    const int SH32  = (128 + 32)  * 13 * 16 * 2;  // 66560
    cudaFuncSetAttribute(
        conv_h<0, 4, 4, 2, 1, 128, 64, 128, true, true, false, true, false>,
        cudaFuncAttributeMaxDynamicSharedMemorySize, SH128);
    cudaFuncSetAttribute(
        conv_h<0, 3, 3, 1, 1, 64, 128, 128, true, false, true, true, true>,
        cudaFuncAttributeMaxDynamicSharedMemorySize, SH128);
    cudaFuncSetAttribute(
        conv_h<0, 3, 3, 1, 1, 64, 128, 32, false, false, true, false, false>,
        cudaFuncAttributeMaxDynamicSharedMemorySize, SH32);
    cudaFuncSetAttribute(
        conv_h<1, 4, 4, 1, 0, 64, 128, 64, true, true, true, false, false>,
        cudaFuncAttributeMaxDynamicSharedMemorySize, SH64);

    // prep + enc1
    im2col_enc1<<<65536, 256>>>(x, pCol);
    pad_w1<<<16, 256>>>(enc_w1, pW1p);
    prep_w_half<16, 64, 128><<<512, 256>>>(enc_w2, pWH + WH_ENC2);
    flat_gemm<64, 64, 128, 8, 4, true, true><<<2048, 256>>>(pCol, pW1p, enc_b1, pA);
    cvt3_act<64, false><<<2048, 256>>>(pA, cv3A, 262144);
    prep_w_half<9, 128, 128><<<576, 256>>>(enc_w3, pWH + WH_ENC3);
    prep_w_half<9, 128, 32><<<144, 256>>>(erb1_w1, pWH + WH_ERB1);
    prep_w_half<9, 128, 32><<<144, 256>>>(erb2_w1, pWH + WH_ERB2);
    prep_w_half<9, 128, 128><<<576, 256>>>(dec_w, pWH + WH_DEC);
    prep_w_half<9, 128, 32><<<144, 256>>>(drb1_w1, pWH + WH_DRB1);
    prep_w_half<9, 128, 32><<<144, 256>>>(drb2_w1, pWH + WH_DRB2);
    prep_w_half<16, 128, 64><<<512, 256>>>(dt1_w, pWH + WH_DT1);
    transpose_w<<<12, 256>>>(dt2_w, pWdt2, 16, 64, 3);
    norme_kernel<<<2, 256>>>(emb, pN);
    embT_kernel<<<64, 256>>>(emb, pE);

    // Encoder (fp16 triple-channel)
    conv_h<0, 4, 4, 2, 1, 128, 64, 128, true, true, false, true, false>
        <<<512, 256, SH128>>>(cv3A, pWH + WH_ENC2, enc_b2, nullptr, cv3B);
    conv_h<0, 3, 3, 1, 1, 64, 128, 128, true, false, true, true, true>
        <<<512, 256, SH128>>>(cv3B, pWH + WH_ENC3, enc_b3, pB2, cv3A);
    conv_h<0, 3, 3, 1, 1, 64, 128, 32, false, false, true, false, false>
        <<<512, 256, SH32>>>(cv3A, pWH + WH_ERB1, nullptr, pT, nullptr);
    conv1x1_res<false, true, 2, true><<<8192, 256>>>(pT, pB2, erb1_w2, pB1, cv3B);
    conv_h<0, 3, 3, 1, 1, 64, 128, 32, false, false, true, false, false>
        <<<512, 256, SH32>>>(cv3B, pWH + WH_ERB2, nullptr, pT, nullptr);
    conv1x1_res<true, true, 0, false><<<8192, 256>>>(pT, pB1, erb2_w2, fout, nullptr);

    // VQ (q + fp16 triple cvt)
    vq16<<<4096, 128>>>(fout, pE, emb, pN, qout, cv3A);

    // Decoder (fp16 triple-channel)
    conv_h<0, 3, 3, 1, 1, 64, 128, 128, true, false, true, true, true>
        <<<512, 256, SH128>>>(cv3A, pWH + WH_DEC, dec_b, pB1, cv3B);
    conv_h<0, 3, 3, 1, 1, 64, 128, 32, false, false, true, false, false>
        <<<512, 256, SH32>>>(cv3B, pWH + WH_DRB1, nullptr, pT, nullptr);
    conv1x1_res<false, true, 2, true><<<8192, 256>>>(pT, pB1, drb1_w2, pB2, cv3A);
    conv_h<0, 3, 3, 1, 1, 64, 128, 32, false, false, true, false, false>
        <<<512, 256, SH32>>>(cv3A, pWH + WH_DRB2, nullptr, pT, nullptr);
    conv1x1_res<true, false, 2, false><<<8192, 256>>>(pT, pB2, drb2_w2, nullptr, cv3B);
    conv_h<1, 4, 4, 1, 0, 64, 128, 64, true, true, true, false, false>
        <<<dim3(512, 4), 256, SH64>>>(cv3B, pWH + WH_DT1, dt1_b, pA, nullptr);
    dt2_kernel<<<4096, 256>>>(pA, pWdt2, dt2_b, yout);
}